// round 7
// baseline (speedup 1.0000x reference)
#include <cuda_runtime.h>
#include <cuda_bf16.h>
#include <cstdint>

// ---------------------------------------------------------------------------
// Problem constants
// ---------------------------------------------------------------------------
#define D_MODEL 1024
#define NHEAD   16
#define HDIM    64
#define TXT_LEN 226
#define CHUNKS  4
#define SEQ_TXT 904
#define VID_LEN 3328
#define CHUNK_VID 1024
#define T_ATTN  1250
#define M_ATTN  5000
#define SEQ_SSM 4232
#define ATTN_SCALE 0.125f
#define NCHUNK  34

// ---------------------------------------------------------------------------
// Scratch (static __device__)
// ---------------------------------------------------------------------------
__device__ float g_curp [5242880];
__device__ float g_qkv  [15360000];
__device__ float g_qt   [5120000];
__device__ float g_kt   [5120000];
__device__ float g_vt   [5120000];
__device__ float g_attnp[5242880];
__device__ float g_proj [5120000];
__device__ float g_emb  [4333568];
__device__ float g_embp [4456448];
__device__ float g_u    [4333568];
__device__ float g_hloc [4333568];
__device__ float g_hp   [4456448];
__device__ float g_y    [4333568];
__device__ float g_emb2 [4333568];
__device__ float g_revp [4456448];
__device__ float g_carry[34816];
__device__ float g_wqkv[3145728];
__device__ float g_bqkv[3072];
__device__ float g_wo  [1048576];
__device__ float g_win [1048576];
__device__ float g_wout[1048576];

__device__ __forceinline__ float tf32_rna(float x) {
  float r;
  asm("cvt.rna.tf32.f32 %0, %1;" : "=f"(r) : "f"(x));
  return r;
}

// A-fragment permuted offset for element (r, c) of an Mx1024 matrix.
__device__ __forceinline__ size_t aperm_off(int r, int c) {
  const int rb = r >> 7, rl = r & 127;
  const int kt = c >> 4, cl = c & 15;
  const int g  = rl >> 4;
  const int j  = ((rl >> 3) & 1) | (((cl >> 2) & 1) << 1);
  const int lane = ((rl & 7) << 2) | (cl & 3);
  return ((size_t)(rb * 64 + kt)) * 2048 + (((g << 1) + (cl >> 3)) << 7) +
         (lane << 2) + j;
}

// B-fragment permuted offset for element (k, c) of a 1024xN weight matrix.
__device__ __forceinline__ size_t bperm_off(int k, int c) {
  const int nb = c >> 7, kt = k >> 4;
  const int n8 = (c >> 3) & 15;
  const int kb = (k >> 3) & 1;
  const int j  = (k >> 2) & 1;
  const int lane = ((c & 7) << 2) | (k & 3);
  return ((size_t)(nb * 64 + kt)) * 2048 + (((n8 << 1) + kb) << 6) +
         (lane << 1) + j;
}

__device__ __forceinline__ void cp16(uint32_t s, const void* g) {
  asm volatile("cp.async.cg.shared.global [%0], [%1], 16;" :: "r"(s), "l"(g));
}
__device__ __forceinline__ void cp16z(uint32_t s, const void* g, int n) {
  asm volatile("cp.async.cg.shared.global [%0], [%1], 16, %2;" :: "r"(s), "l"(g), "r"(n));
}

// ---------------------------------------------------------------------------
// Weight packing
// ---------------------------------------------------------------------------
__global__ void pack_qkv_perm_kernel(const float* __restrict__ Wq,
                                     const float* __restrict__ Wk,
                                     const float* __restrict__ Wv,
                                     float* __restrict__ dst) {
  const int c = blockIdx.x * 256 + threadIdx.x;
  const int k = blockIdx.y;
  const float* W = (c < 1024) ? Wq : (c < 2048) ? Wk : Wv;
  dst[bperm_off(k, c)] = tf32_rna(W[(size_t)k * 1024 + (c & 1023)]);
}

__global__ void pack_bias_kernel(const float* __restrict__ bq,
                                 const float* __restrict__ bk,
                                 const float* __restrict__ bv,
                                 float* __restrict__ bp) {
  const int i = blockIdx.x * 256 + threadIdx.x;
  if (i < 1024) { bp[i] = bq[i]; bp[1024 + i] = bk[i]; bp[2048 + i] = bv[i]; }
}

__global__ void pack_b_perm_kernel(const float* __restrict__ W,
                                   float* __restrict__ dst) {
  const int c = blockIdx.x * 256 + threadIdx.x;
  const int k = blockIdx.y;
  dst[bperm_off(k, c)] = tf32_rna(W[(size_t)k * 1024 + c]);
}

// ---------------------------------------------------------------------------
// TF32 GEMM on fragment-permuted operands, cp.async 3-stage pipeline.
// Block tile 128x128x16, 8 warps (4 row-slabs x 2 col-halves). (R4 config)
// ---------------------------------------------------------------------------
#define STAGES 3
__global__ void __launch_bounds__(256) tf32_gemm_perm(
    const float* __restrict__ Ap, const float* __restrict__ Bp,
    const float* __restrict__ bias, float* __restrict__ C,
    int M, int N) {
  __shared__ float As[STAGES][2048];
  __shared__ float Bs[STAGES][2048];
  const int tid = threadIdx.x;
  const int warp = tid >> 5, lane = tid & 31;
  const int ws = warp & 3;
  const int wn = (warp >> 2) << 6;
  const int grp = lane >> 2, gcc = lane & 3;
  const int rb = blockIdx.y, nb = blockIdx.x;
  const float* Abase = Ap + (size_t)rb * 64 * 2048;
  const float* Bbase = Bp + (size_t)nb * 64 * 2048;
  const uint32_t sA = (uint32_t)__cvta_generic_to_shared(&As[0][0]);
  const uint32_t sB = (uint32_t)__cvta_generic_to_shared(&Bs[0][0]);

  float acc[2][8][4];
#pragma unroll
  for (int mi = 0; mi < 2; mi++)
#pragma unroll
    for (int ni = 0; ni < 8; ni++)
#pragma unroll
      for (int j = 0; j < 4; j++) acc[mi][ni][j] = 0.f;

  auto issue = [&](int kt, int s) {
    const float* ga = Abase + (size_t)kt * 2048;
    const float* gb = Bbase + (size_t)kt * 2048;
    const uint32_t da = sA + s * 8192 + tid * 16;
    const uint32_t db = sB + s * 8192 + tid * 16;
    cp16(da,        ga + tid * 4);
    cp16(da + 4096, ga + 1024 + tid * 4);
    cp16(db,        gb + tid * 4);
    cp16(db + 4096, gb + 1024 + tid * 4);
    asm volatile("cp.async.commit_group;");
  };

  issue(0, 0);
  issue(1, 1);

  int s = 0;
  for (int kt = 0; kt < 64; kt++) {
    if (kt < 62) { asm volatile("cp.async.wait_group 1;"); }
    else         { asm volatile("cp.async.wait_group 0;"); }
    __syncthreads();
    if (kt + 2 < 64) issue(kt + 2, (kt + 2) % STAGES);

    const float4* a4 = reinterpret_cast<const float4*>(As[s]);
    const float2* b2 = reinterpret_cast<const float2*>(Bs[s]);
#pragma unroll
    for (int kb = 0; kb < 2; kb++) {
      float4 af[2];
      float2 bf[8];
#pragma unroll
      for (int mi = 0; mi < 2; mi++)
        af[mi] = a4[((((ws << 1) + mi) * 2 + kb) << 5) + lane];
#pragma unroll
      for (int ni = 0; ni < 8; ni++)
        bf[ni] = b2[((((wn >> 3) + ni) * 2 + kb) << 5) + lane];
#pragma unroll
      for (int mi = 0; mi < 2; mi++) {
        const uint32_t a0 = __float_as_uint(af[mi].x);
        const uint32_t a1 = __float_as_uint(af[mi].y);
        const uint32_t a2 = __float_as_uint(af[mi].z);
        const uint32_t a3 = __float_as_uint(af[mi].w);
#pragma unroll
        for (int ni = 0; ni < 8; ni++) {
          asm volatile(
              "mma.sync.aligned.m16n8k8.row.col.f32.tf32.tf32.f32 "
              "{%0,%1,%2,%3}, {%4,%5,%6,%7}, {%8,%9}, {%0,%1,%2,%3};"
              : "+f"(acc[mi][ni][0]), "+f"(acc[mi][ni][1]),
                "+f"(acc[mi][ni][2]), "+f"(acc[mi][ni][3])
              : "r"(a0), "r"(a1), "r"(a2), "r"(a3),
                "r"(__float_as_uint(bf[ni].x)), "r"(__float_as_uint(bf[ni].y)));
        }
      }
    }
    s = (s + 1) % STAGES;
  }

  const int row0 = rb * 128 + ws * 32;
  const int col0 = nb * 128 + wn;
#pragma unroll
  for (int mi = 0; mi < 2; mi++) {
    const int row = row0 + mi * 16 + grp;
#pragma unroll
    for (int ni = 0; ni < 8; ni++) {
      const int col = col0 + ni * 8 + (gcc << 1);
      float b0 = 0.f, b1 = 0.f;
      if (bias) { b0 = __ldg(bias + col); b1 = __ldg(bias + col + 1); }
      if (row < M) {
        float2 o; o.x = acc[mi][ni][0] + b0; o.y = acc[mi][ni][1] + b1;
        *reinterpret_cast<float2*>(C + (size_t)row * N + col) = o;
      }
      if (row + 8 < M) {
        float2 o; o.x = acc[mi][ni][2] + b0; o.y = acc[mi][ni][3] + b1;
        *reinterpret_cast<float2*>(C + (size_t)(row + 8) * N + col) = o;
      }
    }
  }
}

// ---------------------------------------------------------------------------
// Gather -> permuted cur
// ---------------------------------------------------------------------------
__global__ void gather_cur_perm_kernel(const float* __restrict__ vid,
                                       const float* __restrict__ txt,
                                       float* __restrict__ curp) {
  const int c = blockIdx.x * 256 + threadIdx.x;
  const int m = blockIdx.y;
  const int bc = m / T_ATTN;
  const int t  = m - bc * T_ATTN;
  const float v = (t < TXT_LEN)
      ? txt[((size_t)(bc * TXT_LEN + t)) * D_MODEL + c]
      : vid[((size_t)(bc * 768 + (t - TXT_LEN))) * D_MODEL + c];
  curp[aperm_off(m, c)] = tf32_rna(v);
}

// ---------------------------------------------------------------------------
// LayerNorm + RoPE + transpose
// ---------------------------------------------------------------------------
__device__ __forceinline__ void norm_rope_one(const float* __restrict__ src,
                                              const float* __restrict__ w,
                                              const float* __restrict__ b,
                                              float* __restrict__ dst, int t) {
  float x[64];
  float s = 0.f, ss = 0.f;
#pragma unroll
  for (int d = 0; d < 64; d++) {
    const float a = src[d];
    x[d] = a; s += a; ss += a * a;
  }
  const float mu  = s * (1.f / 64.f);
  const float var = ss * (1.f / 64.f) - mu * mu;
  const float rr  = rsqrtf(var + 1e-6f);
#pragma unroll
  for (int d = 0; d < 64; d++) x[d] = (x[d] - mu) * rr * w[d] + b[d];

  if (t >= TXT_LEN) {
    const int p = t - TXT_LEN;
    const float fpos = (float)(p >> 8);
    const int rem = p & 255;
    const float hpos = (float)(rem >> 4);
    const float wpos = (float)(rem & 15);
#pragma unroll
    for (int i = 0; i < 8; i++) {
      const float ang = fpos * __powf(10000.f, -(float)i * 0.125f);
      float sn, cs; sincosf(ang, &sn, &cs);
      const float x1 = x[i], x2 = x[8 + i];
      x[i]     = x1 * cs - x2 * sn;
      x[8 + i] = x1 * sn + x2 * cs;
    }
#pragma unroll
    for (int i = 0; i < 12; i++) {
      const float ang = hpos * __powf(10000.f, -(float)i * (1.f / 12.f));
      float sn, cs; sincosf(ang, &sn, &cs);
      const float x1 = x[16 + i], x2 = x[28 + i];
      x[16 + i] = x1 * cs - x2 * sn;
      x[28 + i] = x1 * sn + x2 * cs;
    }
#pragma unroll
    for (int i = 0; i < 12; i++) {
      const float ang = wpos * __powf(10000.f, -(float)i * (1.f / 12.f));
      float sn, cs; sincosf(ang, &sn, &cs);
      const float x1 = x[40 + i], x2 = x[52 + i];
      x[40 + i] = x1 * cs - x2 * sn;
      x[52 + i] = x1 * sn + x2 * cs;
    }
  }
#pragma unroll
  for (int d = 0; d < 64; d += 4)
    *reinterpret_cast<float4*>(dst + d) =
        make_float4(tf32_rna(x[d]), tf32_rna(x[d+1]), tf32_rna(x[d+2]), tf32_rna(x[d+3]));
}

__global__ void qkv_prep_kernel(const float* __restrict__ qkv,
                                const float* __restrict__ qw, const float* __restrict__ qb,
                                const float* __restrict__ kw, const float* __restrict__ kb,
                                float* __restrict__ qt, float* __restrict__ kt,
                                float* __restrict__ vt) {
  const int idx = blockIdx.x * blockDim.x + threadIdx.x;
  if (idx >= M_ATTN * NHEAD) return;
  const int m = idx >> 4;
  const int h = idx & 15;
  const int bc = m / T_ATTN;
  const int t  = m - bc * T_ATTN;
  const size_t src = (size_t)m * 3072 + h * HDIM;
  const size_t dst = ((size_t)(bc * NHEAD + h) * T_ATTN + t) * HDIM;
  norm_rope_one(qkv + src,        qw, qb, qt + dst, t);
  norm_rope_one(qkv + src + 1024, kw, kb, kt + dst, t);
#pragma unroll
  for (int d = 0; d < 64; d += 4) {
    const float4 v4 = *reinterpret_cast<const float4*>(qkv + src + 2048 + d);
    *reinterpret_cast<float4*>(vt + dst + d) =
        make_float4(tf32_rna(v4.x), tf32_rna(v4.y), tf32_rna(v4.z), tf32_rna(v4.w));
  }
}

// ---------------------------------------------------------------------------
// Flash attention tf32 with cp.async double-buffered K/V (R5 version)
// ---------------------------------------------------------------------------
#define FS 68
#define FA_TILE (64 * FS)
#define FA_SMEM ((6 * FA_TILE + 192) * 4)

__global__ void __launch_bounds__(256) flash_tf32_kernel(
    const float* __restrict__ Qt, const float* __restrict__ Kt,
    const float* __restrict__ Vt, float* __restrict__ Outp) {
  extern __shared__ float sm[];
  float* Qs = sm;
  float* KsB[2] = {sm + FA_TILE, sm + 2 * FA_TILE};
  float* VsB[2] = {sm + 3 * FA_TILE, sm + 4 * FA_TILE};
  float* Ss = sm + 5 * FA_TILE;
  float* sm_m  = sm + 6 * FA_TILE;
  float* sm_l  = sm_m + 64;
  float* sm_sc = sm_m + 128;

  const int mat = blockIdx.y;
  const int q0  = blockIdx.x * 64;
  const int tid = threadIdx.x;
  const int warp = tid >> 5;
  const int lane = tid & 31;
  const int gr = lane >> 2;
  const int gc = lane & 3;
  const int wm = (warp & 3) * 16;
  const int wn = (warp >> 2) * 32;

  const float* Qb = Qt + (size_t)mat * T_ATTN * HDIM;
  const float* Kb = Kt + (size_t)mat * T_ATTN * HDIM;
  const float* Vb = Vt + (size_t)mat * T_ATTN * HDIM;

  const int ldr  = tid >> 2;
  const int ldd  = (tid & 3) << 4;

  auto load_kv = [&](int k0, int buf) {
    const int gk = k0 + ldr;
    const int sz = (gk < T_ATTN) ? 16 : 0;
    const int gks = (gk < T_ATTN) ? gk : 0;
    const float* kp = Kb + (size_t)gks * HDIM + ldd;
    const float* vp = Vb + (size_t)gks * HDIM + ldd;
    const uint32_t dk = (uint32_t)__cvta_generic_to_shared(&KsB[buf][ldr * FS + ldd]);
    const uint32_t dv = (uint32_t)__cvta_generic_to_shared(&VsB[buf][ldr * FS + ldd]);
#pragma unroll
    for (int i = 0; i < 16; i += 4) {
      cp16z(dk + i * 4, kp + i, sz);
      cp16z(dv + i * 4, vp + i, sz);
    }
    asm volatile("cp.async.commit_group;");
  };

  if (tid < 64) { sm_m[tid] = -1e30f; sm_l[tid] = 0.f; }

  load_kv(0, 0);

  {
    const int gq = q0 + ldr;
#pragma unroll
    for (int i = 0; i < 16; i += 4) {
      float4 v4 = make_float4(0.f, 0.f, 0.f, 0.f);
      if (gq < T_ATTN)
        v4 = *reinterpret_cast<const float4*>(Qb + (size_t)gq * HDIM + ldd + i);
      *reinterpret_cast<float4*>(&Qs[ldr * FS + ldd + i]) = v4;
    }
  }
  __syncthreads();

  uint32_t qf[8][4];
#pragma unroll
  for (int kb = 0; kb < 8; kb++) {
    const int base = (wm + gr) * FS + kb * 8 + gc;
    qf[kb][0] = __float_as_uint(Qs[base]);
    qf[kb][1] = __float_as_uint(Qs[base + 8 * FS]);
    qf[kb][2] = __float_as_uint(Qs[base + 4]);
    qf[kb][3] = __float_as_uint(Qs[base + 8 * FS + 4]);
  }

  float acc[4][4];
#pragma unroll
  for (int ni = 0; ni < 4; ni++)
#pragma unroll
    for (int j = 0; j < 4; j++) acc[ni][j] = 0.f;

  const int NT = (T_ATTN + 63) >> 6;
  for (int it = 0; it < NT; it++) {
    asm volatile("cp.async.wait_group 0;");
    __syncthreads();
    if (it + 1 < NT) load_kv((it + 1) * 64, (it + 1) & 1);

    const float* Ks = KsB[it & 1];
    const float* Vs = VsB[it & 1];
    const int k0 = it * 64;

    float sacc[4][4];
#pragma unroll
    for (int ni = 0; ni < 4; ni++)
#pragma unroll
      for (int j = 0; j < 4; j++) sacc[ni][j] = 0.f;
#pragma unroll
    for (int kb = 0; kb < 8; kb++) {
      uint32_t bf[4][2];
#pragma unroll
      for (int ni = 0; ni < 4; ni++) {
        const int kbase = (wn + ni * 8 + gr) * FS + kb * 8 + gc;
        bf[ni][0] = __float_as_uint(Ks[kbase]);
        bf[ni][1] = __float_as_uint(Ks[kbase + 4]);
      }
#pragma unroll
      for (int ni = 0; ni < 4; ni++) {
        asm volatile(
            "mma.sync.aligned.m16n8k8.row.col.f32.tf32.tf32.f32 "
            "{%0,%1,%2,%3}, {%4,%5,%6,%7}, {%8,%9}, {%0,%1,%2,%3};"
            : "+f"(sacc[ni][0]), "+f"(sacc[ni][1]),
              "+f"(sacc[ni][2]), "+f"(sacc[ni][3])
            : "r"(qf[kb][0]), "r"(qf[kb][1]), "r"(qf[kb][2]), "r"(qf[kb][3]),
              "r"(bf[ni][0]), "r"(bf[ni][1]));
      }
    }

#pragma unroll
    for (int ni = 0; ni < 4; ni++) {
      const int col = wn + ni * 8 + (gc << 1);
      const int gk  = k0 + col;
      float2 s0, s1;
      s0.x = (gk     < T_ATTN) ? sacc[ni][0] * ATTN_SCALE : -1e30f;
      s0.y = (gk + 1 < T_ATTN) ? sacc[ni][1] * ATTN_SCALE : -1e30f;
      s1.x = (gk     < T_ATTN) ? sacc[ni][2] * ATTN_SCALE : -1e30f;
      s1.y = (gk + 1 < T_ATTN) ? sacc[ni][3] * ATTN_SCALE : -1e30f;
      *reinterpret_cast<float2*>(&Ss[(wm + gr) * FS + col])     = s0;
      *reinterpret_cast<float2*>(&Ss[(wm + 8 + gr) * FS + col]) = s1;
    }
    __syncthreads();

    {
      const int row = tid >> 2;
      const int qq  = tid & 3;
      float* rp = &Ss[row * FS + qq * 16];
      float v[16];
#pragma unroll
      for (int i = 0; i < 16; i += 4) {
        const float4 t4 = *reinterpret_cast<const float4*>(rp + i);
        v[i] = t4.x; v[i+1] = t4.y; v[i+2] = t4.z; v[i+3] = t4.w;
      }
      float mx = v[0];
#pragma unroll
      for (int i = 1; i < 16; i++) mx = fmaxf(mx, v[i]);
      mx = fmaxf(mx, __shfl_xor_sync(0xffffffffu, mx, 1));
      mx = fmaxf(mx, __shfl_xor_sync(0xffffffffu, mx, 2));
      const float m_old = sm_m[row];
      const float m_new = fmaxf(m_old, mx);
      const float sc = __expf(m_old - m_new);
      float sum = 0.f;
#pragma unroll
      for (int i = 0; i < 16; i++) {
        const float p = tf32_rna(__expf(v[i] - m_new));
        v[i] = p; sum += p;
      }
#pragma unroll
      for (int i = 0; i < 16; i += 4)
        *reinterpret_cast<float4*>(rp + i) = make_float4(v[i], v[i+1], v[i+2], v[i+3]);
      sum += __shfl_xor_sync(0xffffffffu, sum, 1);
      sum += __shfl_xor_sync(0xffffffffu, sum, 2);
      if (qq == 0) {
        sm_sc[row] = sc;
        sm_m[row]  = m_new;
        sm_l[row]  = sm_l[row] * sc + sum;
      }
    }
    __syncthreads();

    {
      const float sc0 = sm_sc[wm + gr];
      const float sc1 = sm_sc[wm + 8 + gr];
#pragma unroll
      for (int ni = 0; ni < 4; ni++) {
        acc[ni][0] *= sc0; acc[ni][1] *= sc0;
        acc[ni][2] *= sc1; acc[ni][3] *= sc1;
      }
#pragma unroll
      for (int kb = 0; kb < 8; kb++) {
        uint32_t af[4];
        const int abase = (wm + gr) * FS + kb * 8 + gc;
        af[0] = __float_as_uint(Ss[abase]);
        af[1] = __float_as_uint(Ss[abase + 8 * FS]);
        af[2] = __float_as_uint(Ss[abase + 4]);
        af[3] = __float_as_uint(Ss[abase + 8 * FS + 4]);
        uint32_t bf[4][2];
#pragma unroll
        for (int ni = 0; ni < 4; ni++) {
          const int vbase = (kb * 8 + gc) * FS + wn + ni * 8 + gr;
          bf[ni][0] = __float_as_uint(Vs[vbase]);
          bf[ni][1] = __float_as_uint(Vs[vbase + 4 * FS]);
        }
#pragma unroll
        for (int ni = 0; ni < 4; ni++) {
          asm volatile(
              "mma.sync.aligned.m16n8k8.row.col.f32.tf32.tf32.f32 "
              "{%0,%1,%2,%3}, {%4,%5,%6,%7}, {%8,%9}, {%0,%1,%2,%3};"
              : "+f"(acc[ni][0]), "+f"(acc[ni][1]),
                "+f"(acc[ni][2]), "+f"(acc[ni][3])
              : "r"(af[0]), "r"(af[1]), "r"(af[2]), "r"(af[3]),
                "r"(bf[ni][0]), "r"(bf[ni][1]));
        }
      }
    }
    __syncthreads();
  }

  const int bc = mat >> 4;
  const int h  = mat & 15;
  const float inv0 = 1.f / sm_l[wm + gr];
  const float inv1 = 1.f / sm_l[wm + 8 + gr];
  const int r0 = q0 + wm + gr;
  const int r1 = r0 + 8;
#pragma unroll
  for (int ni = 0; ni < 4; ni++) {
    const int col = h * HDIM + wn + ni * 8 + (gc << 1);
    if (r0 < T_ATTN) {
      const int gm = bc * T_ATTN + r0;
      Outp[aperm_off(gm, col)]     = tf32_rna(acc[ni][0] * inv0);
      Outp[aperm_off(gm, col + 1)] = tf32_rna(acc[ni][1] * inv0);
    }
    if (r1 < T_ATTN) {
      const int gm = bc * T_ATTN + r1;
      Outp[aperm_off(gm, col)]     = tf32_rna(acc[ni][2] * inv1);
      Outp[aperm_off(gm, col + 1)] = tf32_rna(acc[ni][3] * inv1);
    }
  }
}

// ---------------------------------------------------------------------------
// build emb
// ---------------------------------------------------------------------------
__global__ void build_emb_kernel(const float* __restrict__ proj,
                                 float* __restrict__ emb,
                                 float* __restrict__ embp) {
  const int idx = blockIdx.x * blockDim.x + threadIdx.x;
  if (idx >= SEQ_SSM * 256) return;
  const int i  = idx >> 8;
  const int d4 = (idx & 255) << 2;
  float4 o;
  if (i < SEQ_TXT) {
    const int c = i / TXT_LEN;
    const int t = i - c * TXT_LEN;
    o = *reinterpret_cast<const float4*>(proj + ((size_t)(c * T_ATTN + t)) * D_MODEL + d4);
  } else {
    const int p = i - SEQ_TXT;
    float4 acc = make_float4(0.f, 0.f, 0.f, 0.f);
    int cnt = 0;
#pragma unroll
    for (int c = 0; c < 4; c++) {
      const int j = p - c * 768;
      if (j >= 0 && j < CHUNK_VID) {
        const float4 v4 = *reinterpret_cast<const float4*>(
            proj + ((size_t)(c * T_ATTN + TXT_LEN + j)) * D_MODEL + d4);
        acc.x += v4.x; acc.y += v4.y; acc.z += v4.z; acc.w += v4.w;
        cnt++;
      }
    }
    const float inv = 1.f / (float)cnt;
    o.x = acc.x * inv; o.y = acc.y * inv; o.z = acc.z * inv; o.w = acc.w * inv;
  }
  *reinterpret_cast<float4*>(emb + (size_t)i * D_MODEL + d4) = o;
  embp[aperm_off(i, d4 + 0)] = tf32_rna(o.x);
  embp[aperm_off(i, d4 + 1)] = tf32_rna(o.y);
  embp[aperm_off(i, d4 + 2)] = tf32_rna(o.z);
  embp[aperm_off(i, d4 + 3)] = tf32_rna(o.w);
}

// ---------------------------------------------------------------------------
// Parallel SSM scan
// ---------------------------------------------------------------------------
__global__ void scan_pass1_kernel(const float* __restrict__ u,
                                  const float* __restrict__ gate,
                                  float* __restrict__ hloc,
                                  float* __restrict__ carry) {
  const int d = blockIdx.x * 256 + threadIdx.x;
  const int c = blockIdx.y;
  const float a = 1.f / (1.f + expf(-gate[d]));
  const int t0 = c * 128;
  const int t1 = (t0 + 128 < SEQ_SSM) ? (t0 + 128) : SEQ_SSM;
  float hv = 0.f;
  for (int t = t0; t < t1; t++) {
    hv = fmaf(a, hv, u[(size_t)t * D_MODEL + d]);
    hloc[(size_t)t * D_MODEL + d] = hv;
  }
  carry[c * 1024 + d] = hv;
}

__global__ void scan_pass2_kernel(const float* __restrict__ gate,
                                  float* __restrict__ carry) {
  const int d = blockIdx.x * 256 + threadIdx.x;
  const float a = 1.f / (1.f + expf(-gate[d]));
  const float a128 = __powf(a, 128.f);
  float s = 0.f;
  for (int c = 0; c < NCHUNK; c++) {
    const float cv = carry[c * 1024 + d];
    carry[c * 1024 + d] = s;
    s = a128 * s + cv;
  }
}

__global__ void scan_pass3_kernel(const float* __restrict__ hloc,
                                  const float* __restrict__ gate,
                                  const float* __restrict__ carry,
                                  float* __restrict__ hp) {
  const int d = blockIdx.x * 256 + threadIdx.x;
  const int c = blockIdx.y;
  const float a = 1.f / (1.f + expf(-gate[d]));
  const float cin = carry[c * 1024 + d];
  const int t0 = c * 128;
  const int t1 = (t0 + 128 < SEQ_SSM) ? (t0 + 128) : SEQ_SSM;
  float p = a;
  for (int t = t0; t < t1; t++) {
    const float hv = hloc[(size_t)t * D_MODEL + d] + p * cin;
    p *= a;
    hp[aperm_off(t, d)] = tf32_rna(hv);
  }
}

// ---------------------------------------------------------------------------
// gates / reverse / final
// ---------------------------------------------------------------------------
__global__ void gate_add_kernel(const float* __restrict__ base, const float* __restrict__ y,
                                const float* __restrict__ gt, const float* __restrict__ gv,
                                float* __restrict__ out) {
  const int idx = blockIdx.x * blockDim.x + threadIdx.x;
  if (idx >= SEQ_SSM * 256) return;
  const int i  = idx >> 8;
  const int d4 = (idx & 255) << 2;
  const float* g = (i < SEQ_TXT) ? gt : gv;
  const float4 b4 = *reinterpret_cast<const float4*>(base + (size_t)i * D_MODEL + d4);
  const float4 y4 = *reinterpret_cast<const float4*>(y + (size_t)i * D_MODEL + d4);
  float4 o;
  o.x = b4.x + tanhf(g[d4 + 0]) * y4.x;
  o.y = b4.y + tanhf(g[d4 + 1]) * y4.y;
  o.z = b4.z + tanhf(g[d4 + 2]) * y4.z;
  o.w = b4.w + tanhf(g[d4 + 3]) * y4.w;
  *reinterpret_cast<float4*>(out + (size_t)i * D_MODEL + d4) = o;
}

__device__ __forceinline__ int rev_map(int i) {
  if (i < SEQ_TXT) {
    const int c = i / TXT_LEN;
    return (3 - c) * TXT_LEN + (i - c * TXT_LEN);
  }
  return 5135 - i;
}

__global__ void rev_perm_kernel(const float* __restrict__ src, float* __restrict__ dstp) {
  const int c = blockIdx.x * 256 + threadIdx.x;
  const int i = blockIdx.y;
  const int s = rev_map(i);
  dstp[aperm_off(i, c)] = tf32_rna(src[(size_t)s * D_MODEL + c]);
}

__global__ void final_kernel(const float* __restrict__ emb2, const float* __restrict__ y2,
                             const float* __restrict__ gt, const float* __restrict__ gv,
                             float* __restrict__ out) {
  const int idx = blockIdx.x * blockDim.x + threadIdx.x;
  if (idx >= SEQ_SSM * 256) return;
  const int i  = idx >> 8;
  const int d4 = (idx & 255) << 2;
  const int s = rev_map(i);
  const float* g = (i < SEQ_TXT) ? gt : gv;
  const float4 e4 = *reinterpret_cast<const float4*>(emb2 + (size_t)i * D_MODEL + d4);
  const float4 y4 = *reinterpret_cast<const float4*>(y2 + (size_t)s * D_MODEL + d4);
  float4 o;
  o.x = e4.x + tanhf(g[d4 + 0]) * y4.x;
  o.y = e4.y + tanhf(g[d4 + 1]) * y4.y;
  o.z = e4.z + tanhf(g[d4 + 2]) * y4.z;
  o.w = e4.w + tanhf(g[d4 + 3]) * y4.w;
  const int dst = (i < SEQ_TXT) ? (VID_LEN + i) : (i - SEQ_TXT);
  *reinterpret_cast<float4*>(out + (size_t)dst * D_MODEL + d4) = o;
}

// ---------------------------------------------------------------------------
// Launch
// ---------------------------------------------------------------------------
static float* sym_addr(const void* symbol) {
  void* p = nullptr;
  cudaGetSymbolAddress(&p, symbol);
  return (float*)p;
}

extern "C" void kernel_launch(void* const* d_in, const int* in_sizes, int n_in,
                              void* d_out, int out_size) {
  (void)in_sizes; (void)n_in; (void)out_size;
  const float* vid   = (const float*)d_in[0];
  const float* txt   = (const float*)d_in[1];
  const float* Wq    = (const float*)d_in[2];
  const float* bq    = (const float*)d_in[3];
  const float* Wk    = (const float*)d_in[4];
  const float* bk    = (const float*)d_in[5];
  const float* Wv    = (const float*)d_in[6];
  const float* bv    = (const float*)d_in[7];
  const float* Wo    = (const float*)d_in[8];
  const float* bo    = (const float*)d_in[9];
  const float* qn_w  = (const float*)d_in[10];
  const float* qn_b  = (const float*)d_in[11];
  const float* kn_w  = (const float*)d_in[12];
  const float* kn_b  = (const float*)d_in[13];
  const float* Win   = (const float*)d_in[14];
  const float* Wout  = (const float*)d_in[15];
  const float* gate  = (const float*)d_in[16];
  const float* fg_t  = (const float*)d_in[17];
  const float* fg_v  = (const float*)d_in[18];
  const float* bg_t  = (const float*)d_in[19];
  const float* bg_v  = (const float*)d_in[20];
  float* out = (float*)d_out;

  float* curp  = sym_addr(g_curp);
  float* qkv   = sym_addr(g_qkv);
  float* qt    = sym_addr(g_qt);
  float* kt    = sym_addr(g_kt);
  float* vt    = sym_addr(g_vt);
  float* attnp = sym_addr(g_attnp);
  float* proj  = sym_addr(g_proj);
  float* emb   = sym_addr(g_emb);
  float* embp  = sym_addr(g_embp);
  float* u     = sym_addr(g_u);
  float* hloc  = sym_addr(g_hloc);
  float* hp    = sym_addr(g_hp);
  float* y     = sym_addr(g_y);
  float* emb2  = sym_addr(g_emb2);
  float* revp  = sym_addr(g_revp);
  float* carry = sym_addr(g_carry);
  float* wqkv  = sym_addr(g_wqkv);
  float* bqkv  = sym_addr(g_bqkv);
  float* wo_p  = sym_addr(g_wo);
  float* win_p  = sym_addr(g_win);
  float* wout_p = sym_addr(g_wout);

  cudaFuncSetAttribute(flash_tf32_kernel, cudaFuncAttributeMaxDynamicSharedMemorySize, FA_SMEM);

  pack_qkv_perm_kernel<<<dim3(12, 1024), 256>>>(Wq, Wk, Wv, wqkv);
  pack_bias_kernel<<<4, 256>>>(bq, bk, bv, bqkv);
  pack_b_perm_kernel<<<dim3(4, 1024), 256>>>(Wo, wo_p);
  pack_b_perm_kernel<<<dim3(4, 1024), 256>>>(Win, win_p);
  pack_b_perm_kernel<<<dim3(4, 1024), 256>>>(Wout, wout_p);

  gather_cur_perm_kernel<<<dim3(4, M_ATTN), 256>>>(vid, txt, curp);
  tf32_gemm_perm<<<dim3(24, 40), 256>>>(curp, wqkv, bqkv, qkv, M_ATTN, 3072);
  qkv_prep_kernel<<<(M_ATTN * NHEAD) / 128, 128>>>(qkv, qn_w, qn_b, kn_w, kn_b,
                                                   qt, kt, vt);
  flash_tf32_kernel<<<dim3(20, 64), 256, FA_SMEM>>>(qt, kt, vt, attnp);
  tf32_gemm_perm<<<dim3(8, 40), 256>>>(attnp, wo_p, bo, proj, M_ATTN, 1024);
  build_emb_kernel<<<SEQ_SSM, 256>>>(proj, emb, embp);

  tf32_gemm_perm<<<dim3(8, 34), 256>>>(embp, win_p, nullptr, u, SEQ_SSM, 1024);
  scan_pass1_kernel<<<dim3(4, NCHUNK), 256>>>(u, gate, hloc, carry);
  scan_pass2_kernel<<<4, 256>>>(gate, carry);
  scan_pass3_kernel<<<dim3(4, NCHUNK), 256>>>(hloc, gate, carry, hp);
  tf32_gemm_perm<<<dim3(8, 34), 256>>>(hp, wout_p, nullptr, y, SEQ_SSM, 1024);
  gate_add_kernel<<<SEQ_SSM, 256>>>(emb, y, fg_t, fg_v, emb2);

  rev_perm_kernel<<<dim3(4, SEQ_SSM), 256>>>(emb2, revp);
  tf32_gemm_perm<<<dim3(8, 34), 256>>>(revp, win_p, nullptr, u, SEQ_SSM, 1024);
  scan_pass1_kernel<<<dim3(4, NCHUNK), 256>>>(u, gate, hloc, carry);
  scan_pass2_kernel<<<4, 256>>>(gate, carry);
  scan_pass3_kernel<<<dim3(4, NCHUNK), 256>>>(hloc, gate, carry, hp);
  tf32_gemm_perm<<<dim3(8, 34), 256>>>(hp, wout_p, nullptr, y, SEQ_SSM, 1024);
  final_kernel<<<SEQ_SSM, 256>>>(emb2, y, bg_t, bg_v, out);
}

// round 8
// speedup vs baseline: 1.5529x; 1.5529x over previous
#include <cuda_runtime.h>
#include <cuda_bf16.h>
#include <cstdint>

// ---------------------------------------------------------------------------
// Problem constants
// ---------------------------------------------------------------------------
#define D_MODEL 1024
#define NHEAD   16
#define HDIM    64
#define TXT_LEN 226
#define CHUNKS  4
#define SEQ_TXT 904
#define VID_LEN 3328
#define CHUNK_VID 1024
#define T_ATTN  1250
#define SEG_PAD 1280         // padded attention segment rows (mult of 128)
#define M_ATTN  5000
#define M_PAD   5120         // 4 * 1280
#define SEQ_SSM 4232
#define ATTN_SCALE 0.125f
#define NCHUNK  34

// ---------------------------------------------------------------------------
// Scratch (static __device__)
// ---------------------------------------------------------------------------
__device__ float g_curp [5242880];   // 40 tiles (perm A, 5120 rows)
__device__ float g_qkv  [15360000];  // 5000 x 3072
__device__ float g_qt   [5120000];
__device__ float g_kt   [5120000];
__device__ float g_vt   [5120000];
__device__ float g_attnp[5242880];   // perm A, padded 5120 rows
__device__ float g_proj [5242880];   // padded 5120 rows x 1024
__device__ float g_emb  [4333568];
__device__ float g_embp [4456448];   // perm, 34 tiles
__device__ float g_u    [4333568];
__device__ float g_hloc [4333568];
__device__ float g_hp   [4456448];
__device__ float g_y    [4333568];
__device__ float g_emb2 [4333568];
__device__ float g_revp [4456448];
__device__ float g_carry[34816];
__device__ float g_wqkv[3145728];
__device__ float g_bqkv[3072];
__device__ float g_wo  [1048576];
__device__ float g_win [1048576];
__device__ float g_wout[1048576];

__device__ __forceinline__ float tf32_rna(float x) {
  float r;
  asm("cvt.rna.tf32.f32 %0, %1;" : "=f"(r) : "f"(x));
  return r;
}

// B-fragment permuted offset for element (k, c) of a 1024xN weight matrix.
__device__ __forceinline__ size_t bperm_off(int k, int c) {
  const int nb = c >> 7, kt = k >> 4;
  const int n8 = (c >> 3) & 15;
  const int kb = (k >> 3) & 1;
  const int j  = (k >> 2) & 1;
  const int lane = ((c & 7) << 2) | (k & 3);
  return ((size_t)(nb * 64 + kt)) * 2048 + (((n8 << 1) + kb) << 6) +
         (lane << 1) + j;
}

// A-perm float4 decode: one float4 covers (r0,c0),(r0+8,c0),(r0,c0+4),(r0+8,c0+4)
struct APermIdx { int r0, c0; size_t off; };
__device__ __forceinline__ APermIdx aperm_decode(int idx) {
  const int lane = idx & 31;
  const int half = (idx >> 5) & 1;
  const int g    = (idx >> 6) & 7;
  const int kt   = (idx >> 9) & 63;
  const int rb   = idx >> 15;
  APermIdx o;
  o.r0  = rb * 128 + g * 16 + (lane >> 2);
  o.c0  = kt * 16 + half * 8 + (lane & 3);
  o.off = ((size_t)(rb * 64 + kt)) * 2048 + (((g << 1) + half) << 7) + (lane << 2);
  return o;
}

__device__ __forceinline__ void cp16(uint32_t s, const void* g) {
  asm volatile("cp.async.cg.shared.global [%0], [%1], 16;" :: "r"(s), "l"(g));
}

// ---------------------------------------------------------------------------
// Weight packing
// ---------------------------------------------------------------------------
__global__ void pack_qkv_perm_kernel(const float* __restrict__ Wq,
                                     const float* __restrict__ Wk,
                                     const float* __restrict__ Wv,
                                     float* __restrict__ dst) {
  const int c = blockIdx.x * 256 + threadIdx.x;
  const int k = blockIdx.y;
  const float* W = (c < 1024) ? Wq : (c < 2048) ? Wk : Wv;
  dst[bperm_off(k, c)] = tf32_rna(W[(size_t)k * 1024 + (c & 1023)]);
}

__global__ void pack_bias_kernel(const float* __restrict__ bq,
                                 const float* __restrict__ bk,
                                 const float* __restrict__ bv,
                                 float* __restrict__ bp) {
  const int i = blockIdx.x * 256 + threadIdx.x;
  if (i < 1024) { bp[i] = bq[i]; bp[1024 + i] = bk[i]; bp[2048 + i] = bv[i]; }
}

__global__ void pack_b_perm_kernel(const float* __restrict__ W,
                                   float* __restrict__ dst) {
  const int c = blockIdx.x * 256 + threadIdx.x;
  const int k = blockIdx.y;
  dst[bperm_off(k, c)] = tf32_rna(W[(size_t)k * 1024 + c]);
}

// ---------------------------------------------------------------------------
// TF32 GEMM on fragment-permuted operands, cp.async 3-stage pipeline.
// Block tile 128x128x16, 8 warps (R4 config — known good).
// ---------------------------------------------------------------------------
#define STAGES 3
__global__ void __launch_bounds__(256) tf32_gemm_perm(
    const float* __restrict__ Ap, const float* __restrict__ Bp,
    const float* __restrict__ bias, float* __restrict__ C,
    int M, int N) {
  __shared__ float As[STAGES][2048];
  __shared__ float Bs[STAGES][2048];
  const int tid = threadIdx.x;
  const int warp = tid >> 5, lane = tid & 31;
  const int ws = warp & 3;
  const int wn = (warp >> 2) << 6;
  const int grp = lane >> 2, gcc = lane & 3;
  const int rb = blockIdx.y, nb = blockIdx.x;
  const float* Abase = Ap + (size_t)rb * 64 * 2048;
  const float* Bbase = Bp + (size_t)nb * 64 * 2048;
  const uint32_t sA = (uint32_t)__cvta_generic_to_shared(&As[0][0]);
  const uint32_t sB = (uint32_t)__cvta_generic_to_shared(&Bs[0][0]);

  float acc[2][8][4];
#pragma unroll
  for (int mi = 0; mi < 2; mi++)
#pragma unroll
    for (int ni = 0; ni < 8; ni++)
#pragma unroll
      for (int j = 0; j < 4; j++) acc[mi][ni][j] = 0.f;

  auto issue = [&](int kt, int s) {
    const float* ga = Abase + (size_t)kt * 2048;
    const float* gb = Bbase + (size_t)kt * 2048;
    const uint32_t da = sA + s * 8192 + tid * 16;
    const uint32_t db = sB + s * 8192 + tid * 16;
    cp16(da,        ga + tid * 4);
    cp16(da + 4096, ga + 1024 + tid * 4);
    cp16(db,        gb + tid * 4);
    cp16(db + 4096, gb + 1024 + tid * 4);
    asm volatile("cp.async.commit_group;");
  };

  issue(0, 0);
  issue(1, 1);

  int s = 0;
  for (int kt = 0; kt < 64; kt++) {
    if (kt < 62) { asm volatile("cp.async.wait_group 1;"); }
    else         { asm volatile("cp.async.wait_group 0;"); }
    __syncthreads();
    if (kt + 2 < 64) issue(kt + 2, (kt + 2) % STAGES);

    const float4* a4 = reinterpret_cast<const float4*>(As[s]);
    const float2* b2 = reinterpret_cast<const float2*>(Bs[s]);
#pragma unroll
    for (int kb = 0; kb < 2; kb++) {
      float4 af[2];
      float2 bf[8];
#pragma unroll
      for (int mi = 0; mi < 2; mi++)
        af[mi] = a4[((((ws << 1) + mi) * 2 + kb) << 5) + lane];
#pragma unroll
      for (int ni = 0; ni < 8; ni++)
        bf[ni] = b2[((((wn >> 3) + ni) * 2 + kb) << 5) + lane];
#pragma unroll
      for (int mi = 0; mi < 2; mi++) {
        const uint32_t a0 = __float_as_uint(af[mi].x);
        const uint32_t a1 = __float_as_uint(af[mi].y);
        const uint32_t a2 = __float_as_uint(af[mi].z);
        const uint32_t a3 = __float_as_uint(af[mi].w);
#pragma unroll
        for (int ni = 0; ni < 8; ni++) {
          asm volatile(
              "mma.sync.aligned.m16n8k8.row.col.f32.tf32.tf32.f32 "
              "{%0,%1,%2,%3}, {%4,%5,%6,%7}, {%8,%9}, {%0,%1,%2,%3};"
              : "+f"(acc[mi][ni][0]), "+f"(acc[mi][ni][1]),
                "+f"(acc[mi][ni][2]), "+f"(acc[mi][ni][3])
              : "r"(a0), "r"(a1), "r"(a2), "r"(a3),
                "r"(__float_as_uint(bf[ni].x)), "r"(__float_as_uint(bf[ni].y)));
        }
      }
    }
    s = (s + 1) % STAGES;
  }

  const int row0 = rb * 128 + ws * 32;
  const int col0 = nb * 128 + wn;
#pragma unroll
  for (int mi = 0; mi < 2; mi++) {
    const int row = row0 + mi * 16 + grp;
#pragma unroll
    for (int ni = 0; ni < 8; ni++) {
      const int col = col0 + ni * 8 + (gcc << 1);
      float b0 = 0.f, b1 = 0.f;
      if (bias) { b0 = __ldg(bias + col); b1 = __ldg(bias + col + 1); }
      if (row < M) {
        float2 o; o.x = acc[mi][ni][0] + b0; o.y = acc[mi][ni][1] + b1;
        *reinterpret_cast<float2*>(C + (size_t)row * N + col) = o;
      }
      if (row + 8 < M) {
        float2 o; o.x = acc[mi][ni][2] + b0; o.y = acc[mi][ni][3] + b1;
        *reinterpret_cast<float2*>(C + (size_t)(row + 8) * N + col) = o;
      }
    }
  }
}

// ---------------------------------------------------------------------------
// Coalesced A-perm writers (one thread builds one float4)
// ---------------------------------------------------------------------------
// gather: cur rows are attention rows (4 segments x 1250 valid of 1280? NO:
// curp is for the QKV GEMM which uses 1250-based rows, 40 tiles of 5120 with
// rows >= 5000 zeroed)
__global__ void gather_cur_perm4(const float* __restrict__ vid,
                                 const float* __restrict__ txt,
                                 float* __restrict__ curp) {
  const int idx = blockIdx.x * 256 + threadIdx.x;
  const APermIdx ix = aperm_decode(idx);
  auto ld = [&](int r, int c) -> float {
    if (r >= M_ATTN) return 0.f;
    const int bc = r / T_ATTN;
    const int t  = r - bc * T_ATTN;
    return (t < TXT_LEN)
        ? txt[(size_t)(bc * TXT_LEN + t) * D_MODEL + c]
        : vid[(size_t)(bc * 768 + (t - TXT_LEN)) * D_MODEL + c];
  };
  float4 o;
  o.x = tf32_rna(ld(ix.r0,     ix.c0));
  o.y = tf32_rna(ld(ix.r0 + 8, ix.c0));
  o.z = tf32_rna(ld(ix.r0,     ix.c0 + 4));
  o.w = tf32_rna(ld(ix.r0 + 8, ix.c0 + 4));
  *reinterpret_cast<float4*>(curp + ix.off) = o;
}

// row-major -> A-perm (for emb -> embp), rows < SEQ_SSM
__global__ void rowmajor_to_aperm4(const float* __restrict__ src,
                                   float* __restrict__ dst) {
  const int idx = blockIdx.x * 256 + threadIdx.x;
  const APermIdx ix = aperm_decode(idx);
  auto ld = [&](int r, int c) -> float {
    return (r < SEQ_SSM) ? src[(size_t)r * D_MODEL + c] : 0.f;
  };
  float4 o;
  o.x = tf32_rna(ld(ix.r0,     ix.c0));
  o.y = tf32_rna(ld(ix.r0 + 8, ix.c0));
  o.z = tf32_rna(ld(ix.r0,     ix.c0 + 4));
  o.w = tf32_rna(ld(ix.r0 + 8, ix.c0 + 4));
  *reinterpret_cast<float4*>(dst + ix.off) = o;
}

__device__ __forceinline__ int rev_map(int i) {
  if (i < SEQ_TXT) {
    const int c = i / TXT_LEN;
    return (3 - c) * TXT_LEN + (i - c * TXT_LEN);
  }
  return 5135 - i;
}

__global__ void rev_perm4(const float* __restrict__ src, float* __restrict__ dst) {
  const int idx = blockIdx.x * 256 + threadIdx.x;
  const APermIdx ix = aperm_decode(idx);
  auto ld = [&](int r, int c) -> float {
    return (r < SEQ_SSM) ? src[(size_t)rev_map(r) * D_MODEL + c] : 0.f;
  };
  float4 o;
  o.x = tf32_rna(ld(ix.r0,     ix.c0));
  o.y = tf32_rna(ld(ix.r0 + 8, ix.c0));
  o.z = tf32_rna(ld(ix.r0,     ix.c0 + 4));
  o.w = tf32_rna(ld(ix.r0 + 8, ix.c0 + 4));
  *reinterpret_cast<float4*>(dst + ix.off) = o;
}

// ---------------------------------------------------------------------------
// LayerNorm + RoPE + transpose (unchanged)
// ---------------------------------------------------------------------------
__device__ __forceinline__ void norm_rope_one(const float* __restrict__ src,
                                              const float* __restrict__ w,
                                              const float* __restrict__ b,
                                              float* __restrict__ dst, int t) {
  float x[64];
  float s = 0.f, ss = 0.f;
#pragma unroll
  for (int d = 0; d < 64; d++) {
    const float a = src[d];
    x[d] = a; s += a; ss += a * a;
  }
  const float mu  = s * (1.f / 64.f);
  const float var = ss * (1.f / 64.f) - mu * mu;
  const float rr  = rsqrtf(var + 1e-6f);
#pragma unroll
  for (int d = 0; d < 64; d++) x[d] = (x[d] - mu) * rr * w[d] + b[d];

  if (t >= TXT_LEN) {
    const int p = t - TXT_LEN;
    const float fpos = (float)(p >> 8);
    const int rem = p & 255;
    const float hpos = (float)(rem >> 4);
    const float wpos = (float)(rem & 15);
#pragma unroll
    for (int i = 0; i < 8; i++) {
      const float ang = fpos * __powf(10000.f, -(float)i * 0.125f);
      float sn, cs; sincosf(ang, &sn, &cs);
      const float x1 = x[i], x2 = x[8 + i];
      x[i]     = x1 * cs - x2 * sn;
      x[8 + i] = x1 * sn + x2 * cs;
    }
#pragma unroll
    for (int i = 0; i < 12; i++) {
      const float ang = hpos * __powf(10000.f, -(float)i * (1.f / 12.f));
      float sn, cs; sincosf(ang, &sn, &cs);
      const float x1 = x[16 + i], x2 = x[28 + i];
      x[16 + i] = x1 * cs - x2 * sn;
      x[28 + i] = x1 * sn + x2 * cs;
    }
#pragma unroll
    for (int i = 0; i < 12; i++) {
      const float ang = wpos * __powf(10000.f, -(float)i * (1.f / 12.f));
      float sn, cs; sincosf(ang, &sn, &cs);
      const float x1 = x[40 + i], x2 = x[52 + i];
      x[40 + i] = x1 * cs - x2 * sn;
      x[52 + i] = x1 * sn + x2 * cs;
    }
  }
#pragma unroll
  for (int d = 0; d < 64; d += 4)
    *reinterpret_cast<float4*>(dst + d) =
        make_float4(tf32_rna(x[d]), tf32_rna(x[d+1]), tf32_rna(x[d+2]), tf32_rna(x[d+3]));
}

__global__ void qkv_prep_kernel(const float* __restrict__ qkv,
                                const float* __restrict__ qw, const float* __restrict__ qb,
                                const float* __restrict__ kw, const float* __restrict__ kb,
                                float* __restrict__ qt, float* __restrict__ kt,
                                float* __restrict__ vt) {
  const int idx = blockIdx.x * blockDim.x + threadIdx.x;
  if (idx >= M_ATTN * NHEAD) return;
  const int m = idx >> 4;
  const int h = idx & 15;
  const int bc = m / T_ATTN;
  const int t  = m - bc * T_ATTN;
  const size_t src = (size_t)m * 3072 + h * HDIM;
  const size_t dst = ((size_t)(bc * NHEAD + h) * T_ATTN + t) * HDIM;
  norm_rope_one(qkv + src,        qw, qb, qt + dst, t);
  norm_rope_one(qkv + src + 1024, kw, kb, kt + dst, t);
#pragma unroll
  for (int d = 0; d < 64; d += 4) {
    const float4 v4 = *reinterpret_cast<const float4*>(qkv + src + 2048 + d);
    *reinterpret_cast<float4*>(vt + dst + d) =
        make_float4(tf32_rna(v4.x), tf32_rna(v4.y), tf32_rna(v4.z), tf32_rna(v4.w));
  }
}

// ---------------------------------------------------------------------------
// Flash attention tf32 (R4 sync version) + coalesced perm epilogue.
// attnp uses SEG_PAD(1280)-row segments so 64-row windows tile-align.
// ---------------------------------------------------------------------------
#define FS 68
#define FA_SMEM ((4 * 64 * FS + 192) * 4)

__global__ void __launch_bounds__(256) flash_tf32_kernel(
    const float* __restrict__ Qt, const float* __restrict__ Kt,
    const float* __restrict__ Vt, float* __restrict__ Outp) {
  extern __shared__ float sm[];
  float* Qs = sm;
  float* Ks = sm + 64 * FS;
  float* Vs = sm + 2 * 64 * FS;
  float* Ss = sm + 3 * 64 * FS;
  float* sm_m  = sm + 4 * 64 * FS;
  float* sm_l  = sm_m + 64;
  float* sm_sc = sm_m + 128;

  const int mat = blockIdx.y;
  const int q0  = blockIdx.x * 64;
  const int tid = threadIdx.x;
  const int warp = tid >> 5;
  const int lane = tid & 31;
  const int gr = lane >> 2;
  const int gc = lane & 3;
  const int wm = (warp & 3) * 16;
  const int wn = (warp >> 2) * 32;

  const float* Qb = Qt + (size_t)mat * T_ATTN * HDIM;
  const float* Kb = Kt + (size_t)mat * T_ATTN * HDIM;
  const float* Vb = Vt + (size_t)mat * T_ATTN * HDIM;

  if (tid < 64) { sm_m[tid] = -1e30f; sm_l[tid] = 0.f; }

  {
    const int r  = tid >> 2;
    const int d0 = (tid & 3) << 4;
    const int gq = q0 + r;
#pragma unroll
    for (int i = 0; i < 16; i += 4) {
      float4 v4 = make_float4(0.f, 0.f, 0.f, 0.f);
      if (gq < T_ATTN)
        v4 = *reinterpret_cast<const float4*>(Qb + (size_t)gq * HDIM + d0 + i);
      *reinterpret_cast<float4*>(&Qs[r * FS + d0 + i]) = v4;
    }
  }
  __syncthreads();

  uint32_t qf[8][4];
#pragma unroll
  for (int kb = 0; kb < 8; kb++) {
    const int base = (wm + gr) * FS + kb * 8 + gc;
    qf[kb][0] = __float_as_uint(Qs[base]);
    qf[kb][1] = __float_as_uint(Qs[base + 8 * FS]);
    qf[kb][2] = __float_as_uint(Qs[base + 4]);
    qf[kb][3] = __float_as_uint(Qs[base + 8 * FS + 4]);
  }

  float acc[4][4];
#pragma unroll
  for (int ni = 0; ni < 4; ni++)
#pragma unroll
    for (int j = 0; j < 4; j++) acc[ni][j] = 0.f;

  for (int k0 = 0; k0 < T_ATTN; k0 += 64) {
    {
      const int r  = tid >> 2;
      const int d0 = (tid & 3) << 4;
      const int gk = k0 + r;
#pragma unroll
      for (int i = 0; i < 16; i += 4) {
        float4 kv = make_float4(0.f, 0.f, 0.f, 0.f);
        float4 vv = make_float4(0.f, 0.f, 0.f, 0.f);
        if (gk < T_ATTN) {
          kv = *reinterpret_cast<const float4*>(Kb + (size_t)gk * HDIM + d0 + i);
          vv = *reinterpret_cast<const float4*>(Vb + (size_t)gk * HDIM + d0 + i);
        }
        *reinterpret_cast<float4*>(&Ks[r * FS + d0 + i]) = kv;
        *reinterpret_cast<float4*>(&Vs[r * FS + d0 + i]) = vv;
      }
    }
    __syncthreads();

    float sacc[4][4];
#pragma unroll
    for (int ni = 0; ni < 4; ni++)
#pragma unroll
      for (int j = 0; j < 4; j++) sacc[ni][j] = 0.f;
#pragma unroll
    for (int kb = 0; kb < 8; kb++) {
      uint32_t bf[4][2];
#pragma unroll
      for (int ni = 0; ni < 4; ni++) {
        const int kbase = (wn + ni * 8 + gr) * FS + kb * 8 + gc;
        bf[ni][0] = __float_as_uint(Ks[kbase]);
        bf[ni][1] = __float_as_uint(Ks[kbase + 4]);
      }
#pragma unroll
      for (int ni = 0; ni < 4; ni++) {
        asm volatile(
            "mma.sync.aligned.m16n8k8.row.col.f32.tf32.tf32.f32 "
            "{%0,%1,%2,%3}, {%4,%5,%6,%7}, {%8,%9}, {%0,%1,%2,%3};"
            : "+f"(sacc[ni][0]), "+f"(sacc[ni][1]),
              "+f"(sacc[ni][2]), "+f"(sacc[ni][3])
            : "r"(qf[kb][0]), "r"(qf[kb][1]), "r"(qf[kb][2]), "r"(qf[kb][3]),
              "r"(bf[ni][0]), "r"(bf[ni][1]));
      }
    }

#pragma unroll
    for (int ni = 0; ni < 4; ni++) {
      const int col = wn + ni * 8 + (gc << 1);
      const int gk  = k0 + col;
      float2 s0, s1;
      s0.x = (gk     < T_ATTN) ? sacc[ni][0] * ATTN_SCALE : -1e30f;
      s0.y = (gk + 1 < T_ATTN) ? sacc[ni][1] * ATTN_SCALE : -1e30f;
      s1.x = (gk     < T_ATTN) ? sacc[ni][2] * ATTN_SCALE : -1e30f;
      s1.y = (gk + 1 < T_ATTN) ? sacc[ni][3] * ATTN_SCALE : -1e30f;
      *reinterpret_cast<float2*>(&Ss[(wm + gr) * FS + col])     = s0;
      *reinterpret_cast<float2*>(&Ss[(wm + 8 + gr) * FS + col]) = s1;
    }
    __syncthreads();

    {
      const int row = tid >> 2;
      const int qq  = tid & 3;
      float* rp = &Ss[row * FS + qq * 16];
      float v[16];
#pragma unroll
      for (int i = 0; i < 16; i += 4) {
        const float4 t4 = *reinterpret_cast<const float4*>(rp + i);
        v[i] = t4.x; v[i+1] = t4.y; v[i+2] = t4.z; v[i+3] = t4.w;
      }
      float mx = v[0];
#pragma unroll
      for (int i = 1; i < 16; i++) mx = fmaxf(mx, v[i]);
      mx = fmaxf(mx, __shfl_xor_sync(0xffffffffu, mx, 1));
      mx = fmaxf(mx, __shfl_xor_sync(0xffffffffu, mx, 2));
      const float m_old = sm_m[row];
      const float m_new = fmaxf(m_old, mx);
      const float sc = __expf(m_old - m_new);
      float sum = 0.f;
#pragma unroll
      for (int i = 0; i < 16; i++) {
        const float p = tf32_rna(__expf(v[i] - m_new));
        v[i] = p; sum += p;
      }
#pragma unroll
      for (int i = 0; i < 16; i += 4)
        *reinterpret_cast<float4*>(rp + i) = make_float4(v[i], v[i+1], v[i+2], v[i+3]);
      sum += __shfl_xor_sync(0xffffffffu, sum, 1);
      sum += __shfl_xor_sync(0xffffffffu, sum, 2);
      if (qq == 0) {
        sm_sc[row] = sc;
        sm_m[row]  = m_new;
        sm_l[row]  = sm_l[row] * sc + sum;
      }
    }
    __syncthreads();

    {
      const float sc0 = sm_sc[wm + gr];
      const float sc1 = sm_sc[wm + 8 + gr];
#pragma unroll
      for (int ni = 0; ni < 4; ni++) {
        acc[ni][0] *= sc0; acc[ni][1] *= sc0;
        acc[ni][2] *= sc1; acc[ni][3] *= sc1;
      }
#pragma unroll
      for (int kb = 0; kb < 8; kb++) {
        uint32_t af[4];
        const int abase = (wm + gr) * FS + kb * 8 + gc;
        af[0] = __float_as_uint(Ss[abase]);
        af[1] = __float_as_uint(Ss[abase + 8 * FS]);
        af[2] = __float_as_uint(Ss[abase + 4]);
        af[3] = __float_as_uint(Ss[abase + 8 * FS + 4]);
        uint32_t bf[4][2];
#pragma unroll
        for (int ni = 0; ni < 4; ni++) {
          const int vbase = (kb * 8 + gc) * FS + wn + ni * 8 + gr;
          bf[ni][0] = __float_as_uint(Vs[vbase]);
          bf[ni][1] = __float_as_uint(Vs[vbase + 4 * FS]);
        }
#pragma unroll
        for (int ni = 0; ni < 4; ni++) {
          asm volatile(
              "mma.sync.aligned.m16n8k8.row.col.f32.tf32.tf32.f32 "
              "{%0,%1,%2,%3}, {%4,%5,%6,%7}, {%8,%9}, {%0,%1,%2,%3};"
              : "+f"(acc[ni][0]), "+f"(acc[ni][1]),
                "+f"(acc[ni][2]), "+f"(acc[ni][3])
              : "r"(af[0]), "r"(af[1]), "r"(af[2]), "r"(af[3]),
                "r"(bf[ni][0]), "r"(bf[ni][1]));
        }
      }
    }
    __syncthreads();
  }

  // stage normalized output in Ss, then write coalesced A-perm float4s
  {
    const float inv0 = 1.f / sm_l[wm + gr];
    const float inv1 = 1.f / sm_l[wm + 8 + gr];
#pragma unroll
    for (int ni = 0; ni < 4; ni++) {
      const int col = wn + ni * 8 + (gc << 1);
      Ss[(wm + gr) * FS + col]         = acc[ni][0] * inv0;
      Ss[(wm + gr) * FS + col + 1]     = acc[ni][1] * inv0;
      Ss[(wm + 8 + gr) * FS + col]     = acc[ni][2] * inv1;
      Ss[(wm + 8 + gr) * FS + col + 1] = acc[ni][3] * inv1;
    }
  }
  __syncthreads();
  {
    const int bc = mat >> 4;
    const int h  = mat & 15;
    const int w0 = bc * SEG_PAD + q0;      // multiple of 64
    const int rb = w0 >> 7;
    const int g0 = (w0 >> 4) & 7;          // 0 or 4
    for (int ii = tid; ii < 1024; ii += 256) {
      const int l2   = ii & 31;
      const int half = (ii >> 5) & 1;
      const int ktl  = (ii >> 6) & 3;
      const int gg   = (ii >> 8) & 3;
      const int rl = gg * 16 + (l2 >> 2);
      const int cl = ktl * 16 + half * 8 + (l2 & 3);
      float4 o;
      o.x = tf32_rna(Ss[rl * FS + cl]);
      o.y = tf32_rna(Ss[(rl + 8) * FS + cl]);
      o.z = tf32_rna(Ss[rl * FS + cl + 4]);
      o.w = tf32_rna(Ss[(rl + 8) * FS + cl + 4]);
      const int kt = h * 4 + ktl;
      const size_t off = ((size_t)(rb * 64 + kt)) * 2048 +
                         ((((g0 + gg) << 1) + half) << 7) + (l2 << 2);
      *reinterpret_cast<float4*>(Outp + off) = o;
    }
  }
}

// ---------------------------------------------------------------------------
// build emb (reads padded proj: SEG_PAD rows per segment)
// ---------------------------------------------------------------------------
__global__ void build_emb_kernel(const float* __restrict__ proj,
                                 float* __restrict__ emb) {
  const int idx = blockIdx.x * blockDim.x + threadIdx.x;
  if (idx >= SEQ_SSM * 256) return;
  const int i  = idx >> 8;
  const int d4 = (idx & 255) << 2;
  float4 o;
  if (i < SEQ_TXT) {
    const int c = i / TXT_LEN;
    const int t = i - c * TXT_LEN;
    o = *reinterpret_cast<const float4*>(proj + ((size_t)(c * SEG_PAD + t)) * D_MODEL + d4);
  } else {
    const int p = i - SEQ_TXT;
    float4 acc = make_float4(0.f, 0.f, 0.f, 0.f);
    int cnt = 0;
#pragma unroll
    for (int c = 0; c < 4; c++) {
      const int j = p - c * 768;
      if (j >= 0 && j < CHUNK_VID) {
        const float4 v4 = *reinterpret_cast<const float4*>(
            proj + ((size_t)(c * SEG_PAD + TXT_LEN + j)) * D_MODEL + d4);
        acc.x += v4.x; acc.y += v4.y; acc.z += v4.z; acc.w += v4.w;
        cnt++;
      }
    }
    const float inv = 1.f / (float)cnt;
    o.x = acc.x * inv; o.y = acc.y * inv; o.z = acc.z * inv; o.w = acc.w * inv;
  }
  *reinterpret_cast<float4*>(emb + (size_t)i * D_MODEL + d4) = o;
}

// ---------------------------------------------------------------------------
// Parallel SSM scan
// ---------------------------------------------------------------------------
__global__ void scan_pass1_kernel(const float* __restrict__ u,
                                  const float* __restrict__ gate,
                                  float* __restrict__ hloc,
                                  float* __restrict__ carry) {
  const int d = blockIdx.x * 256 + threadIdx.x;
  const int c = blockIdx.y;
  const float a = 1.f / (1.f + expf(-gate[d]));
  const int t0 = c * 128;
  const int t1 = (t0 + 128 < SEQ_SSM) ? (t0 + 128) : SEQ_SSM;
  float hv = 0.f;
  for (int t = t0; t < t1; t++) {
    hv = fmaf(a, hv, u[(size_t)t * D_MODEL + d]);
    hloc[(size_t)t * D_MODEL + d] = hv;
  }
  carry[c * 1024 + d] = hv;
}

__global__ void scan_pass2_kernel(const float* __restrict__ gate,
                                  float* __restrict__ carry) {
  const int d = blockIdx.x * 256 + threadIdx.x;
  const float a = 1.f / (1.f + expf(-gate[d]));
  const float a128 = __powf(a, 128.f);
  float s = 0.f;
  for (int c = 0; c < NCHUNK; c++) {
    const float cv = carry[c * 1024 + d];
    carry[c * 1024 + d] = s;
    s = a128 * s + cv;
  }
}

// pass3: fixup + coalesced A-perm write. Chunks (128) == perm tiles (128).
__global__ void scan_pass3_perm4(const float* __restrict__ hloc,
                                 const float* __restrict__ gate,
                                 const float* __restrict__ carry,
                                 float* __restrict__ hp) {
  const int idx = blockIdx.x * 256 + threadIdx.x;
  const APermIdx ix = aperm_decode(idx);
  const int chunk = ix.r0 >> 7;
  const int t0 = chunk << 7;
  const float a0 = 1.f / (1.f + expf(-gate[ix.c0]));
  const float a1 = 1.f / (1.f + expf(-gate[ix.c0 + 4]));
  const float cin0 = carry[chunk * 1024 + ix.c0];
  const float cin1 = carry[chunk * 1024 + ix.c0 + 4];
  const float e = (float)(ix.r0 - t0 + 1);
  const float p0  = __powf(a0, e);
  const float p1  = __powf(a1, e);
  const float p0b = p0 * __powf(a0, 8.f);
  const float p1b = p1 * __powf(a1, 8.f);
  auto ld = [&](int r, int c) -> float {
    return (r < SEQ_SSM) ? hloc[(size_t)r * D_MODEL + c] : 0.f;
  };
  float4 o;
  o.x = (ix.r0     < SEQ_SSM) ? tf32_rna(ld(ix.r0,     ix.c0)     + p0  * cin0) : 0.f;
  o.y = (ix.r0 + 8 < SEQ_SSM) ? tf32_rna(ld(ix.r0 + 8, ix.c0)     + p0b * cin0) : 0.f;
  o.z = (ix.r0     < SEQ_SSM) ? tf32_rna(ld(ix.r0,     ix.c0 + 4) + p1  * cin1) : 0.f;
  o.w = (ix.r0 + 8 < SEQ_SSM) ? tf32_rna(ld(ix.r0 + 8, ix.c0 + 4) + p1b * cin1) : 0.f;
  *reinterpret_cast<float4*>(hp + ix.off) = o;
}

// ---------------------------------------------------------------------------
// gates / final
// ---------------------------------------------------------------------------
__global__ void gate_add_kernel(const float* __restrict__ base, const float* __restrict__ y,
                                const float* __restrict__ gt, const float* __restrict__ gv,
                                float* __restrict__ out) {
  const int idx = blockIdx.x * blockDim.x + threadIdx.x;
  if (idx >= SEQ_SSM * 256) return;
  const int i  = idx >> 8;
  const int d4 = (idx & 255) << 2;
  const float* g = (i < SEQ_TXT) ? gt : gv;
  const float4 b4 = *reinterpret_cast<const float4*>(base + (size_t)i * D_MODEL + d4);
  const float4 y4 = *reinterpret_cast<const float4*>(y + (size_t)i * D_MODEL + d4);
  float4 o;
  o.x = b4.x + tanhf(g[d4 + 0]) * y4.x;
  o.y = b4.y + tanhf(g[d4 + 1]) * y4.y;
  o.z = b4.z + tanhf(g[d4 + 2]) * y4.z;
  o.w = b4.w + tanhf(g[d4 + 3]) * y4.w;
  *reinterpret_cast<float4*>(out + (size_t)i * D_MODEL + d4) = o;
}

__global__ void final_kernel(const float* __restrict__ emb2, const float* __restrict__ y2,
                             const float* __restrict__ gt, const float* __restrict__ gv,
                             float* __restrict__ out) {
  const int idx = blockIdx.x * blockDim.x + threadIdx.x;
  if (idx >= SEQ_SSM * 256) return;
  const int i  = idx >> 8;
  const int d4 = (idx & 255) << 2;
  const int s = rev_map(i);
  const float* g = (i < SEQ_TXT) ? gt : gv;
  const float4 e4 = *reinterpret_cast<const float4*>(emb2 + (size_t)i * D_MODEL + d4);
  const float4 y4 = *reinterpret_cast<const float4*>(y2 + (size_t)s * D_MODEL + d4);
  float4 o;
  o.x = e4.x + tanhf(g[d4 + 0]) * y4.x;
  o.y = e4.y + tanhf(g[d4 + 1]) * y4.y;
  o.z = e4.z + tanhf(g[d4 + 2]) * y4.z;
  o.w = e4.w + tanhf(g[d4 + 3]) * y4.w;
  const int dst = (i < SEQ_TXT) ? (VID_LEN + i) : (i - SEQ_TXT);
  *reinterpret_cast<float4*>(out + (size_t)dst * D_MODEL + d4) = o;
}

// ---------------------------------------------------------------------------
// Launch
// ---------------------------------------------------------------------------
static float* sym_addr(const void* symbol) {
  void* p = nullptr;
  cudaGetSymbolAddress(&p, symbol);
  return (float*)p;
}

extern "C" void kernel_launch(void* const* d_in, const int* in_sizes, int n_in,
                              void* d_out, int out_size) {
  (void)in_sizes; (void)n_in; (void)out_size;
  const float* vid   = (const float*)d_in[0];
  const float* txt   = (const float*)d_in[1];
  const float* Wq    = (const float*)d_in[2];
  const float* bq    = (const float*)d_in[3];
  const float* Wk    = (const float*)d_in[4];
  const float* bk    = (const float*)d_in[5];
  const float* Wv    = (const float*)d_in[6];
  const float* bv    = (const float*)d_in[7];
  const float* Wo    = (const float*)d_in[8];
  const float* bo    = (const float*)d_in[9];
  const float* qn_w  = (const float*)d_in[10];
  const float* qn_b  = (const float*)d_in[11];
  const float* kn_w  = (const float*)d_in[12];
  const float* kn_b  = (const float*)d_in[13];
  const float* Win   = (const float*)d_in[14];
  const float* Wout  = (const float*)d_in[15];
  const float* gate  = (const float*)d_in[16];
  const float* fg_t  = (const float*)d_in[17];
  const float* fg_v  = (const float*)d_in[18];
  const float* bg_t  = (const float*)d_in[19];
  const float* bg_v  = (const float*)d_in[20];
  float* out = (float*)d_out;

  float* curp  = sym_addr(g_curp);
  float* qkv   = sym_addr(g_qkv);
  float* qt    = sym_addr(g_qt);
  float* kt    = sym_addr(g_kt);
  float* vt    = sym_addr(g_vt);
  float* attnp = sym_addr(g_attnp);
  float* proj  = sym_addr(g_proj);
  float* emb   = sym_addr(g_emb);
  float* embp  = sym_addr(g_embp);
  float* u     = sym_addr(g_u);
  float* hloc  = sym_addr(g_hloc);
  float* hp    = sym_addr(g_hp);
  float* y     = sym_addr(g_y);
  float* emb2  = sym_addr(g_emb2);
  float* revp  = sym_addr(g_revp);
  float* carry = sym_addr(g_carry);
  float* wqkv  = sym_addr(g_wqkv);
  float* bqkv  = sym_addr(g_bqkv);
  float* wo_p  = sym_addr(g_wo);
  float* win_p  = sym_addr(g_win);
  float* wout_p = sym_addr(g_wout);

  cudaFuncSetAttribute(flash_tf32_kernel, cudaFuncAttributeMaxDynamicSharedMemorySize, FA_SMEM);

  pack_qkv_perm_kernel<<<dim3(12, 1024), 256>>>(Wq, Wk, Wv, wqkv);
  pack_bias_kernel<<<4, 256>>>(bq, bk, bv, bqkv);
  pack_b_perm_kernel<<<dim3(4, 1024), 256>>>(Wo, wo_p);
  pack_b_perm_kernel<<<dim3(4, 1024), 256>>>(Win, win_p);
  pack_b_perm_kernel<<<dim3(4, 1024), 256>>>(Wout, wout_p);

  gather_cur_perm4<<<5120, 256>>>(vid, txt, curp);
  tf32_gemm_perm<<<dim3(24, 40), 256>>>(curp, wqkv, bqkv, qkv, M_ATTN, 3072);
  qkv_prep_kernel<<<(M_ATTN * NHEAD) / 128, 128>>>(qkv, qn_w, qn_b, kn_w, kn_b,
                                                   qt, kt, vt);
  flash_tf32_kernel<<<dim3(20, 64), 256, FA_SMEM>>>(qt, kt, vt, attnp);
  tf32_gemm_perm<<<dim3(8, 40), 256>>>(attnp, wo_p, bo, proj, M_PAD, 1024);
  build_emb_kernel<<<SEQ_SSM, 256>>>(proj, emb);
  rowmajor_to_aperm4<<<4352, 256>>>(emb, embp);

  tf32_gemm_perm<<<dim3(8, 34), 256>>>(embp, win_p, nullptr, u, SEQ_SSM, 1024);
  scan_pass1_kernel<<<dim3(4, NCHUNK), 256>>>(u, gate, hloc, carry);
  scan_pass2_kernel<<<4, 256>>>(gate, carry);
  scan_pass3_perm4<<<4352, 256>>>(hloc, gate, carry, hp);
  tf32_gemm_perm<<<dim3(8, 34), 256>>>(hp, wout_p, nullptr, y, SEQ_SSM, 1024);
  gate_add_kernel<<<SEQ_SSM, 256>>>(emb, y, fg_t, fg_v, emb2);

  rev_perm4<<<4352, 256>>>(emb2, revp);
  tf32_gemm_perm<<<dim3(8, 34), 256>>>(revp, win_p, nullptr, u, SEQ_SSM, 1024);
  scan_pass1_kernel<<<dim3(4, NCHUNK), 256>>>(u, gate, hloc, carry);
  scan_pass2_kernel<<<4, 256>>>(gate, carry);
  scan_pass3_perm4<<<4352, 256>>>(hloc, gate, carry, hp);
  tf32_gemm_perm<<<dim3(8, 34), 256>>>(hp, wout_p, nullptr, y, SEQ_SSM, 1024);
  final_kernel<<<SEQ_SSM, 256>>>(emb2, y, bg_t, bg_v, out);
}

// round 9
// speedup vs baseline: 1.6215x; 1.0442x over previous
#include <cuda_runtime.h>
#include <cuda_bf16.h>
#include <cstdint>

// ---------------------------------------------------------------------------
// Problem constants
// ---------------------------------------------------------------------------
#define D_MODEL 1024
#define NHEAD   16
#define HDIM    64
#define TXT_LEN 226
#define CHUNKS  4
#define SEQ_TXT 904
#define VID_LEN 3328
#define CHUNK_VID 1024
#define T_ATTN  1250
#define SEG_PAD 1280
#define M_ATTN  5000
#define M_PAD   5120
#define SEQ_SSM 4232
#define ATTN_SCALE 0.125f
#define NCHUNK  34

// ---------------------------------------------------------------------------
// Scratch (static __device__)
// ---------------------------------------------------------------------------
__device__ float g_curp [5242880];
__device__ float g_qkv  [15360000];
__device__ float g_qt   [5120000];
__device__ float g_kt   [5120000];
__device__ float g_vt   [5120000];
__device__ float g_attnp[5242880];
__device__ float g_proj [5242880];
__device__ float g_emb  [4333568];
__device__ float g_embp [4456448];
__device__ float g_u    [4333568];
__device__ float g_hloc [4333568];
__device__ float g_hp   [4456448];
__device__ float g_y    [4333568];
__device__ float g_emb2 [4333568];
__device__ float g_revp [4456448];
__device__ float g_carry[34816];
__device__ float g_wqkv[3145728];
__device__ float g_bqkv[3072];
__device__ float g_wo  [1048576];
__device__ float g_win [1048576];
__device__ float g_wout[1048576];

__device__ __forceinline__ float tf32_rna(float x) {
  float r;
  asm("cvt.rna.tf32.f32 %0, %1;" : "=f"(r) : "f"(x));
  return r;
}

// B-fragment permuted offset for element (k, c) of a 1024xN weight matrix.
__device__ __forceinline__ size_t bperm_off(int k, int c) {
  const int nb = c >> 7, kt = k >> 4;
  const int n8 = (c >> 3) & 15;
  const int kb = (k >> 3) & 1;
  const int j  = (k >> 2) & 1;
  const int lane = ((c & 7) << 2) | (k & 3);
  return ((size_t)(nb * 64 + kt)) * 2048 + (((n8 << 1) + kb) << 6) +
         (lane << 1) + j;
}

// A-perm float4 decode
struct APermIdx { int r0, c0; size_t off; };
__device__ __forceinline__ APermIdx aperm_decode(int idx) {
  const int lane = idx & 31;
  const int half = (idx >> 5) & 1;
  const int g    = (idx >> 6) & 7;
  const int kt   = (idx >> 9) & 63;
  const int rb   = idx >> 15;
  APermIdx o;
  o.r0  = rb * 128 + g * 16 + (lane >> 2);
  o.c0  = kt * 16 + half * 8 + (lane & 3);
  o.off = ((size_t)(rb * 64 + kt)) * 2048 + (((g << 1) + half) << 7) + (lane << 2);
  return o;
}

__device__ __forceinline__ void cp16(uint32_t s, const void* g) {
  asm volatile("cp.async.cg.shared.global [%0], [%1], 16;" :: "r"(s), "l"(g));
}

// ---------------------------------------------------------------------------
// Weight packing
// ---------------------------------------------------------------------------
__global__ void pack_qkv_perm_kernel(const float* __restrict__ Wq,
                                     const float* __restrict__ Wk,
                                     const float* __restrict__ Wv,
                                     float* __restrict__ dst) {
  const int c = blockIdx.x * 256 + threadIdx.x;
  const int k = blockIdx.y;
  const float* W = (c < 1024) ? Wq : (c < 2048) ? Wk : Wv;
  dst[bperm_off(k, c)] = tf32_rna(W[(size_t)k * 1024 + (c & 1023)]);
}

__global__ void pack_bias_kernel(const float* __restrict__ bq,
                                 const float* __restrict__ bk,
                                 const float* __restrict__ bv,
                                 float* __restrict__ bp) {
  const int i = blockIdx.x * 256 + threadIdx.x;
  if (i < 1024) { bp[i] = bq[i]; bp[1024 + i] = bk[i]; bp[2048 + i] = bv[i]; }
}

// fused: Wo / Win / Wout in one launch
__global__ void pack3_b_perm_kernel(const float* __restrict__ W0,
                                    const float* __restrict__ W1,
                                    const float* __restrict__ W2,
                                    float* __restrict__ D0,
                                    float* __restrict__ D1,
                                    float* __restrict__ D2) {
  const int cx = blockIdx.x * 256 + threadIdx.x;   // < 3072
  const int k  = blockIdx.y;
  const int c  = cx & 1023;
  const float* W; float* D;
  if (cx < 1024)      { W = W0; D = D0; }
  else if (cx < 2048) { W = W1; D = D1; }
  else                { W = W2; D = D2; }
  D[bperm_off(k, c)] = tf32_rna(W[(size_t)k * 1024 + c]);
}

// ---------------------------------------------------------------------------
// TF32 GEMM on fragment-permuted operands (R4 config — known good).
// ---------------------------------------------------------------------------
#define STAGES 3
__global__ void __launch_bounds__(256) tf32_gemm_perm(
    const float* __restrict__ Ap, const float* __restrict__ Bp,
    const float* __restrict__ bias, float* __restrict__ C,
    int M, int N) {
  __shared__ float As[STAGES][2048];
  __shared__ float Bs[STAGES][2048];
  const int tid = threadIdx.x;
  const int warp = tid >> 5, lane = tid & 31;
  const int ws = warp & 3;
  const int wn = (warp >> 2) << 6;
  const int grp = lane >> 2, gcc = lane & 3;
  const int rb = blockIdx.y, nb = blockIdx.x;
  const float* Abase = Ap + (size_t)rb * 64 * 2048;
  const float* Bbase = Bp + (size_t)nb * 64 * 2048;
  const uint32_t sA = (uint32_t)__cvta_generic_to_shared(&As[0][0]);
  const uint32_t sB = (uint32_t)__cvta_generic_to_shared(&Bs[0][0]);

  float acc[2][8][4];
#pragma unroll
  for (int mi = 0; mi < 2; mi++)
#pragma unroll
    for (int ni = 0; ni < 8; ni++)
#pragma unroll
      for (int j = 0; j < 4; j++) acc[mi][ni][j] = 0.f;

  auto issue = [&](int kt, int s) {
    const float* ga = Abase + (size_t)kt * 2048;
    const float* gb = Bbase + (size_t)kt * 2048;
    const uint32_t da = sA + s * 8192 + tid * 16;
    const uint32_t db = sB + s * 8192 + tid * 16;
    cp16(da,        ga + tid * 4);
    cp16(da + 4096, ga + 1024 + tid * 4);
    cp16(db,        gb + tid * 4);
    cp16(db + 4096, gb + 1024 + tid * 4);
    asm volatile("cp.async.commit_group;");
  };

  issue(0, 0);
  issue(1, 1);

  int s = 0;
  for (int kt = 0; kt < 64; kt++) {
    if (kt < 62) { asm volatile("cp.async.wait_group 1;"); }
    else         { asm volatile("cp.async.wait_group 0;"); }
    __syncthreads();
    if (kt + 2 < 64) issue(kt + 2, (kt + 2) % STAGES);

    const float4* a4 = reinterpret_cast<const float4*>(As[s]);
    const float2* b2 = reinterpret_cast<const float2*>(Bs[s]);
#pragma unroll
    for (int kb = 0; kb < 2; kb++) {
      float4 af[2];
      float2 bf[8];
#pragma unroll
      for (int mi = 0; mi < 2; mi++)
        af[mi] = a4[((((ws << 1) + mi) * 2 + kb) << 5) + lane];
#pragma unroll
      for (int ni = 0; ni < 8; ni++)
        bf[ni] = b2[((((wn >> 3) + ni) * 2 + kb) << 5) + lane];
#pragma unroll
      for (int mi = 0; mi < 2; mi++) {
        const uint32_t a0 = __float_as_uint(af[mi].x);
        const uint32_t a1 = __float_as_uint(af[mi].y);
        const uint32_t a2 = __float_as_uint(af[mi].z);
        const uint32_t a3 = __float_as_uint(af[mi].w);
#pragma unroll
        for (int ni = 0; ni < 8; ni++) {
          asm volatile(
              "mma.sync.aligned.m16n8k8.row.col.f32.tf32.tf32.f32 "
              "{%0,%1,%2,%3}, {%4,%5,%6,%7}, {%8,%9}, {%0,%1,%2,%3};"
              : "+f"(acc[mi][ni][0]), "+f"(acc[mi][ni][1]),
                "+f"(acc[mi][ni][2]), "+f"(acc[mi][ni][3])
              : "r"(a0), "r"(a1), "r"(a2), "r"(a3),
                "r"(__float_as_uint(bf[ni].x)), "r"(__float_as_uint(bf[ni].y)));
        }
      }
    }
    s = (s + 1) % STAGES;
  }

  const int row0 = rb * 128 + ws * 32;
  const int col0 = nb * 128 + wn;
#pragma unroll
  for (int mi = 0; mi < 2; mi++) {
    const int row = row0 + mi * 16 + grp;
#pragma unroll
    for (int ni = 0; ni < 8; ni++) {
      const int col = col0 + ni * 8 + (gcc << 1);
      float b0 = 0.f, b1 = 0.f;
      if (bias) { b0 = __ldg(bias + col); b1 = __ldg(bias + col + 1); }
      if (row < M) {
        float2 o; o.x = acc[mi][ni][0] + b0; o.y = acc[mi][ni][1] + b1;
        *reinterpret_cast<float2*>(C + (size_t)row * N + col) = o;
      }
      if (row + 8 < M) {
        float2 o; o.x = acc[mi][ni][2] + b0; o.y = acc[mi][ni][3] + b1;
        *reinterpret_cast<float2*>(C + (size_t)(row + 8) * N + col) = o;
      }
    }
  }
}

// ---------------------------------------------------------------------------
// Coalesced A-perm writers
// ---------------------------------------------------------------------------
__global__ void gather_cur_perm4(const float* __restrict__ vid,
                                 const float* __restrict__ txt,
                                 float* __restrict__ curp) {
  const int idx = blockIdx.x * 256 + threadIdx.x;
  const APermIdx ix = aperm_decode(idx);
  auto ld = [&](int r, int c) -> float {
    if (r >= M_ATTN) return 0.f;
    const int bc = r / T_ATTN;
    const int t  = r - bc * T_ATTN;
    return (t < TXT_LEN)
        ? txt[(size_t)(bc * TXT_LEN + t) * D_MODEL + c]
        : vid[(size_t)(bc * 768 + (t - TXT_LEN)) * D_MODEL + c];
  };
  float4 o;
  o.x = tf32_rna(ld(ix.r0,     ix.c0));
  o.y = tf32_rna(ld(ix.r0 + 8, ix.c0));
  o.z = tf32_rna(ld(ix.r0,     ix.c0 + 4));
  o.w = tf32_rna(ld(ix.r0 + 8, ix.c0 + 4));
  *reinterpret_cast<float4*>(curp + ix.off) = o;
}

__global__ void rowmajor_to_aperm4(const float* __restrict__ src,
                                   float* __restrict__ dst) {
  const int idx = blockIdx.x * 256 + threadIdx.x;
  const APermIdx ix = aperm_decode(idx);
  auto ld = [&](int r, int c) -> float {
    return (r < SEQ_SSM) ? src[(size_t)r * D_MODEL + c] : 0.f;
  };
  float4 o;
  o.x = tf32_rna(ld(ix.r0,     ix.c0));
  o.y = tf32_rna(ld(ix.r0 + 8, ix.c0));
  o.z = tf32_rna(ld(ix.r0,     ix.c0 + 4));
  o.w = tf32_rna(ld(ix.r0 + 8, ix.c0 + 4));
  *reinterpret_cast<float4*>(dst + ix.off) = o;
}

__device__ __forceinline__ int rev_map(int i) {
  if (i < SEQ_TXT) {
    const int c = i / TXT_LEN;
    return (3 - c) * TXT_LEN + (i - c * TXT_LEN);
  }
  return 5135 - i;
}

__global__ void rev_perm4(const float* __restrict__ src, float* __restrict__ dst) {
  const int idx = blockIdx.x * 256 + threadIdx.x;
  const APermIdx ix = aperm_decode(idx);
  auto ld = [&](int r, int c) -> float {
    return (r < SEQ_SSM) ? src[(size_t)rev_map(r) * D_MODEL + c] : 0.f;
  };
  float4 o;
  o.x = tf32_rna(ld(ix.r0,     ix.c0));
  o.y = tf32_rna(ld(ix.r0 + 8, ix.c0));
  o.z = tf32_rna(ld(ix.r0,     ix.c0 + 4));
  o.w = tf32_rna(ld(ix.r0 + 8, ix.c0 + 4));
  *reinterpret_cast<float4*>(dst + ix.off) = o;
}

// ---------------------------------------------------------------------------
// LayerNorm + RoPE + transpose
// ---------------------------------------------------------------------------
__device__ __forceinline__ void norm_rope_one(const float* __restrict__ src,
                                              const float* __restrict__ w,
                                              const float* __restrict__ b,
                                              float* __restrict__ dst, int t) {
  float x[64];
  float s = 0.f, ss = 0.f;
#pragma unroll
  for (int d = 0; d < 64; d++) {
    const float a = src[d];
    x[d] = a; s += a; ss += a * a;
  }
  const float mu  = s * (1.f / 64.f);
  const float var = ss * (1.f / 64.f) - mu * mu;
  const float rr  = rsqrtf(var + 1e-6f);
#pragma unroll
  for (int d = 0; d < 64; d++) x[d] = (x[d] - mu) * rr * w[d] + b[d];

  if (t >= TXT_LEN) {
    const int p = t - TXT_LEN;
    const float fpos = (float)(p >> 8);
    const int rem = p & 255;
    const float hpos = (float)(rem >> 4);
    const float wpos = (float)(rem & 15);
#pragma unroll
    for (int i = 0; i < 8; i++) {
      const float ang = fpos * __powf(10000.f, -(float)i * 0.125f);
      float sn, cs; sincosf(ang, &sn, &cs);
      const float x1 = x[i], x2 = x[8 + i];
      x[i]     = x1 * cs - x2 * sn;
      x[8 + i] = x1 * sn + x2 * cs;
    }
#pragma unroll
    for (int i = 0; i < 12; i++) {
      const float ang = hpos * __powf(10000.f, -(float)i * (1.f / 12.f));
      float sn, cs; sincosf(ang, &sn, &cs);
      const float x1 = x[16 + i], x2 = x[28 + i];
      x[16 + i] = x1 * cs - x2 * sn;
      x[28 + i] = x1 * sn + x2 * cs;
    }
#pragma unroll
    for (int i = 0; i < 12; i++) {
      const float ang = wpos * __powf(10000.f, -(float)i * (1.f / 12.f));
      float sn, cs; sincosf(ang, &sn, &cs);
      const float x1 = x[40 + i], x2 = x[52 + i];
      x[40 + i] = x1 * cs - x2 * sn;
      x[52 + i] = x1 * sn + x2 * cs;
    }
  }
#pragma unroll
  for (int d = 0; d < 64; d += 4)
    *reinterpret_cast<float4*>(dst + d) =
        make_float4(tf32_rna(x[d]), tf32_rna(x[d+1]), tf32_rna(x[d+2]), tf32_rna(x[d+3]));
}

__global__ void qkv_prep_kernel(const float* __restrict__ qkv,
                                const float* __restrict__ qw, const float* __restrict__ qb,
                                const float* __restrict__ kw, const float* __restrict__ kb,
                                float* __restrict__ qt, float* __restrict__ kt,
                                float* __restrict__ vt) {
  const int idx = blockIdx.x * blockDim.x + threadIdx.x;
  if (idx >= M_ATTN * NHEAD) return;
  const int m = idx >> 4;
  const int h = idx & 15;
  const int bc = m / T_ATTN;
  const int t  = m - bc * T_ATTN;
  const size_t src = (size_t)m * 3072 + h * HDIM;
  const size_t dst = ((size_t)(bc * NHEAD + h) * T_ATTN + t) * HDIM;
  norm_rope_one(qkv + src,        qw, qb, qt + dst, t);
  norm_rope_one(qkv + src + 1024, kw, kb, kt + dst, t);
#pragma unroll
  for (int d = 0; d < 64; d += 4) {
    const float4 v4 = *reinterpret_cast<const float4*>(qkv + src + 2048 + d);
    *reinterpret_cast<float4*>(vt + dst + d) =
        make_float4(tf32_rna(v4.x), tf32_rna(v4.y), tf32_rna(v4.z), tf32_rna(v4.w));
  }
}

// ---------------------------------------------------------------------------
// Flash attention tf32, 128-query-row tiles, sync K/V loads.
// 8 warps; warp w owns S rows [w*16, w*16+16) x 64 cols.
// ---------------------------------------------------------------------------
#define FS 68
#define FA_SMEM ((384 * FS + 384) * 4)

__global__ void __launch_bounds__(256) flash_tf32_kernel(
    const float* __restrict__ Qt, const float* __restrict__ Kt,
    const float* __restrict__ Vt, float* __restrict__ Outp) {
  extern __shared__ float sm[];
  float* Qs = sm;                   // [128][FS]
  float* Ks = sm + 128 * FS;        // [64][FS]
  float* Vs = sm + 192 * FS;        // [64][FS]
  float* Ss = sm + 256 * FS;        // [128][FS]
  float* sm_m  = sm + 384 * FS;     // [128]
  float* sm_l  = sm_m + 128;        // [128]
  float* sm_sc = sm_m + 256;        // [128]

  const int mat = blockIdx.y;
  const int q0  = blockIdx.x * 128;
  const int tid = threadIdx.x;
  const int warp = tid >> 5;
  const int lane = tid & 31;
  const int gr = lane >> 2;
  const int gc = lane & 3;
  const int wm = warp * 16;

  const float* Qb = Qt + (size_t)mat * T_ATTN * HDIM;
  const float* Kb = Kt + (size_t)mat * T_ATTN * HDIM;
  const float* Vb = Vt + (size_t)mat * T_ATTN * HDIM;

  if (tid < 128) { sm_m[tid] = -1e30f; sm_l[tid] = 0.f; }

  // load Q tile: 128 rows; 256 threads -> 2 rows per thread-pass
  {
    const int r  = tid >> 1;             // 0..127
    const int d0 = (tid & 1) << 5;       // 0 or 32
    const int gq = q0 + r;
#pragma unroll
    for (int i = 0; i < 32; i += 4) {
      float4 v4 = make_float4(0.f, 0.f, 0.f, 0.f);
      if (gq < T_ATTN)
        v4 = *reinterpret_cast<const float4*>(Qb + (size_t)gq * HDIM + d0 + i);
      *reinterpret_cast<float4*>(&Qs[r * FS + d0 + i]) = v4;
    }
  }
  __syncthreads();

  uint32_t qf[8][4];
#pragma unroll
  for (int kb = 0; kb < 8; kb++) {
    const int base = (wm + gr) * FS + kb * 8 + gc;
    qf[kb][0] = __float_as_uint(Qs[base]);
    qf[kb][1] = __float_as_uint(Qs[base + 8 * FS]);
    qf[kb][2] = __float_as_uint(Qs[base + 4]);
    qf[kb][3] = __float_as_uint(Qs[base + 8 * FS + 4]);
  }

  float acc[8][4];
#pragma unroll
  for (int ni = 0; ni < 8; ni++)
#pragma unroll
    for (int j = 0; j < 4; j++) acc[ni][j] = 0.f;

  for (int k0 = 0; k0 < T_ATTN; k0 += 64) {
    // load K,V tile (64 rows)
    {
      const int r  = tid >> 2;
      const int d0 = (tid & 3) << 4;
      const int gk = k0 + r;
#pragma unroll
      for (int i = 0; i < 16; i += 4) {
        float4 kv = make_float4(0.f, 0.f, 0.f, 0.f);
        float4 vv = make_float4(0.f, 0.f, 0.f, 0.f);
        if (gk < T_ATTN) {
          kv = *reinterpret_cast<const float4*>(Kb + (size_t)gk * HDIM + d0 + i);
          vv = *reinterpret_cast<const float4*>(Vb + (size_t)gk * HDIM + d0 + i);
        }
        *reinterpret_cast<float4*>(&Ks[r * FS + d0 + i]) = kv;
        *reinterpret_cast<float4*>(&Vs[r * FS + d0 + i]) = vv;
      }
    }
    __syncthreads();

    // S = Q @ K^T : warp rows wm..+16, all 64 cols
    float sacc[8][4];
#pragma unroll
    for (int ni = 0; ni < 8; ni++)
#pragma unroll
      for (int j = 0; j < 4; j++) sacc[ni][j] = 0.f;
#pragma unroll
    for (int kb = 0; kb < 8; kb++) {
      uint32_t bf[8][2];
#pragma unroll
      for (int ni = 0; ni < 8; ni++) {
        const int kbase = (ni * 8 + gr) * FS + kb * 8 + gc;
        bf[ni][0] = __float_as_uint(Ks[kbase]);
        bf[ni][1] = __float_as_uint(Ks[kbase + 4]);
      }
#pragma unroll
      for (int ni = 0; ni < 8; ni++) {
        asm volatile(
            "mma.sync.aligned.m16n8k8.row.col.f32.tf32.tf32.f32 "
            "{%0,%1,%2,%3}, {%4,%5,%6,%7}, {%8,%9}, {%0,%1,%2,%3};"
            : "+f"(sacc[ni][0]), "+f"(sacc[ni][1]),
              "+f"(sacc[ni][2]), "+f"(sacc[ni][3])
            : "r"(qf[kb][0]), "r"(qf[kb][1]), "r"(qf[kb][2]), "r"(qf[kb][3]),
              "r"(bf[ni][0]), "r"(bf[ni][1]));
      }
    }

#pragma unroll
    for (int ni = 0; ni < 8; ni++) {
      const int col = ni * 8 + (gc << 1);
      const int gk  = k0 + col;
      float2 s0, s1;
      s0.x = (gk     < T_ATTN) ? sacc[ni][0] * ATTN_SCALE : -1e30f;
      s0.y = (gk + 1 < T_ATTN) ? sacc[ni][1] * ATTN_SCALE : -1e30f;
      s1.x = (gk     < T_ATTN) ? sacc[ni][2] * ATTN_SCALE : -1e30f;
      s1.y = (gk + 1 < T_ATTN) ? sacc[ni][3] * ATTN_SCALE : -1e30f;
      *reinterpret_cast<float2*>(&Ss[(wm + gr) * FS + col])     = s0;
      *reinterpret_cast<float2*>(&Ss[(wm + 8 + gr) * FS + col]) = s1;
    }
    __syncthreads();

    // softmax: 2 threads per row, 32 cols each
    {
      const int row = tid >> 1;
      const int qq  = tid & 1;
      float* rp = &Ss[row * FS + qq * 32];
      float v[32];
#pragma unroll
      for (int i = 0; i < 32; i += 4) {
        const float4 t4 = *reinterpret_cast<const float4*>(rp + i);
        v[i] = t4.x; v[i+1] = t4.y; v[i+2] = t4.z; v[i+3] = t4.w;
      }
      float mx = v[0];
#pragma unroll
      for (int i = 1; i < 32; i++) mx = fmaxf(mx, v[i]);
      mx = fmaxf(mx, __shfl_xor_sync(0xffffffffu, mx, 1));
      const float m_old = sm_m[row];
      const float m_new = fmaxf(m_old, mx);
      const float sc = __expf(m_old - m_new);
      float sum = 0.f;
#pragma unroll
      for (int i = 0; i < 32; i++) {
        const float p = tf32_rna(__expf(v[i] - m_new));
        v[i] = p; sum += p;
      }
#pragma unroll
      for (int i = 0; i < 32; i += 4)
        *reinterpret_cast<float4*>(rp + i) = make_float4(v[i], v[i+1], v[i+2], v[i+3]);
      sum += __shfl_xor_sync(0xffffffffu, sum, 1);
      if (qq == 0) {
        sm_sc[row] = sc;
        sm_m[row]  = m_new;
        sm_l[row]  = sm_l[row] * sc + sum;
      }
    }
    __syncthreads();

    // PV: warp rows wm..+16, d-cols 0..64
    {
      const float sc0 = sm_sc[wm + gr];
      const float sc1 = sm_sc[wm + 8 + gr];
#pragma unroll
      for (int ni = 0; ni < 8; ni++) {
        acc[ni][0] *= sc0; acc[ni][1] *= sc0;
        acc[ni][2] *= sc1; acc[ni][3] *= sc1;
      }
#pragma unroll
      for (int kb = 0; kb < 8; kb++) {
        uint32_t af[4];
        const int abase = (wm + gr) * FS + kb * 8 + gc;
        af[0] = __float_as_uint(Ss[abase]);
        af[1] = __float_as_uint(Ss[abase + 8 * FS]);
        af[2] = __float_as_uint(Ss[abase + 4]);
        af[3] = __float_as_uint(Ss[abase + 8 * FS + 4]);
        uint32_t bf[8][2];
#pragma unroll
        for (int ni = 0; ni < 8; ni++) {
          const int vbase = (kb * 8 + gc) * FS + ni * 8 + gr;
          bf[ni][0] = __float_as_uint(Vs[vbase]);
          bf[ni][1] = __float_as_uint(Vs[vbase + 4 * FS]);
        }
#pragma unroll
        for (int ni = 0; ni < 8; ni++) {
          asm volatile(
              "mma.sync.aligned.m16n8k8.row.col.f32.tf32.tf32.f32 "
              "{%0,%1,%2,%3}, {%4,%5,%6,%7}, {%8,%9}, {%0,%1,%2,%3};"
              : "+f"(acc[ni][0]), "+f"(acc[ni][1]),
                "+f"(acc[ni][2]), "+f"(acc[ni][3])
              : "r"(af[0]), "r"(af[1]), "r"(af[2]), "r"(af[3]),
                "r"(bf[ni][0]), "r"(bf[ni][1]));
        }
      }
    }
    __syncthreads();
  }

  // stage normalized output in Ss, then coalesced perm write (128-aligned)
  {
    const float inv0 = 1.f / sm_l[wm + gr];
    const float inv1 = 1.f / sm_l[wm + 8 + gr];
#pragma unroll
    for (int ni = 0; ni < 8; ni++) {
      const int col = ni * 8 + (gc << 1);
      Ss[(wm + gr) * FS + col]         = acc[ni][0] * inv0;
      Ss[(wm + gr) * FS + col + 1]     = acc[ni][1] * inv0;
      Ss[(wm + 8 + gr) * FS + col]     = acc[ni][2] * inv1;
      Ss[(wm + 8 + gr) * FS + col + 1] = acc[ni][3] * inv1;
    }
  }
  __syncthreads();
  {
    const int bc = mat >> 4;
    const int h  = mat & 15;
    const int rb = (bc * SEG_PAD + q0) >> 7;   // tile-aligned
    for (int ii = tid; ii < 2048; ii += 256) {
      const int l2   = ii & 31;
      const int half = (ii >> 5) & 1;
      const int ktl  = (ii >> 6) & 3;
      const int gg   = (ii >> 8) & 7;
      const int rl = gg * 16 + (l2 >> 2);
      const int cl = ktl * 16 + half * 8 + (l2 & 3);
      float4 o;
      o.x = tf32_rna(Ss[rl * FS + cl]);
      o.y = tf32_rna(Ss[(rl + 8) * FS + cl]);
      o.z = tf32_rna(Ss[rl * FS + cl + 4]);
      o.w = tf32_rna(Ss[(rl + 8) * FS + cl + 4]);
      const int kt = h * 4 + ktl;
      const size_t off = ((size_t)(rb * 64 + kt)) * 2048 +
                         (((gg << 1) + half) << 7) + (l2 << 2);
      *reinterpret_cast<float4*>(Outp + off) = o;
    }
  }
}

// ---------------------------------------------------------------------------
// build emb (reads padded proj)
// ---------------------------------------------------------------------------
__global__ void build_emb_kernel(const float* __restrict__ proj,
                                 float* __restrict__ emb) {
  const int idx = blockIdx.x * blockDim.x + threadIdx.x;
  if (idx >= SEQ_SSM * 256) return;
  const int i  = idx >> 8;
  const int d4 = (idx & 255) << 2;
  float4 o;
  if (i < SEQ_TXT) {
    const int c = i / TXT_LEN;
    const int t = i - c * TXT_LEN;
    o = *reinterpret_cast<const float4*>(proj + ((size_t)(c * SEG_PAD + t)) * D_MODEL + d4);
  } else {
    const int p = i - SEQ_TXT;
    float4 acc = make_float4(0.f, 0.f, 0.f, 0.f);
    int cnt = 0;
#pragma unroll
    for (int c = 0; c < 4; c++) {
      const int j = p - c * 768;
      if (j >= 0 && j < CHUNK_VID) {
        const float4 v4 = *reinterpret_cast<const float4*>(
            proj + ((size_t)(c * SEG_PAD + TXT_LEN + j)) * D_MODEL + d4);
        acc.x += v4.x; acc.y += v4.y; acc.z += v4.z; acc.w += v4.w;
        cnt++;
      }
    }
    const float inv = 1.f / (float)cnt;
    o.x = acc.x * inv; o.y = acc.y * inv; o.z = acc.z * inv; o.w = acc.w * inv;
  }
  *reinterpret_cast<float4*>(emb + (size_t)i * D_MODEL + d4) = o;
}

// ---------------------------------------------------------------------------
// Parallel SSM scan
// ---------------------------------------------------------------------------
__global__ void scan_pass1_kernel(const float* __restrict__ u,
                                  const float* __restrict__ gate,
                                  float* __restrict__ hloc,
                                  float* __restrict__ carry) {
  const int d = blockIdx.x * 256 + threadIdx.x;
  const int c = blockIdx.y;
  const float a = 1.f / (1.f + expf(-gate[d]));
  const int t0 = c * 128;
  const int t1 = (t0 + 128 < SEQ_SSM) ? (t0 + 128) : SEQ_SSM;
  float hv = 0.f;
  for (int t = t0; t < t1; t++) {
    hv = fmaf(a, hv, u[(size_t)t * D_MODEL + d]);
    hloc[(size_t)t * D_MODEL + d] = hv;
  }
  carry[c * 1024 + d] = hv;
}

__global__ void scan_pass2_kernel(const float* __restrict__ gate,
                                  float* __restrict__ carry) {
  const int d = blockIdx.x * 256 + threadIdx.x;
  const float a = 1.f / (1.f + expf(-gate[d]));
  const float a128 = __powf(a, 128.f);
  float s = 0.f;
  for (int c = 0; c < NCHUNK; c++) {
    const float cv = carry[c * 1024 + d];
    carry[c * 1024 + d] = s;
    s = a128 * s + cv;
  }
}

__global__ void scan_pass3_perm4(const float* __restrict__ hloc,
                                 const float* __restrict__ gate,
                                 const float* __restrict__ carry,
                                 float* __restrict__ hp) {
  const int idx = blockIdx.x * 256 + threadIdx.x;
  const APermIdx ix = aperm_decode(idx);
  const int chunk = ix.r0 >> 7;
  const int t0 = chunk << 7;
  const float a0 = 1.f / (1.f + expf(-gate[ix.c0]));
  const float a1 = 1.f / (1.f + expf(-gate[ix.c0 + 4]));
  const float cin0 = carry[chunk * 1024 + ix.c0];
  const float cin1 = carry[chunk * 1024 + ix.c0 + 4];
  const float e = (float)(ix.r0 - t0 + 1);
  const float p0  = __powf(a0, e);
  const float p1  = __powf(a1, e);
  const float p0b = p0 * __powf(a0, 8.f);
  const float p1b = p1 * __powf(a1, 8.f);
  auto ld = [&](int r, int c) -> float {
    return (r < SEQ_SSM) ? hloc[(size_t)r * D_MODEL + c] : 0.f;
  };
  float4 o;
  o.x = (ix.r0     < SEQ_SSM) ? tf32_rna(ld(ix.r0,     ix.c0)     + p0  * cin0) : 0.f;
  o.y = (ix.r0 + 8 < SEQ_SSM) ? tf32_rna(ld(ix.r0 + 8, ix.c0)     + p0b * cin0) : 0.f;
  o.z = (ix.r0     < SEQ_SSM) ? tf32_rna(ld(ix.r0,     ix.c0 + 4) + p1  * cin1) : 0.f;
  o.w = (ix.r0 + 8 < SEQ_SSM) ? tf32_rna(ld(ix.r0 + 8, ix.c0 + 4) + p1b * cin1) : 0.f;
  *reinterpret_cast<float4*>(hp + ix.off) = o;
}

// ---------------------------------------------------------------------------
// gates / final
// ---------------------------------------------------------------------------
__global__ void gate_add_kernel(const float* __restrict__ base, const float* __restrict__ y,
                                const float* __restrict__ gt, const float* __restrict__ gv,
                                float* __restrict__ out) {
  const int idx = blockIdx.x * blockDim.x + threadIdx.x;
  if (idx >= SEQ_SSM * 256) return;
  const int i  = idx >> 8;
  const int d4 = (idx & 255) << 2;
  const float* g = (i < SEQ_TXT) ? gt : gv;
  const float4 b4 = *reinterpret_cast<const float4*>(base + (size_t)i * D_MODEL + d4);
  const float4 y4 = *reinterpret_cast<const float4*>(y + (size_t)i * D_MODEL + d4);
  float4 o;
  o.x = b4.x + tanhf(g[d4 + 0]) * y4.x;
  o.y = b4.y + tanhf(g[d4 + 1]) * y4.y;
  o.z = b4.z + tanhf(g[d4 + 2]) * y4.z;
  o.w = b4.w + tanhf(g[d4 + 3]) * y4.w;
  *reinterpret_cast<float4*>(out + (size_t)i * D_MODEL + d4) = o;
}

__global__ void final_kernel(const float* __restrict__ emb2, const float* __restrict__ y2,
                             const float* __restrict__ gt, const float* __restrict__ gv,
                             float* __restrict__ out) {
  const int idx = blockIdx.x * blockDim.x + threadIdx.x;
  if (idx >= SEQ_SSM * 256) return;
  const int i  = idx >> 8;
  const int d4 = (idx & 255) << 2;
  const int s = rev_map(i);
  const float* g = (i < SEQ_TXT) ? gt : gv;
  const float4 e4 = *reinterpret_cast<const float4*>(emb2 + (size_t)i * D_MODEL + d4);
  const float4 y4 = *reinterpret_cast<const float4*>(y2 + (size_t)s * D_MODEL + d4);
  float4 o;
  o.x = e4.x + tanhf(g[d4 + 0]) * y4.x;
  o.y = e4.y + tanhf(g[d4 + 1]) * y4.y;
  o.z = e4.z + tanhf(g[d4 + 2]) * y4.z;
  o.w = e4.w + tanhf(g[d4 + 3]) * y4.w;
  const int dst = (i < SEQ_TXT) ? (VID_LEN + i) : (i - SEQ_TXT);
  *reinterpret_cast<float4*>(out + (size_t)dst * D_MODEL + d4) = o;
}

// ---------------------------------------------------------------------------
// Launch
// ---------------------------------------------------------------------------
static float* sym_addr(const void* symbol) {
  void* p = nullptr;
  cudaGetSymbolAddress(&p, symbol);
  return (float*)p;
}

extern "C" void kernel_launch(void* const* d_in, const int* in_sizes, int n_in,
                              void* d_out, int out_size) {
  (void)in_sizes; (void)n_in; (void)out_size;
  const float* vid   = (const float*)d_in[0];
  const float* txt   = (const float*)d_in[1];
  const float* Wq    = (const float*)d_in[2];
  const float* bq    = (const float*)d_in[3];
  const float* Wk    = (const float*)d_in[4];
  const float* bk    = (const float*)d_in[5];
  const float* Wv    = (const float*)d_in[6];
  const float* bv    = (const float*)d_in[7];
  const float* Wo    = (const float*)d_in[8];
  const float* bo    = (const float*)d_in[9];
  const float* qn_w  = (const float*)d_in[10];
  const float* qn_b  = (const float*)d_in[11];
  const float* kn_w  = (const float*)d_in[12];
  const float* kn_b  = (const float*)d_in[13];
  const float* Win   = (const float*)d_in[14];
  const float* Wout  = (const float*)d_in[15];
  const float* gate  = (const float*)d_in[16];
  const float* fg_t  = (const float*)d_in[17];
  const float* fg_v  = (const float*)d_in[18];
  const float* bg_t  = (const float*)d_in[19];
  const float* bg_v  = (const float*)d_in[20];
  float* out = (float*)d_out;

  float* curp  = sym_addr(g_curp);
  float* qkv   = sym_addr(g_qkv);
  float* qt    = sym_addr(g_qt);
  float* kt    = sym_addr(g_kt);
  float* vt    = sym_addr(g_vt);
  float* attnp = sym_addr(g_attnp);
  float* proj  = sym_addr(g_proj);
  float* emb   = sym_addr(g_emb);
  float* embp  = sym_addr(g_embp);
  float* u     = sym_addr(g_u);
  float* hloc  = sym_addr(g_hloc);
  float* hp    = sym_addr(g_hp);
  float* y     = sym_addr(g_y);
  float* emb2  = sym_addr(g_emb2);
  float* revp  = sym_addr(g_revp);
  float* carry = sym_addr(g_carry);
  float* wqkv  = sym_addr(g_wqkv);
  float* bqkv  = sym_addr(g_bqkv);
  float* wo_p  = sym_addr(g_wo);
  float* win_p  = sym_addr(g_win);
  float* wout_p = sym_addr(g_wout);

  cudaFuncSetAttribute(flash_tf32_kernel, cudaFuncAttributeMaxDynamicSharedMemorySize, FA_SMEM);

  pack_qkv_perm_kernel<<<dim3(12, 1024), 256>>>(Wq, Wk, Wv, wqkv);
  pack_bias_kernel<<<4, 256>>>(bq, bk, bv, bqkv);
  pack3_b_perm_kernel<<<dim3(12, 1024), 256>>>(Wo, Win, Wout, wo_p, win_p, wout_p);

  gather_cur_perm4<<<5120, 256>>>(vid, txt, curp);
  tf32_gemm_perm<<<dim3(24, 40), 256>>>(curp, wqkv, bqkv, qkv, M_ATTN, 3072);
  qkv_prep_kernel<<<(M_ATTN * NHEAD) / 128, 128>>>(qkv, qn_w, qn_b, kn_w, kn_b,
                                                   qt, kt, vt);
  flash_tf32_kernel<<<dim3(10, 64), 256, FA_SMEM>>>(qt, kt, vt, attnp);
  tf32_gemm_perm<<<dim3(8, 40), 256>>>(attnp, wo_p, bo, proj, M_PAD, 1024);
  build_emb_kernel<<<SEQ_SSM, 256>>>(proj, emb);
  rowmajor_to_aperm4<<<4352, 256>>>(emb, embp);

  tf32_gemm_perm<<<dim3(8, 34), 256>>>(embp, win_p, nullptr, u, SEQ_SSM, 1024);
  scan_pass1_kernel<<<dim3(4, NCHUNK), 256>>>(u, gate, hloc, carry);
  scan_pass2_kernel<<<4, 256>>>(gate, carry);
  scan_pass3_perm4<<<4352, 256>>>(hloc, gate, carry, hp);
  tf32_gemm_perm<<<dim3(8, 34), 256>>>(hp, wout_p, nullptr, y, SEQ_SSM, 1024);
  gate_add_kernel<<<SEQ_SSM, 256>>>(emb, y, fg_t, fg_v, emb2);

  rev_perm4<<<4352, 256>>>(emb2, revp);
  tf32_gemm_perm<<<dim3(8, 34), 256>>>(revp, win_p, nullptr, u, SEQ_SSM, 1024);
  scan_pass1_kernel<<<dim3(4, NCHUNK), 256>>>(u, gate, hloc, carry);
  scan_pass2_kernel<<<4, 256>>>(gate, carry);
  scan_pass3_perm4<<<4352, 256>>>(hloc, gate, carry, hp);
  tf32_gemm_perm<<<dim3(8, 34), 256>>>(hp, wout_p, nullptr, y, SEQ_SSM, 1024);
  final_kernel<<<SEQ_SSM, 256>>>(emb2, y, bg_t, bg_v, out);
}

// round 10
// speedup vs baseline: 1.7054x; 1.0517x over previous
#include <cuda_runtime.h>
#include <cuda_bf16.h>
#include <cstdint>

// ---------------------------------------------------------------------------
// Problem constants
// ---------------------------------------------------------------------------
#define D_MODEL 1024
#define NHEAD   16
#define HDIM    64
#define TXT_LEN 226
#define CHUNKS  4
#define SEQ_TXT 904
#define VID_LEN 3328
#define CHUNK_VID 1024
#define T_ATTN  1250
#define SEG_PAD 1280
#define M_ATTN  5000
#define M_PAD   5120
#define SEQ_SSM 4232
#define ATTN_SCALE 0.125f
#define NCHUNK  34

// ---------------------------------------------------------------------------
// Scratch (static __device__)
// ---------------------------------------------------------------------------
__device__ float g_curp [5242880];
__device__ float g_qkv  [15360000];
__device__ float g_qt   [5120000];
__device__ float g_kt   [5120000];
__device__ float g_vt   [5120000];
__device__ float g_attnp[5242880];
__device__ float g_proj [5242880];
__device__ float g_emb  [4333568];
__device__ float g_embp [4456448];
__device__ float g_u    [4333568];
__device__ float g_hloc [4333568];
__device__ float g_hp   [4456448];
__device__ float g_y    [4333568];
__device__ float g_emb2 [4333568];
__device__ float g_revp [4456448];
__device__ float g_carry[34816];
__device__ float g_wqkv[3145728];
__device__ float g_bqkv[3072];
__device__ float g_wo  [1048576];
__device__ float g_win [1048576];
__device__ float g_wout[1048576];

__device__ __forceinline__ float tf32_rna(float x) {
  float r;
  asm("cvt.rna.tf32.f32 %0, %1;" : "=f"(r) : "f"(x));
  return r;
}

// B-fragment permuted offset for element (k, c) of a 1024xN weight matrix.
__device__ __forceinline__ size_t bperm_off(int k, int c) {
  const int nb = c >> 7, kt = k >> 4;
  const int n8 = (c >> 3) & 15;
  const int kb = (k >> 3) & 1;
  const int j  = (k >> 2) & 1;
  const int lane = ((c & 7) << 2) | (k & 3);
  return ((size_t)(nb * 64 + kt)) * 2048 + (((n8 << 1) + kb) << 6) +
         (lane << 1) + j;
}

// A-perm float4 decode
struct APermIdx { int r0, c0; size_t off; };
__device__ __forceinline__ APermIdx aperm_decode(int idx) {
  const int lane = idx & 31;
  const int half = (idx >> 5) & 1;
  const int g    = (idx >> 6) & 7;
  const int kt   = (idx >> 9) & 63;
  const int rb   = idx >> 15;
  APermIdx o;
  o.r0  = rb * 128 + g * 16 + (lane >> 2);
  o.c0  = kt * 16 + half * 8 + (lane & 3);
  o.off = ((size_t)(rb * 64 + kt)) * 2048 + (((g << 1) + half) << 7) + (lane << 2);
  return o;
}

__device__ __forceinline__ void cp16(uint32_t s, const void* g) {
  asm volatile("cp.async.cg.shared.global [%0], [%1], 16;" :: "r"(s), "l"(g));
}

// ---------------------------------------------------------------------------
// Weight packing
// ---------------------------------------------------------------------------
__global__ void pack_qkv_perm_kernel(const float* __restrict__ Wq,
                                     const float* __restrict__ Wk,
                                     const float* __restrict__ Wv,
                                     float* __restrict__ dst) {
  const int c = blockIdx.x * 256 + threadIdx.x;
  const int k = blockIdx.y;
  const float* W = (c < 1024) ? Wq : (c < 2048) ? Wk : Wv;
  dst[bperm_off(k, c)] = tf32_rna(W[(size_t)k * 1024 + (c & 1023)]);
}

__global__ void pack_bias_kernel(const float* __restrict__ bq,
                                 const float* __restrict__ bk,
                                 const float* __restrict__ bv,
                                 float* __restrict__ bp) {
  const int i = blockIdx.x * 256 + threadIdx.x;
  if (i < 1024) { bp[i] = bq[i]; bp[1024 + i] = bk[i]; bp[2048 + i] = bv[i]; }
}

__global__ void pack3_b_perm_kernel(const float* __restrict__ W0,
                                    const float* __restrict__ W1,
                                    const float* __restrict__ W2,
                                    float* __restrict__ D0,
                                    float* __restrict__ D1,
                                    float* __restrict__ D2) {
  const int cx = blockIdx.x * 256 + threadIdx.x;
  const int k  = blockIdx.y;
  const int c  = cx & 1023;
  const float* W; float* D;
  if (cx < 1024)      { W = W0; D = D0; }
  else if (cx < 2048) { W = W1; D = D1; }
  else                { W = W2; D = D2; }
  D[bperm_off(k, c)] = tf32_rna(W[(size_t)k * 1024 + c]);
}

// ---------------------------------------------------------------------------
// TF32 GEMM on fragment-permuted operands (R4 config — known good).
// ---------------------------------------------------------------------------
#define STAGES 3
__global__ void __launch_bounds__(256) tf32_gemm_perm(
    const float* __restrict__ Ap, const float* __restrict__ Bp,
    const float* __restrict__ bias, float* __restrict__ C,
    int M, int N) {
  __shared__ float As[STAGES][2048];
  __shared__ float Bs[STAGES][2048];
  const int tid = threadIdx.x;
  const int warp = tid >> 5, lane = tid & 31;
  const int ws = warp & 3;
  const int wn = (warp >> 2) << 6;
  const int grp = lane >> 2, gcc = lane & 3;
  const int rb = blockIdx.y, nb = blockIdx.x;
  const float* Abase = Ap + (size_t)rb * 64 * 2048;
  const float* Bbase = Bp + (size_t)nb * 64 * 2048;
  const uint32_t sA = (uint32_t)__cvta_generic_to_shared(&As[0][0]);
  const uint32_t sB = (uint32_t)__cvta_generic_to_shared(&Bs[0][0]);

  float acc[2][8][4];
#pragma unroll
  for (int mi = 0; mi < 2; mi++)
#pragma unroll
    for (int ni = 0; ni < 8; ni++)
#pragma unroll
      for (int j = 0; j < 4; j++) acc[mi][ni][j] = 0.f;

  auto issue = [&](int kt, int s) {
    const float* ga = Abase + (size_t)kt * 2048;
    const float* gb = Bbase + (size_t)kt * 2048;
    const uint32_t da = sA + s * 8192 + tid * 16;
    const uint32_t db = sB + s * 8192 + tid * 16;
    cp16(da,        ga + tid * 4);
    cp16(da + 4096, ga + 1024 + tid * 4);
    cp16(db,        gb + tid * 4);
    cp16(db + 4096, gb + 1024 + tid * 4);
    asm volatile("cp.async.commit_group;");
  };

  issue(0, 0);
  issue(1, 1);

  int s = 0;
  for (int kt = 0; kt < 64; kt++) {
    if (kt < 62) { asm volatile("cp.async.wait_group 1;"); }
    else         { asm volatile("cp.async.wait_group 0;"); }
    __syncthreads();
    if (kt + 2 < 64) issue(kt + 2, (kt + 2) % STAGES);

    const float4* a4 = reinterpret_cast<const float4*>(As[s]);
    const float2* b2 = reinterpret_cast<const float2*>(Bs[s]);
#pragma unroll
    for (int kb = 0; kb < 2; kb++) {
      float4 af[2];
      float2 bf[8];
#pragma unroll
      for (int mi = 0; mi < 2; mi++)
        af[mi] = a4[((((ws << 1) + mi) * 2 + kb) << 5) + lane];
#pragma unroll
      for (int ni = 0; ni < 8; ni++)
        bf[ni] = b2[((((wn >> 3) + ni) * 2 + kb) << 5) + lane];
#pragma unroll
      for (int mi = 0; mi < 2; mi++) {
        const uint32_t a0 = __float_as_uint(af[mi].x);
        const uint32_t a1 = __float_as_uint(af[mi].y);
        const uint32_t a2 = __float_as_uint(af[mi].z);
        const uint32_t a3 = __float_as_uint(af[mi].w);
#pragma unroll
        for (int ni = 0; ni < 8; ni++) {
          asm volatile(
              "mma.sync.aligned.m16n8k8.row.col.f32.tf32.tf32.f32 "
              "{%0,%1,%2,%3}, {%4,%5,%6,%7}, {%8,%9}, {%0,%1,%2,%3};"
              : "+f"(acc[mi][ni][0]), "+f"(acc[mi][ni][1]),
                "+f"(acc[mi][ni][2]), "+f"(acc[mi][ni][3])
              : "r"(a0), "r"(a1), "r"(a2), "r"(a3),
                "r"(__float_as_uint(bf[ni].x)), "r"(__float_as_uint(bf[ni].y)));
        }
      }
    }
    s = (s + 1) % STAGES;
  }

  const int row0 = rb * 128 + ws * 32;
  const int col0 = nb * 128 + wn;
#pragma unroll
  for (int mi = 0; mi < 2; mi++) {
    const int row = row0 + mi * 16 + grp;
#pragma unroll
    for (int ni = 0; ni < 8; ni++) {
      const int col = col0 + ni * 8 + (gcc << 1);
      float b0 = 0.f, b1 = 0.f;
      if (bias) { b0 = __ldg(bias + col); b1 = __ldg(bias + col + 1); }
      if (row < M) {
        float2 o; o.x = acc[mi][ni][0] + b0; o.y = acc[mi][ni][1] + b1;
        *reinterpret_cast<float2*>(C + (size_t)row * N + col) = o;
      }
      if (row + 8 < M) {
        float2 o; o.x = acc[mi][ni][2] + b0; o.y = acc[mi][ni][3] + b1;
        *reinterpret_cast<float2*>(C + (size_t)(row + 8) * N + col) = o;
      }
    }
  }
}

// ---------------------------------------------------------------------------
// Coalesced A-perm writers
// ---------------------------------------------------------------------------
__global__ void gather_cur_perm4(const float* __restrict__ vid,
                                 const float* __restrict__ txt,
                                 float* __restrict__ curp) {
  const int idx = blockIdx.x * 256 + threadIdx.x;
  const APermIdx ix = aperm_decode(idx);
  auto ld = [&](int r, int c) -> float {
    if (r >= M_ATTN) return 0.f;
    const int bc = r / T_ATTN;
    const int t  = r - bc * T_ATTN;
    return (t < TXT_LEN)
        ? txt[(size_t)(bc * TXT_LEN + t) * D_MODEL + c]
        : vid[(size_t)(bc * 768 + (t - TXT_LEN)) * D_MODEL + c];
  };
  float4 o;
  o.x = tf32_rna(ld(ix.r0,     ix.c0));
  o.y = tf32_rna(ld(ix.r0 + 8, ix.c0));
  o.z = tf32_rna(ld(ix.r0,     ix.c0 + 4));
  o.w = tf32_rna(ld(ix.r0 + 8, ix.c0 + 4));
  *reinterpret_cast<float4*>(curp + ix.off) = o;
}

__global__ void rowmajor_to_aperm4(const float* __restrict__ src,
                                   float* __restrict__ dst) {
  const int idx = blockIdx.x * 256 + threadIdx.x;
  const APermIdx ix = aperm_decode(idx);
  auto ld = [&](int r, int c) -> float {
    return (r < SEQ_SSM) ? src[(size_t)r * D_MODEL + c] : 0.f;
  };
  float4 o;
  o.x = tf32_rna(ld(ix.r0,     ix.c0));
  o.y = tf32_rna(ld(ix.r0 + 8, ix.c0));
  o.z = tf32_rna(ld(ix.r0,     ix.c0 + 4));
  o.w = tf32_rna(ld(ix.r0 + 8, ix.c0 + 4));
  *reinterpret_cast<float4*>(dst + ix.off) = o;
}

__device__ __forceinline__ int rev_map(int i) {
  if (i < SEQ_TXT) {
    const int c = i / TXT_LEN;
    return (3 - c) * TXT_LEN + (i - c * TXT_LEN);
  }
  return 5135 - i;
}

__global__ void rev_perm4(const float* __restrict__ src, float* __restrict__ dst) {
  const int idx = blockIdx.x * 256 + threadIdx.x;
  const APermIdx ix = aperm_decode(idx);
  auto ld = [&](int r, int c) -> float {
    return (r < SEQ_SSM) ? src[(size_t)rev_map(r) * D_MODEL + c] : 0.f;
  };
  float4 o;
  o.x = tf32_rna(ld(ix.r0,     ix.c0));
  o.y = tf32_rna(ld(ix.r0 + 8, ix.c0));
  o.z = tf32_rna(ld(ix.r0,     ix.c0 + 4));
  o.w = tf32_rna(ld(ix.r0 + 8, ix.c0 + 4));
  *reinterpret_cast<float4*>(dst + ix.off) = o;
}

// ---------------------------------------------------------------------------
// LayerNorm + RoPE + transpose
// ---------------------------------------------------------------------------
__device__ __forceinline__ void norm_rope_one(const float* __restrict__ src,
                                              const float* __restrict__ w,
                                              const float* __restrict__ b,
                                              float* __restrict__ dst, int t) {
  float x[64];
  float s = 0.f, ss = 0.f;
#pragma unroll
  for (int d = 0; d < 64; d++) {
    const float a = src[d];
    x[d] = a; s += a; ss += a * a;
  }
  const float mu  = s * (1.f / 64.f);
  const float var = ss * (1.f / 64.f) - mu * mu;
  const float rr  = rsqrtf(var + 1e-6f);
#pragma unroll
  for (int d = 0; d < 64; d++) x[d] = (x[d] - mu) * rr * w[d] + b[d];

  if (t >= TXT_LEN) {
    const int p = t - TXT_LEN;
    const float fpos = (float)(p >> 8);
    const int rem = p & 255;
    const float hpos = (float)(rem >> 4);
    const float wpos = (float)(rem & 15);
#pragma unroll
    for (int i = 0; i < 8; i++) {
      const float ang = fpos * __powf(10000.f, -(float)i * 0.125f);
      float sn, cs; sincosf(ang, &sn, &cs);
      const float x1 = x[i], x2 = x[8 + i];
      x[i]     = x1 * cs - x2 * sn;
      x[8 + i] = x1 * sn + x2 * cs;
    }
#pragma unroll
    for (int i = 0; i < 12; i++) {
      const float ang = hpos * __powf(10000.f, -(float)i * (1.f / 12.f));
      float sn, cs; sincosf(ang, &sn, &cs);
      const float x1 = x[16 + i], x2 = x[28 + i];
      x[16 + i] = x1 * cs - x2 * sn;
      x[28 + i] = x1 * sn + x2 * cs;
    }
#pragma unroll
    for (int i = 0; i < 12; i++) {
      const float ang = wpos * __powf(10000.f, -(float)i * (1.f / 12.f));
      float sn, cs; sincosf(ang, &sn, &cs);
      const float x1 = x[40 + i], x2 = x[52 + i];
      x[40 + i] = x1 * cs - x2 * sn;
      x[52 + i] = x1 * sn + x2 * cs;
    }
  }
#pragma unroll
  for (int d = 0; d < 64; d += 4)
    *reinterpret_cast<float4*>(dst + d) =
        make_float4(tf32_rna(x[d]), tf32_rna(x[d+1]), tf32_rna(x[d+2]), tf32_rna(x[d+3]));
}

__global__ void qkv_prep_kernel(const float* __restrict__ qkv,
                                const float* __restrict__ qw, const float* __restrict__ qb,
                                const float* __restrict__ kw, const float* __restrict__ kb,
                                float* __restrict__ qt, float* __restrict__ kt,
                                float* __restrict__ vt) {
  const int idx = blockIdx.x * blockDim.x + threadIdx.x;
  if (idx >= M_ATTN * NHEAD) return;
  const int m = idx >> 4;
  const int h = idx & 15;
  const int bc = m / T_ATTN;
  const int t  = m - bc * T_ATTN;
  const size_t src = (size_t)m * 3072 + h * HDIM;
  const size_t dst = ((size_t)(bc * NHEAD + h) * T_ATTN + t) * HDIM;
  norm_rope_one(qkv + src,        qw, qb, qt + dst, t);
  norm_rope_one(qkv + src + 1024, kw, kb, kt + dst, t);
#pragma unroll
  for (int d = 0; d < 64; d += 4) {
    const float4 v4 = *reinterpret_cast<const float4*>(qkv + src + 2048 + d);
    *reinterpret_cast<float4*>(vt + dst + d) =
        make_float4(tf32_rna(v4.x), tf32_rna(v4.y), tf32_rna(v4.z), tf32_rna(v4.w));
  }
}

// ---------------------------------------------------------------------------
// Flash attention tf32, 128-row tiles, in-warp softmax (2 block syncs/tile).
// ---------------------------------------------------------------------------
#define FS 68
#define FA_SMEM ((384 * FS) * 4)

__global__ void __launch_bounds__(256) flash_tf32_kernel(
    const float* __restrict__ Qt, const float* __restrict__ Kt,
    const float* __restrict__ Vt, float* __restrict__ Outp) {
  extern __shared__ float sm[];
  float* Qs = sm;                   // [128][FS]
  float* Ks = sm + 128 * FS;        // [64][FS]
  float* Vs = sm + 192 * FS;        // [64][FS]
  float* Ss = sm + 256 * FS;        // [128][FS]

  const int mat = blockIdx.y;
  const int q0  = blockIdx.x * 128;
  const int tid = threadIdx.x;
  const int warp = tid >> 5;
  const int lane = tid & 31;
  const int gr = lane >> 2;
  const int gc = lane & 3;
  const int wm = warp * 16;

  const float* Qb = Qt + (size_t)mat * T_ATTN * HDIM;
  const float* Kb = Kt + (size_t)mat * T_ATTN * HDIM;
  const float* Vb = Vt + (size_t)mat * T_ATTN * HDIM;

  // load Q tile (128 rows)
  {
    const int r  = tid >> 1;
    const int d0 = (tid & 1) << 5;
    const int gq = q0 + r;
#pragma unroll
    for (int i = 0; i < 32; i += 4) {
      float4 v4 = make_float4(0.f, 0.f, 0.f, 0.f);
      if (gq < T_ATTN)
        v4 = *reinterpret_cast<const float4*>(Qb + (size_t)gq * HDIM + d0 + i);
      *reinterpret_cast<float4*>(&Qs[r * FS + d0 + i]) = v4;
    }
  }
  __syncthreads();

  uint32_t qf[8][4];
#pragma unroll
  for (int kb = 0; kb < 8; kb++) {
    const int base = (wm + gr) * FS + kb * 8 + gc;
    qf[kb][0] = __float_as_uint(Qs[base]);
    qf[kb][1] = __float_as_uint(Qs[base + 8 * FS]);
    qf[kb][2] = __float_as_uint(Qs[base + 4]);
    qf[kb][3] = __float_as_uint(Qs[base + 8 * FS + 4]);
  }
  __syncthreads();   // Qs no longer needed as staging; (kept: Ss aliases later)

  float acc[8][4];
#pragma unroll
  for (int ni = 0; ni < 8; ni++)
#pragma unroll
    for (int j = 0; j < 4; j++) acc[ni][j] = 0.f;

  // register-resident softmax state (replicated within each quad)
  float mrun0 = -1e30f, mrun1 = -1e30f;
  float lrun0 = 0.f, lrun1 = 0.f;

  for (int k0 = 0; k0 < T_ATTN; k0 += 64) {
    // load K,V tile
    {
      const int r  = tid >> 2;
      const int d0 = (tid & 3) << 4;
      const int gk = k0 + r;
#pragma unroll
      for (int i = 0; i < 16; i += 4) {
        float4 kv = make_float4(0.f, 0.f, 0.f, 0.f);
        float4 vv = make_float4(0.f, 0.f, 0.f, 0.f);
        if (gk < T_ATTN) {
          kv = *reinterpret_cast<const float4*>(Kb + (size_t)gk * HDIM + d0 + i);
          vv = *reinterpret_cast<const float4*>(Vb + (size_t)gk * HDIM + d0 + i);
        }
        *reinterpret_cast<float4*>(&Ks[r * FS + d0 + i]) = kv;
        *reinterpret_cast<float4*>(&Vs[r * FS + d0 + i]) = vv;
      }
    }
    __syncthreads();

    // S = Q @ K^T
    float sacc[8][4];
#pragma unroll
    for (int ni = 0; ni < 8; ni++)
#pragma unroll
      for (int j = 0; j < 4; j++) sacc[ni][j] = 0.f;
#pragma unroll
    for (int kb = 0; kb < 8; kb++) {
      uint32_t bf[8][2];
#pragma unroll
      for (int ni = 0; ni < 8; ni++) {
        const int kbase = (ni * 8 + gr) * FS + kb * 8 + gc;
        bf[ni][0] = __float_as_uint(Ks[kbase]);
        bf[ni][1] = __float_as_uint(Ks[kbase + 4]);
      }
#pragma unroll
      for (int ni = 0; ni < 8; ni++) {
        asm volatile(
            "mma.sync.aligned.m16n8k8.row.col.f32.tf32.tf32.f32 "
            "{%0,%1,%2,%3}, {%4,%5,%6,%7}, {%8,%9}, {%0,%1,%2,%3};"
            : "+f"(sacc[ni][0]), "+f"(sacc[ni][1]),
              "+f"(sacc[ni][2]), "+f"(sacc[ni][3])
            : "r"(qf[kb][0]), "r"(qf[kb][1]), "r"(qf[kb][2]), "r"(qf[kb][3]),
              "r"(bf[ni][0]), "r"(bf[ni][1]));
      }
    }

    // in-register mask + scale + row max (quad covers a full 64-col row)
    float m0 = -1e30f, m1 = -1e30f;
#pragma unroll
    for (int ni = 0; ni < 8; ni++) {
      const int gk = k0 + ni * 8 + (gc << 1);
      sacc[ni][0] = (gk     < T_ATTN) ? sacc[ni][0] * ATTN_SCALE : -1e30f;
      sacc[ni][1] = (gk + 1 < T_ATTN) ? sacc[ni][1] * ATTN_SCALE : -1e30f;
      sacc[ni][2] = (gk     < T_ATTN) ? sacc[ni][2] * ATTN_SCALE : -1e30f;
      sacc[ni][3] = (gk + 1 < T_ATTN) ? sacc[ni][3] * ATTN_SCALE : -1e30f;
      m0 = fmaxf(m0, fmaxf(sacc[ni][0], sacc[ni][1]));
      m1 = fmaxf(m1, fmaxf(sacc[ni][2], sacc[ni][3]));
    }
    m0 = fmaxf(m0, __shfl_xor_sync(0xffffffffu, m0, 1));
    m0 = fmaxf(m0, __shfl_xor_sync(0xffffffffu, m0, 2));
    m1 = fmaxf(m1, __shfl_xor_sync(0xffffffffu, m1, 1));
    m1 = fmaxf(m1, __shfl_xor_sync(0xffffffffu, m1, 2));
    const float mn0 = fmaxf(mrun0, m0);
    const float mn1 = fmaxf(mrun1, m1);
    const float sc0 = __expf(mrun0 - mn0);
    const float sc1 = __expf(mrun1 - mn1);
    mrun0 = mn0; mrun1 = mn1;

    float s0 = 0.f, s1 = 0.f;
#pragma unroll
    for (int ni = 0; ni < 8; ni++) {
      sacc[ni][0] = tf32_rna(__expf(sacc[ni][0] - mn0));
      sacc[ni][1] = tf32_rna(__expf(sacc[ni][1] - mn0));
      sacc[ni][2] = tf32_rna(__expf(sacc[ni][2] - mn1));
      sacc[ni][3] = tf32_rna(__expf(sacc[ni][3] - mn1));
      s0 += sacc[ni][0] + sacc[ni][1];
      s1 += sacc[ni][2] + sacc[ni][3];
    }
    s0 += __shfl_xor_sync(0xffffffffu, s0, 1);
    s0 += __shfl_xor_sync(0xffffffffu, s0, 2);
    s1 += __shfl_xor_sync(0xffffffffu, s1, 1);
    s1 += __shfl_xor_sync(0xffffffffu, s1, 2);
    lrun0 = lrun0 * sc0 + s0;
    lrun1 = lrun1 * sc1 + s1;

    // write P to own-warp rows of Ss
#pragma unroll
    for (int ni = 0; ni < 8; ni++) {
      const int col = ni * 8 + (gc << 1);
      *reinterpret_cast<float2*>(&Ss[(wm + gr) * FS + col]) =
          make_float2(sacc[ni][0], sacc[ni][1]);
      *reinterpret_cast<float2*>(&Ss[(wm + 8 + gr) * FS + col]) =
          make_float2(sacc[ni][2], sacc[ni][3]);
    }
    __syncwarp();

    // rescale acc, then PV (A fragments from own-warp Ss rows)
#pragma unroll
    for (int ni = 0; ni < 8; ni++) {
      acc[ni][0] *= sc0; acc[ni][1] *= sc0;
      acc[ni][2] *= sc1; acc[ni][3] *= sc1;
    }
#pragma unroll
    for (int kb = 0; kb < 8; kb++) {
      uint32_t af[4];
      const int abase = (wm + gr) * FS + kb * 8 + gc;
      af[0] = __float_as_uint(Ss[abase]);
      af[1] = __float_as_uint(Ss[abase + 8 * FS]);
      af[2] = __float_as_uint(Ss[abase + 4]);
      af[3] = __float_as_uint(Ss[abase + 8 * FS + 4]);
      uint32_t bf[8][2];
#pragma unroll
      for (int ni = 0; ni < 8; ni++) {
        const int vbase = (kb * 8 + gc) * FS + ni * 8 + gr;
        bf[ni][0] = __float_as_uint(Vs[vbase]);
        bf[ni][1] = __float_as_uint(Vs[vbase + 4 * FS]);
      }
#pragma unroll
      for (int ni = 0; ni < 8; ni++) {
        asm volatile(
            "mma.sync.aligned.m16n8k8.row.col.f32.tf32.tf32.f32 "
            "{%0,%1,%2,%3}, {%4,%5,%6,%7}, {%8,%9}, {%0,%1,%2,%3};"
            : "+f"(acc[ni][0]), "+f"(acc[ni][1]),
              "+f"(acc[ni][2]), "+f"(acc[ni][3])
            : "r"(af[0]), "r"(af[1]), "r"(af[2]), "r"(af[3]),
              "r"(bf[ni][0]), "r"(bf[ni][1]));
      }
    }
    __syncthreads();   // protect Ks/Vs for next tile load
  }

  // stage normalized output in Ss, coalesced perm write
  {
    const float inv0 = 1.f / lrun0;
    const float inv1 = 1.f / lrun1;
#pragma unroll
    for (int ni = 0; ni < 8; ni++) {
      const int col = ni * 8 + (gc << 1);
      Ss[(wm + gr) * FS + col]         = acc[ni][0] * inv0;
      Ss[(wm + gr) * FS + col + 1]     = acc[ni][1] * inv0;
      Ss[(wm + 8 + gr) * FS + col]     = acc[ni][2] * inv1;
      Ss[(wm + 8 + gr) * FS + col + 1] = acc[ni][3] * inv1;
    }
  }
  __syncthreads();
  {
    const int bc = mat >> 4;
    const int h  = mat & 15;
    const int rb = (bc * SEG_PAD + q0) >> 7;
    for (int ii = tid; ii < 2048; ii += 256) {
      const int l2   = ii & 31;
      const int half = (ii >> 5) & 1;
      const int ktl  = (ii >> 6) & 3;
      const int gg   = (ii >> 8) & 7;
      const int rl = gg * 16 + (l2 >> 2);
      const int cl = ktl * 16 + half * 8 + (l2 & 3);
      float4 o;
      o.x = tf32_rna(Ss[rl * FS + cl]);
      o.y = tf32_rna(Ss[(rl + 8) * FS + cl]);
      o.z = tf32_rna(Ss[rl * FS + cl + 4]);
      o.w = tf32_rna(Ss[(rl + 8) * FS + cl + 4]);
      const int kt = h * 4 + ktl;
      const size_t off = ((size_t)(rb * 64 + kt)) * 2048 +
                         (((gg << 1) + half) << 7) + (l2 << 2);
      *reinterpret_cast<float4*>(Outp + off) = o;
    }
  }
}

// ---------------------------------------------------------------------------
// build emb (reads padded proj)
// ---------------------------------------------------------------------------
__global__ void build_emb_kernel(const float* __restrict__ proj,
                                 float* __restrict__ emb) {
  const int idx = blockIdx.x * blockDim.x + threadIdx.x;
  if (idx >= SEQ_SSM * 256) return;
  const int i  = idx >> 8;
  const int d4 = (idx & 255) << 2;
  float4 o;
  if (i < SEQ_TXT) {
    const int c = i / TXT_LEN;
    const int t = i - c * TXT_LEN;
    o = *reinterpret_cast<const float4*>(proj + ((size_t)(c * SEG_PAD + t)) * D_MODEL + d4);
  } else {
    const int p = i - SEQ_TXT;
    float4 acc = make_float4(0.f, 0.f, 0.f, 0.f);
    int cnt = 0;
#pragma unroll
    for (int c = 0; c < 4; c++) {
      const int j = p - c * 768;
      if (j >= 0 && j < CHUNK_VID) {
        const float4 v4 = *reinterpret_cast<const float4*>(
            proj + ((size_t)(c * SEG_PAD + TXT_LEN + j)) * D_MODEL + d4);
        acc.x += v4.x; acc.y += v4.y; acc.z += v4.z; acc.w += v4.w;
        cnt++;
      }
    }
    const float inv = 1.f / (float)cnt;
    o.x = acc.x * inv; o.y = acc.y * inv; o.z = acc.z * inv; o.w = acc.w * inv;
  }
  *reinterpret_cast<float4*>(emb + (size_t)i * D_MODEL + d4) = o;
}

// ---------------------------------------------------------------------------
// Parallel SSM scan
// ---------------------------------------------------------------------------
__global__ void scan_pass1_kernel(const float* __restrict__ u,
                                  const float* __restrict__ gate,
                                  float* __restrict__ hloc,
                                  float* __restrict__ carry) {
  const int d = blockIdx.x * 256 + threadIdx.x;
  const int c = blockIdx.y;
  const float a = 1.f / (1.f + expf(-gate[d]));
  const int t0 = c * 128;
  const int t1 = (t0 + 128 < SEQ_SSM) ? (t0 + 128) : SEQ_SSM;
  float hv = 0.f;
  for (int t = t0; t < t1; t++) {
    hv = fmaf(a, hv, u[(size_t)t * D_MODEL + d]);
    hloc[(size_t)t * D_MODEL + d] = hv;
  }
  carry[c * 1024 + d] = hv;
}

__global__ void scan_pass2_kernel(const float* __restrict__ gate,
                                  float* __restrict__ carry) {
  const int d = blockIdx.x * 256 + threadIdx.x;
  const float a = 1.f / (1.f + expf(-gate[d]));
  const float a128 = __powf(a, 128.f);
  float s = 0.f;
  for (int c = 0; c < NCHUNK; c++) {
    const float cv = carry[c * 1024 + d];
    carry[c * 1024 + d] = s;
    s = a128 * s + cv;
  }
}

__global__ void scan_pass3_perm4(const float* __restrict__ hloc,
                                 const float* __restrict__ gate,
                                 const float* __restrict__ carry,
                                 float* __restrict__ hp) {
  const int idx = blockIdx.x * 256 + threadIdx.x;
  const APermIdx ix = aperm_decode(idx);
  const int chunk = ix.r0 >> 7;
  const int t0 = chunk << 7;
  const float a0 = 1.f / (1.f + expf(-gate[ix.c0]));
  const float a1 = 1.f / (1.f + expf(-gate[ix.c0 + 4]));
  const float cin0 = carry[chunk * 1024 + ix.c0];
  const float cin1 = carry[chunk * 1024 + ix.c0 + 4];
  const float e = (float)(ix.r0 - t0 + 1);
  const float p0  = __powf(a0, e);
  const float p1  = __powf(a1, e);
  const float p0b = p0 * __powf(a0, 8.f);
  const float p1b = p1 * __powf(a1, 8.f);
  auto ld = [&](int r, int c) -> float {
    return (r < SEQ_SSM) ? hloc[(size_t)r * D_MODEL + c] : 0.f;
  };
  float4 o;
  o.x = (ix.r0     < SEQ_SSM) ? tf32_rna(ld(ix.r0,     ix.c0)     + p0  * cin0) : 0.f;
  o.y = (ix.r0 + 8 < SEQ_SSM) ? tf32_rna(ld(ix.r0 + 8, ix.c0)     + p0b * cin0) : 0.f;
  o.z = (ix.r0     < SEQ_SSM) ? tf32_rna(ld(ix.r0,     ix.c0 + 4) + p1  * cin1) : 0.f;
  o.w = (ix.r0 + 8 < SEQ_SSM) ? tf32_rna(ld(ix.r0 + 8, ix.c0 + 4) + p1b * cin1) : 0.f;
  *reinterpret_cast<float4*>(hp + ix.off) = o;
}

// ---------------------------------------------------------------------------
// gates / final
// ---------------------------------------------------------------------------
__global__ void gate_add_kernel(const float* __restrict__ base, const float* __restrict__ y,
                                const float* __restrict__ gt, const float* __restrict__ gv,
                                float* __restrict__ out) {
  const int idx = blockIdx.x * blockDim.x + threadIdx.x;
  if (idx >= SEQ_SSM * 256) return;
  const int i  = idx >> 8;
  const int d4 = (idx & 255) << 2;
  const float* g = (i < SEQ_TXT) ? gt : gv;
  const float4 b4 = *reinterpret_cast<const float4*>(base + (size_t)i * D_MODEL + d4);
  const float4 y4 = *reinterpret_cast<const float4*>(y + (size_t)i * D_MODEL + d4);
  float4 o;
  o.x = b4.x + tanhf(g[d4 + 0]) * y4.x;
  o.y = b4.y + tanhf(g[d4 + 1]) * y4.y;
  o.z = b4.z + tanhf(g[d4 + 2]) * y4.z;
  o.w = b4.w + tanhf(g[d4 + 3]) * y4.w;
  *reinterpret_cast<float4*>(out + (size_t)i * D_MODEL + d4) = o;
}

__global__ void final_kernel(const float* __restrict__ emb2, const float* __restrict__ y2,
                             const float* __restrict__ gt, const float* __restrict__ gv,
                             float* __restrict__ out) {
  const int idx = blockIdx.x * blockDim.x + threadIdx.x;
  if (idx >= SEQ_SSM * 256) return;
  const int i  = idx >> 8;
  const int d4 = (idx & 255) << 2;
  const int s = rev_map(i);
  const float* g = (i < SEQ_TXT) ? gt : gv;
  const float4 e4 = *reinterpret_cast<const float4*>(emb2 + (size_t)i * D_MODEL + d4);
  const float4 y4 = *reinterpret_cast<const float4*>(y2 + (size_t)s * D_MODEL + d4);
  float4 o;
  o.x = e4.x + tanhf(g[d4 + 0]) * y4.x;
  o.y = e4.y + tanhf(g[d4 + 1]) * y4.y;
  o.z = e4.z + tanhf(g[d4 + 2]) * y4.z;
  o.w = e4.w + tanhf(g[d4 + 3]) * y4.w;
  const int dst = (i < SEQ_TXT) ? (VID_LEN + i) : (i - SEQ_TXT);
  *reinterpret_cast<float4*>(out + (size_t)dst * D_MODEL + d4) = o;
}

// ---------------------------------------------------------------------------
// Launch
// ---------------------------------------------------------------------------
static float* sym_addr(const void* symbol) {
  void* p = nullptr;
  cudaGetSymbolAddress(&p, symbol);
  return (float*)p;
}

extern "C" void kernel_launch(void* const* d_in, const int* in_sizes, int n_in,
                              void* d_out, int out_size) {
  (void)in_sizes; (void)n_in; (void)out_size;
  const float* vid   = (const float*)d_in[0];
  const float* txt   = (const float*)d_in[1];
  const float* Wq    = (const float*)d_in[2];
  const float* bq    = (const float*)d_in[3];
  const float* Wk    = (const float*)d_in[4];
  const float* bk    = (const float*)d_in[5];
  const float* Wv    = (const float*)d_in[6];
  const float* bv    = (const float*)d_in[7];
  const float* Wo    = (const float*)d_in[8];
  const float* bo    = (const float*)d_in[9];
  const float* qn_w  = (const float*)d_in[10];
  const float* qn_b  = (const float*)d_in[11];
  const float* kn_w  = (const float*)d_in[12];
  const float* kn_b  = (const float*)d_in[13];
  const float* Win   = (const float*)d_in[14];
  const float* Wout  = (const float*)d_in[15];
  const float* gate  = (const float*)d_in[16];
  const float* fg_t  = (const float*)d_in[17];
  const float* fg_v  = (const float*)d_in[18];
  const float* bg_t  = (const float*)d_in[19];
  const float* bg_v  = (const float*)d_in[20];
  float* out = (float*)d_out;

  float* curp  = sym_addr(g_curp);
  float* qkv   = sym_addr(g_qkv);
  float* qt    = sym_addr(g_qt);
  float* kt    = sym_addr(g_kt);
  float* vt    = sym_addr(g_vt);
  float* attnp = sym_addr(g_attnp);
  float* proj  = sym_addr(g_proj);
  float* emb   = sym_addr(g_emb);
  float* embp  = sym_addr(g_embp);
  float* u     = sym_addr(g_u);
  float* hloc  = sym_addr(g_hloc);
  float* hp    = sym_addr(g_hp);
  float* y     = sym_addr(g_y);
  float* emb2  = sym_addr(g_emb2);
  float* revp  = sym_addr(g_revp);
  float* carry = sym_addr(g_carry);
  float* wqkv  = sym_addr(g_wqkv);
  float* bqkv  = sym_addr(g_bqkv);
  float* wo_p  = sym_addr(g_wo);
  float* win_p  = sym_addr(g_win);
  float* wout_p = sym_addr(g_wout);

  cudaFuncSetAttribute(flash_tf32_kernel, cudaFuncAttributeMaxDynamicSharedMemorySize, FA_SMEM);

  pack_qkv_perm_kernel<<<dim3(12, 1024), 256>>>(Wq, Wk, Wv, wqkv);
  pack_bias_kernel<<<4, 256>>>(bq, bk, bv, bqkv);
  pack3_b_perm_kernel<<<dim3(12, 1024), 256>>>(Wo, Win, Wout, wo_p, win_p, wout_p);

  gather_cur_perm4<<<5120, 256>>>(vid, txt, curp);
  tf32_gemm_perm<<<dim3(24, 40), 256>>>(curp, wqkv, bqkv, qkv, M_ATTN, 3072);
  qkv_prep_kernel<<<(M_ATTN * NHEAD) / 128, 128>>>(qkv, qn_w, qn_b, kn_w, kn_b,
                                                   qt, kt, vt);
  flash_tf32_kernel<<<dim3(10, 64), 256, FA_SMEM>>>(qt, kt, vt, attnp);
  tf32_gemm_perm<<<dim3(8, 40), 256>>>(attnp, wo_p, bo, proj, M_PAD, 1024);
  build_emb_kernel<<<SEQ_SSM, 256>>>(proj, emb);
  rowmajor_to_aperm4<<<4352, 256>>>(emb, embp);

  tf32_gemm_perm<<<dim3(8, 34), 256>>>(embp, win_p, nullptr, u, SEQ_SSM, 1024);
  scan_pass1_kernel<<<dim3(4, NCHUNK), 256>>>(u, gate, hloc, carry);
  scan_pass2_kernel<<<4, 256>>>(gate, carry);
  scan_pass3_perm4<<<4352, 256>>>(hloc, gate, carry, hp);
  tf32_gemm_perm<<<dim3(8, 34), 256>>>(hp, wout_p, nullptr, y, SEQ_SSM, 1024);
  gate_add_kernel<<<SEQ_SSM, 256>>>(emb, y, fg_t, fg_v, emb2);

  rev_perm4<<<4352, 256>>>(emb2, revp);
  tf32_gemm_perm<<<dim3(8, 34), 256>>>(revp, win_p, nullptr, u, SEQ_SSM, 1024);
  scan_pass1_kernel<<<dim3(4, NCHUNK), 256>>>(u, gate, hloc, carry);
  scan_pass2_kernel<<<4, 256>>>(gate, carry);
  scan_pass3_perm4<<<4352, 256>>>(hloc, gate, carry, hp);
  tf32_gemm_perm<<<dim3(8, 34), 256>>>(hp, wout_p, nullptr, y, SEQ_SSM, 1024);
  final_kernel<<<SEQ_SSM, 256>>>(emb2, y, bg_t, bg_v, out);
}

// round 11
// speedup vs baseline: 1.7927x; 1.0512x over previous
#include <cuda_runtime.h>
#include <cuda_bf16.h>
#include <cstdint>

// ---------------------------------------------------------------------------
// Problem constants
// ---------------------------------------------------------------------------
#define D_MODEL 1024
#define NHEAD   16
#define HDIM    64
#define TXT_LEN 226
#define CHUNKS  4
#define SEQ_TXT 904
#define VID_LEN 3328
#define CHUNK_VID 1024
#define T_ATTN  1250
#define SEG_PAD 1280
#define M_ATTN  5000
#define M_PAD   5120
#define SEQ_SSM 4232
#define ATTN_SCALE 0.125f
#define NCHUNK  34

// ---------------------------------------------------------------------------
// Scratch (static __device__)
// ---------------------------------------------------------------------------
__device__ float g_curp [5242880];
__device__ float g_qkv  [15360000];
__device__ float g_qt   [5120000];
__device__ float g_kt   [5120000];
__device__ float g_vt   [5120000];
__device__ float g_attnp[5242880];
__device__ float g_proj [5242880];
__device__ float g_emb  [4333568];
__device__ float g_embp [4456448];
__device__ float g_u    [4333568];
__device__ float g_hloc [4333568];
__device__ float g_hp   [4456448];
__device__ float g_emb2 [4333568];
__device__ float g_revp [4456448];
__device__ float g_carry[34816];
__device__ float g_wqkv[3145728];
__device__ float g_bqkv[3072];
__device__ float g_wo  [1048576];
__device__ float g_win [1048576];
__device__ float g_wout[1048576];
__device__ float g_tg  [4096];      // tanh(fg_t), tanh(fg_v), tanh(bg_t), tanh(bg_v)

__device__ __forceinline__ float tf32_rna(float x) {
  float r;
  asm("cvt.rna.tf32.f32 %0, %1;" : "=f"(r) : "f"(x));
  return r;
}

// B-fragment permuted offset for element (k, c) of a 1024xN weight matrix.
__device__ __forceinline__ size_t bperm_off(int k, int c) {
  const int nb = c >> 7, kt = k >> 4;
  const int n8 = (c >> 3) & 15;
  const int kb = (k >> 3) & 1;
  const int j  = (k >> 2) & 1;
  const int lane = ((c & 7) << 2) | (k & 3);
  return ((size_t)(nb * 64 + kt)) * 2048 + (((n8 << 1) + kb) << 6) +
         (lane << 1) + j;
}

// A-perm float4 decode
struct APermIdx { int r0, c0; size_t off; };
__device__ __forceinline__ APermIdx aperm_decode(int idx) {
  const int lane = idx & 31;
  const int half = (idx >> 5) & 1;
  const int g    = (idx >> 6) & 7;
  const int kt   = (idx >> 9) & 63;
  const int rb   = idx >> 15;
  APermIdx o;
  o.r0  = rb * 128 + g * 16 + (lane >> 2);
  o.c0  = kt * 16 + half * 8 + (lane & 3);
  o.off = ((size_t)(rb * 64 + kt)) * 2048 + (((g << 1) + half) << 7) + (lane << 2);
  return o;
}

__device__ __forceinline__ void cp16(uint32_t s, const void* g) {
  asm volatile("cp.async.cg.shared.global [%0], [%1], 16;" :: "r"(s), "l"(g));
}

__device__ __forceinline__ int rev_map(int i) {
  if (i < SEQ_TXT) {
    const int c = i / TXT_LEN;
    return (3 - c) * TXT_LEN + (i - c * TXT_LEN);
  }
  return 5135 - i;
}

// ---------------------------------------------------------------------------
// Weight packing
// ---------------------------------------------------------------------------
__global__ void pack_qkv_perm_kernel(const float* __restrict__ Wq,
                                     const float* __restrict__ Wk,
                                     const float* __restrict__ Wv,
                                     float* __restrict__ dst) {
  const int c = blockIdx.x * 256 + threadIdx.x;
  const int k = blockIdx.y;
  const float* W = (c < 1024) ? Wq : (c < 2048) ? Wk : Wv;
  dst[bperm_off(k, c)] = tf32_rna(W[(size_t)k * 1024 + (c & 1023)]);
}

__global__ void pack_bias_kernel(const float* __restrict__ bq,
                                 const float* __restrict__ bk,
                                 const float* __restrict__ bv,
                                 float* __restrict__ bp) {
  const int i = blockIdx.x * 256 + threadIdx.x;
  if (i < 1024) { bp[i] = bq[i]; bp[1024 + i] = bk[i]; bp[2048 + i] = bv[i]; }
}

__global__ void pack3_b_perm_kernel(const float* __restrict__ W0,
                                    const float* __restrict__ W1,
                                    const float* __restrict__ W2,
                                    float* __restrict__ D0,
                                    float* __restrict__ D1,
                                    float* __restrict__ D2) {
  const int cx = blockIdx.x * 256 + threadIdx.x;
  const int k  = blockIdx.y;
  const int c  = cx & 1023;
  const float* W; float* D;
  if (cx < 1024)      { W = W0; D = D0; }
  else if (cx < 2048) { W = W1; D = D1; }
  else                { W = W2; D = D2; }
  D[bperm_off(k, c)] = tf32_rna(W[(size_t)k * 1024 + c]);
}

__global__ void tanh_prep_kernel(const float* __restrict__ fg_t,
                                 const float* __restrict__ fg_v,
                                 const float* __restrict__ bg_t,
                                 const float* __restrict__ bg_v,
                                 float* __restrict__ tg) {
  const int i = blockIdx.x * 256 + threadIdx.x;
  if (i < 1024) {
    tg[i]        = tanhf(fg_t[i]);
    tg[1024 + i] = tanhf(fg_v[i]);
    tg[2048 + i] = tanhf(bg_t[i]);
    tg[3072 + i] = tanhf(bg_v[i]);
  }
}

// ---------------------------------------------------------------------------
// TF32 GEMM, fragment-permuted operands, GBK=32, 3-stage cp.async (dyn smem).
// mode 0: C = A@B (+bias). mode 1: C = e_base + tg*acc (gate add, row select
// by row<SEQ_TXT). mode 2: final — write out[dst(rev_map(row))].
// ---------------------------------------------------------------------------
#define GEMM_SMEM (6 * 4096 * 4)   // 3 stages x (A 4096 + B 4096 floats)
__global__ void __launch_bounds__(256) tf32_gemm_perm(
    const float* __restrict__ Ap, const float* __restrict__ Bp,
    const float* __restrict__ bias, float* __restrict__ C,
    int M, int N,
    const float* __restrict__ e_base, const float* __restrict__ tga,
    const float* __restrict__ tgb, int mode) {
  extern __shared__ float smg[];
  float* As = smg;              // [3][4096]
  float* Bs = smg + 12288;      // [3][4096]
  const int tid = threadIdx.x;
  const int warp = tid >> 5, lane = tid & 31;
  const int ws = warp & 3;
  const int wn = (warp >> 2) << 6;
  const int grp = lane >> 2, gcc = lane & 3;
  const int rb = blockIdx.y, nb = blockIdx.x;
  const float* Abase = Ap + (size_t)rb * 64 * 2048;
  const float* Bbase = Bp + (size_t)nb * 64 * 2048;
  const uint32_t sA = (uint32_t)__cvta_generic_to_shared(As);
  const uint32_t sB = (uint32_t)__cvta_generic_to_shared(Bs);

  float acc[2][8][4];
#pragma unroll
  for (int mi = 0; mi < 2; mi++)
#pragma unroll
    for (int ni = 0; ni < 8; ni++)
#pragma unroll
      for (int j = 0; j < 4; j++) acc[mi][ni][j] = 0.f;

  auto issue = [&](int kt2, int s) {
    const float* ga = Abase + (size_t)kt2 * 4096;
    const float* gb = Bbase + (size_t)kt2 * 4096;
    const uint32_t da = sA + s * 16384 + tid * 16;
    const uint32_t db = sB + s * 16384 + tid * 16;
    cp16(da,         ga + tid * 4);
    cp16(da + 4096,  ga + 1024 + tid * 4);
    cp16(da + 8192,  ga + 2048 + tid * 4);
    cp16(da + 12288, ga + 3072 + tid * 4);
    cp16(db,         gb + tid * 4);
    cp16(db + 4096,  gb + 1024 + tid * 4);
    cp16(db + 8192,  gb + 2048 + tid * 4);
    cp16(db + 12288, gb + 3072 + tid * 4);
    asm volatile("cp.async.commit_group;");
  };

  issue(0, 0);
  issue(1, 1);

  int s = 0;
  const int NT = 32;
  for (int t = 0; t < NT; t++) {
    if (t < NT - 2) { asm volatile("cp.async.wait_group 1;"); }
    else            { asm volatile("cp.async.wait_group 0;"); }
    __syncthreads();
    if (t + 2 < NT) issue(t + 2, (t + 2) % 3);

    const float4* a4 = reinterpret_cast<const float4*>(As + s * 4096);
    const float2* b2 = reinterpret_cast<const float2*>(Bs + s * 4096);
#pragma unroll
    for (int kb = 0; kb < 4; kb++) {
      const int half = kb >> 1;
      const int kbl  = kb & 1;
      float4 af[2];
      float2 bf[8];
#pragma unroll
      for (int mi = 0; mi < 2; mi++)
        af[mi] = a4[half * 512 + ((((ws << 1) + mi) * 2 + kbl) << 5) + lane];
#pragma unroll
      for (int ni = 0; ni < 8; ni++)
        bf[ni] = b2[half * 1024 + ((((wn >> 3) + ni) * 2 + kbl) << 5) + lane];
#pragma unroll
      for (int mi = 0; mi < 2; mi++) {
        const uint32_t a0 = __float_as_uint(af[mi].x);
        const uint32_t a1 = __float_as_uint(af[mi].y);
        const uint32_t a2 = __float_as_uint(af[mi].z);
        const uint32_t a3 = __float_as_uint(af[mi].w);
#pragma unroll
        for (int ni = 0; ni < 8; ni++) {
          asm volatile(
              "mma.sync.aligned.m16n8k8.row.col.f32.tf32.tf32.f32 "
              "{%0,%1,%2,%3}, {%4,%5,%6,%7}, {%8,%9}, {%0,%1,%2,%3};"
              : "+f"(acc[mi][ni][0]), "+f"(acc[mi][ni][1]),
                "+f"(acc[mi][ni][2]), "+f"(acc[mi][ni][3])
              : "r"(a0), "r"(a1), "r"(a2), "r"(a3),
                "r"(__float_as_uint(bf[ni].x)), "r"(__float_as_uint(bf[ni].y)));
        }
      }
    }
    s = (s + 1) % 3;
  }

  const int row0 = rb * 128 + ws * 32;
  const int col0 = nb * 128 + wn;

  if (mode == 0) {
#pragma unroll
    for (int mi = 0; mi < 2; mi++) {
      const int row = row0 + mi * 16 + grp;
#pragma unroll
      for (int ni = 0; ni < 8; ni++) {
        const int col = col0 + ni * 8 + (gcc << 1);
        float b0 = 0.f, b1 = 0.f;
        if (bias) { b0 = __ldg(bias + col); b1 = __ldg(bias + col + 1); }
        if (row < M) {
          float2 o; o.x = acc[mi][ni][0] + b0; o.y = acc[mi][ni][1] + b1;
          *reinterpret_cast<float2*>(C + (size_t)row * N + col) = o;
        }
        if (row + 8 < M) {
          float2 o; o.x = acc[mi][ni][2] + b0; o.y = acc[mi][ni][3] + b1;
          *reinterpret_cast<float2*>(C + (size_t)(row + 8) * N + col) = o;
        }
      }
    }
  } else if (mode == 1) {
    // emb2 = emb + tanh(fg)*y   (row-selected gate)
#pragma unroll
    for (int mi = 0; mi < 2; mi++) {
#pragma unroll
      for (int rr = 0; rr < 2; rr++) {
        const int row = row0 + mi * 16 + grp + rr * 8;
        if (row >= M) continue;
        const float* tg = (row < SEQ_TXT) ? tga : tgb;
#pragma unroll
        for (int ni = 0; ni < 8; ni++) {
          const int col = col0 + ni * 8 + (gcc << 1);
          const float2 e = *reinterpret_cast<const float2*>(e_base + (size_t)row * N + col);
          const float2 t = *reinterpret_cast<const float2*>(tg + col);
          float2 o;
          o.x = e.x + t.x * acc[mi][ni][rr * 2 + 0];
          o.y = e.y + t.y * acc[mi][ni][rr * 2 + 1];
          *reinterpret_cast<float2*>(C + (size_t)row * N + col) = o;
        }
      }
    }
  } else {
    // final: this row r holds y2[r]; contributes to output index i=rev_map(r)
#pragma unroll
    for (int mi = 0; mi < 2; mi++) {
#pragma unroll
      for (int rr = 0; rr < 2; rr++) {
        const int row = row0 + mi * 16 + grp + rr * 8;
        if (row >= M) continue;
        const int i = rev_map(row);
        const int dst = (i < SEQ_TXT) ? (VID_LEN + i) : (i - SEQ_TXT);
        const float* tg = (i < SEQ_TXT) ? tga : tgb;
#pragma unroll
        for (int ni = 0; ni < 8; ni++) {
          const int col = col0 + ni * 8 + (gcc << 1);
          const float2 e = *reinterpret_cast<const float2*>(e_base + (size_t)i * N + col);
          const float2 t = *reinterpret_cast<const float2*>(tg + col);
          float2 o;
          o.x = e.x + t.x * acc[mi][ni][rr * 2 + 0];
          o.y = e.y + t.y * acc[mi][ni][rr * 2 + 1];
          *reinterpret_cast<float2*>(C + (size_t)dst * N + col) = o;
        }
      }
    }
  }
}

// ---------------------------------------------------------------------------
// Coalesced A-perm writers
// ---------------------------------------------------------------------------
__global__ void gather_cur_perm4(const float* __restrict__ vid,
                                 const float* __restrict__ txt,
                                 float* __restrict__ curp) {
  const int idx = blockIdx.x * 256 + threadIdx.x;
  const APermIdx ix = aperm_decode(idx);
  auto ld = [&](int r, int c) -> float {
    if (r >= M_ATTN) return 0.f;
    const int bc = r / T_ATTN;
    const int t  = r - bc * T_ATTN;
    return (t < TXT_LEN)
        ? txt[(size_t)(bc * TXT_LEN + t) * D_MODEL + c]
        : vid[(size_t)(bc * 768 + (t - TXT_LEN)) * D_MODEL + c];
  };
  float4 o;
  o.x = tf32_rna(ld(ix.r0,     ix.c0));
  o.y = tf32_rna(ld(ix.r0 + 8, ix.c0));
  o.z = tf32_rna(ld(ix.r0,     ix.c0 + 4));
  o.w = tf32_rna(ld(ix.r0 + 8, ix.c0 + 4));
  *reinterpret_cast<float4*>(curp + ix.off) = o;
}

__global__ void rowmajor_to_aperm4(const float* __restrict__ src,
                                   float* __restrict__ dst) {
  const int idx = blockIdx.x * 256 + threadIdx.x;
  const APermIdx ix = aperm_decode(idx);
  auto ld = [&](int r, int c) -> float {
    return (r < SEQ_SSM) ? src[(size_t)r * D_MODEL + c] : 0.f;
  };
  float4 o;
  o.x = tf32_rna(ld(ix.r0,     ix.c0));
  o.y = tf32_rna(ld(ix.r0 + 8, ix.c0));
  o.z = tf32_rna(ld(ix.r0,     ix.c0 + 4));
  o.w = tf32_rna(ld(ix.r0 + 8, ix.c0 + 4));
  *reinterpret_cast<float4*>(dst + ix.off) = o;
}

__global__ void rev_perm4(const float* __restrict__ src, float* __restrict__ dst) {
  const int idx = blockIdx.x * 256 + threadIdx.x;
  const APermIdx ix = aperm_decode(idx);
  auto ld = [&](int r, int c) -> float {
    return (r < SEQ_SSM) ? src[(size_t)rev_map(r) * D_MODEL + c] : 0.f;
  };
  float4 o;
  o.x = tf32_rna(ld(ix.r0,     ix.c0));
  o.y = tf32_rna(ld(ix.r0 + 8, ix.c0));
  o.z = tf32_rna(ld(ix.r0,     ix.c0 + 4));
  o.w = tf32_rna(ld(ix.r0 + 8, ix.c0 + 4));
  *reinterpret_cast<float4*>(dst + ix.off) = o;
}

// ---------------------------------------------------------------------------
// LayerNorm + RoPE + transpose
// ---------------------------------------------------------------------------
__device__ __forceinline__ void norm_rope_one(const float* __restrict__ src,
                                              const float* __restrict__ w,
                                              const float* __restrict__ b,
                                              float* __restrict__ dst, int t) {
  float x[64];
  float s = 0.f, ss = 0.f;
#pragma unroll
  for (int d = 0; d < 64; d++) {
    const float a = src[d];
    x[d] = a; s += a; ss += a * a;
  }
  const float mu  = s * (1.f / 64.f);
  const float var = ss * (1.f / 64.f) - mu * mu;
  const float rr  = rsqrtf(var + 1e-6f);
#pragma unroll
  for (int d = 0; d < 64; d++) x[d] = (x[d] - mu) * rr * w[d] + b[d];

  if (t >= TXT_LEN) {
    const int p = t - TXT_LEN;
    const float fpos = (float)(p >> 8);
    const int rem = p & 255;
    const float hpos = (float)(rem >> 4);
    const float wpos = (float)(rem & 15);
#pragma unroll
    for (int i = 0; i < 8; i++) {
      const float ang = fpos * __powf(10000.f, -(float)i * 0.125f);
      float sn, cs; sincosf(ang, &sn, &cs);
      const float x1 = x[i], x2 = x[8 + i];
      x[i]     = x1 * cs - x2 * sn;
      x[8 + i] = x1 * sn + x2 * cs;
    }
#pragma unroll
    for (int i = 0; i < 12; i++) {
      const float ang = hpos * __powf(10000.f, -(float)i * (1.f / 12.f));
      float sn, cs; sincosf(ang, &sn, &cs);
      const float x1 = x[16 + i], x2 = x[28 + i];
      x[16 + i] = x1 * cs - x2 * sn;
      x[28 + i] = x1 * sn + x2 * cs;
    }
#pragma unroll
    for (int i = 0; i < 12; i++) {
      const float ang = wpos * __powf(10000.f, -(float)i * (1.f / 12.f));
      float sn, cs; sincosf(ang, &sn, &cs);
      const float x1 = x[40 + i], x2 = x[52 + i];
      x[40 + i] = x1 * cs - x2 * sn;
      x[52 + i] = x1 * sn + x2 * cs;
    }
  }
#pragma unroll
  for (int d = 0; d < 64; d += 4)
    *reinterpret_cast<float4*>(dst + d) =
        make_float4(tf32_rna(x[d]), tf32_rna(x[d+1]), tf32_rna(x[d+2]), tf32_rna(x[d+3]));
}

__global__ void qkv_prep_kernel(const float* __restrict__ qkv,
                                const float* __restrict__ qw, const float* __restrict__ qb,
                                const float* __restrict__ kw, const float* __restrict__ kb,
                                float* __restrict__ qt, float* __restrict__ kt,
                                float* __restrict__ vt) {
  const int idx = blockIdx.x * blockDim.x + threadIdx.x;
  if (idx >= M_ATTN * NHEAD) return;
  const int m = idx >> 4;
  const int h = idx & 15;
  const int bc = m / T_ATTN;
  const int t  = m - bc * T_ATTN;
  const size_t src = (size_t)m * 3072 + h * HDIM;
  const size_t dst = ((size_t)(bc * NHEAD + h) * T_ATTN + t) * HDIM;
  norm_rope_one(qkv + src,        qw, qb, qt + dst, t);
  norm_rope_one(qkv + src + 1024, kw, kb, kt + dst, t);
#pragma unroll
  for (int d = 0; d < 64; d += 4) {
    const float4 v4 = *reinterpret_cast<const float4*>(qkv + src + 2048 + d);
    *reinterpret_cast<float4*>(vt + dst + d) =
        make_float4(tf32_rna(v4.x), tf32_rna(v4.y), tf32_rna(v4.z), tf32_rna(v4.w));
  }
}

// ---------------------------------------------------------------------------
// Flash attention tf32, 128-row tiles, in-warp softmax (R10 — known good).
// ---------------------------------------------------------------------------
#define FS 68
#define FA_SMEM ((384 * FS) * 4)

__global__ void __launch_bounds__(256) flash_tf32_kernel(
    const float* __restrict__ Qt, const float* __restrict__ Kt,
    const float* __restrict__ Vt, float* __restrict__ Outp) {
  extern __shared__ float sm[];
  float* Qs = sm;
  float* Ks = sm + 128 * FS;
  float* Vs = sm + 192 * FS;
  float* Ss = sm + 256 * FS;

  const int mat = blockIdx.y;
  const int q0  = blockIdx.x * 128;
  const int tid = threadIdx.x;
  const int warp = tid >> 5;
  const int lane = tid & 31;
  const int gr = lane >> 2;
  const int gc = lane & 3;
  const int wm = warp * 16;

  const float* Qb = Qt + (size_t)mat * T_ATTN * HDIM;
  const float* Kb = Kt + (size_t)mat * T_ATTN * HDIM;
  const float* Vb = Vt + (size_t)mat * T_ATTN * HDIM;

  {
    const int r  = tid >> 1;
    const int d0 = (tid & 1) << 5;
    const int gq = q0 + r;
#pragma unroll
    for (int i = 0; i < 32; i += 4) {
      float4 v4 = make_float4(0.f, 0.f, 0.f, 0.f);
      if (gq < T_ATTN)
        v4 = *reinterpret_cast<const float4*>(Qb + (size_t)gq * HDIM + d0 + i);
      *reinterpret_cast<float4*>(&Qs[r * FS + d0 + i]) = v4;
    }
  }
  __syncthreads();

  uint32_t qf[8][4];
#pragma unroll
  for (int kb = 0; kb < 8; kb++) {
    const int base = (wm + gr) * FS + kb * 8 + gc;
    qf[kb][0] = __float_as_uint(Qs[base]);
    qf[kb][1] = __float_as_uint(Qs[base + 8 * FS]);
    qf[kb][2] = __float_as_uint(Qs[base + 4]);
    qf[kb][3] = __float_as_uint(Qs[base + 8 * FS + 4]);
  }
  __syncthreads();

  float acc[8][4];
#pragma unroll
  for (int ni = 0; ni < 8; ni++)
#pragma unroll
    for (int j = 0; j < 4; j++) acc[ni][j] = 0.f;

  float mrun0 = -1e30f, mrun1 = -1e30f;
  float lrun0 = 0.f, lrun1 = 0.f;

  for (int k0 = 0; k0 < T_ATTN; k0 += 64) {
    {
      const int r  = tid >> 2;
      const int d0 = (tid & 3) << 4;
      const int gk = k0 + r;
#pragma unroll
      for (int i = 0; i < 16; i += 4) {
        float4 kv = make_float4(0.f, 0.f, 0.f, 0.f);
        float4 vv = make_float4(0.f, 0.f, 0.f, 0.f);
        if (gk < T_ATTN) {
          kv = *reinterpret_cast<const float4*>(Kb + (size_t)gk * HDIM + d0 + i);
          vv = *reinterpret_cast<const float4*>(Vb + (size_t)gk * HDIM + d0 + i);
        }
        *reinterpret_cast<float4*>(&Ks[r * FS + d0 + i]) = kv;
        *reinterpret_cast<float4*>(&Vs[r * FS + d0 + i]) = vv;
      }
    }
    __syncthreads();

    float sacc[8][4];
#pragma unroll
    for (int ni = 0; ni < 8; ni++)
#pragma unroll
      for (int j = 0; j < 4; j++) sacc[ni][j] = 0.f;
#pragma unroll
    for (int kb = 0; kb < 8; kb++) {
      uint32_t bf[8][2];
#pragma unroll
      for (int ni = 0; ni < 8; ni++) {
        const int kbase = (ni * 8 + gr) * FS + kb * 8 + gc;
        bf[ni][0] = __float_as_uint(Ks[kbase]);
        bf[ni][1] = __float_as_uint(Ks[kbase + 4]);
      }
#pragma unroll
      for (int ni = 0; ni < 8; ni++) {
        asm volatile(
            "mma.sync.aligned.m16n8k8.row.col.f32.tf32.tf32.f32 "
            "{%0,%1,%2,%3}, {%4,%5,%6,%7}, {%8,%9}, {%0,%1,%2,%3};"
            : "+f"(sacc[ni][0]), "+f"(sacc[ni][1]),
              "+f"(sacc[ni][2]), "+f"(sacc[ni][3])
            : "r"(qf[kb][0]), "r"(qf[kb][1]), "r"(qf[kb][2]), "r"(qf[kb][3]),
              "r"(bf[ni][0]), "r"(bf[ni][1]));
      }
    }

    float m0 = -1e30f, m1 = -1e30f;
#pragma unroll
    for (int ni = 0; ni < 8; ni++) {
      const int gk = k0 + ni * 8 + (gc << 1);
      sacc[ni][0] = (gk     < T_ATTN) ? sacc[ni][0] * ATTN_SCALE : -1e30f;
      sacc[ni][1] = (gk + 1 < T_ATTN) ? sacc[ni][1] * ATTN_SCALE : -1e30f;
      sacc[ni][2] = (gk     < T_ATTN) ? sacc[ni][2] * ATTN_SCALE : -1e30f;
      sacc[ni][3] = (gk + 1 < T_ATTN) ? sacc[ni][3] * ATTN_SCALE : -1e30f;
      m0 = fmaxf(m0, fmaxf(sacc[ni][0], sacc[ni][1]));
      m1 = fmaxf(m1, fmaxf(sacc[ni][2], sacc[ni][3]));
    }
    m0 = fmaxf(m0, __shfl_xor_sync(0xffffffffu, m0, 1));
    m0 = fmaxf(m0, __shfl_xor_sync(0xffffffffu, m0, 2));
    m1 = fmaxf(m1, __shfl_xor_sync(0xffffffffu, m1, 1));
    m1 = fmaxf(m1, __shfl_xor_sync(0xffffffffu, m1, 2));
    const float mn0 = fmaxf(mrun0, m0);
    const float mn1 = fmaxf(mrun1, m1);
    const float sc0 = __expf(mrun0 - mn0);
    const float sc1 = __expf(mrun1 - mn1);
    mrun0 = mn0; mrun1 = mn1;

    float s0 = 0.f, s1 = 0.f;
#pragma unroll
    for (int ni = 0; ni < 8; ni++) {
      sacc[ni][0] = tf32_rna(__expf(sacc[ni][0] - mn0));
      sacc[ni][1] = tf32_rna(__expf(sacc[ni][1] - mn0));
      sacc[ni][2] = tf32_rna(__expf(sacc[ni][2] - mn1));
      sacc[ni][3] = tf32_rna(__expf(sacc[ni][3] - mn1));
      s0 += sacc[ni][0] + sacc[ni][1];
      s1 += sacc[ni][2] + sacc[ni][3];
    }
    s0 += __shfl_xor_sync(0xffffffffu, s0, 1);
    s0 += __shfl_xor_sync(0xffffffffu, s0, 2);
    s1 += __shfl_xor_sync(0xffffffffu, s1, 1);
    s1 += __shfl_xor_sync(0xffffffffu, s1, 2);
    lrun0 = lrun0 * sc0 + s0;
    lrun1 = lrun1 * sc1 + s1;

#pragma unroll
    for (int ni = 0; ni < 8; ni++) {
      const int col = ni * 8 + (gc << 1);
      *reinterpret_cast<float2*>(&Ss[(wm + gr) * FS + col]) =
          make_float2(sacc[ni][0], sacc[ni][1]);
      *reinterpret_cast<float2*>(&Ss[(wm + 8 + gr) * FS + col]) =
          make_float2(sacc[ni][2], sacc[ni][3]);
    }
    __syncwarp();

#pragma unroll
    for (int ni = 0; ni < 8; ni++) {
      acc[ni][0] *= sc0; acc[ni][1] *= sc0;
      acc[ni][2] *= sc1; acc[ni][3] *= sc1;
    }
#pragma unroll
    for (int kb = 0; kb < 8; kb++) {
      uint32_t af[4];
      const int abase = (wm + gr) * FS + kb * 8 + gc;
      af[0] = __float_as_uint(Ss[abase]);
      af[1] = __float_as_uint(Ss[abase + 8 * FS]);
      af[2] = __float_as_uint(Ss[abase + 4]);
      af[3] = __float_as_uint(Ss[abase + 8 * FS + 4]);
      uint32_t bf[8][2];
#pragma unroll
      for (int ni = 0; ni < 8; ni++) {
        const int vbase = (kb * 8 + gc) * FS + ni * 8 + gr;
        bf[ni][0] = __float_as_uint(Vs[vbase]);
        bf[ni][1] = __float_as_uint(Vs[vbase + 4 * FS]);
      }
#pragma unroll
      for (int ni = 0; ni < 8; ni++) {
        asm volatile(
            "mma.sync.aligned.m16n8k8.row.col.f32.tf32.tf32.f32 "
            "{%0,%1,%2,%3}, {%4,%5,%6,%7}, {%8,%9}, {%0,%1,%2,%3};"
            : "+f"(acc[ni][0]), "+f"(acc[ni][1]),
              "+f"(acc[ni][2]), "+f"(acc[ni][3])
            : "r"(af[0]), "r"(af[1]), "r"(af[2]), "r"(af[3]),
              "r"(bf[ni][0]), "r"(bf[ni][1]));
      }
    }
    __syncthreads();
  }

  {
    const float inv0 = 1.f / lrun0;
    const float inv1 = 1.f / lrun1;
#pragma unroll
    for (int ni = 0; ni < 8; ni++) {
      const int col = ni * 8 + (gc << 1);
      Ss[(wm + gr) * FS + col]         = acc[ni][0] * inv0;
      Ss[(wm + gr) * FS + col + 1]     = acc[ni][1] * inv0;
      Ss[(wm + 8 + gr) * FS + col]     = acc[ni][2] * inv1;
      Ss[(wm + 8 + gr) * FS + col + 1] = acc[ni][3] * inv1;
    }
  }
  __syncthreads();
  {
    const int bc = mat >> 4;
    const int h  = mat & 15;
    const int rb = (bc * SEG_PAD + q0) >> 7;
    for (int ii = tid; ii < 2048; ii += 256) {
      const int l2   = ii & 31;
      const int half = (ii >> 5) & 1;
      const int ktl  = (ii >> 6) & 3;
      const int gg   = (ii >> 8) & 7;
      const int rl = gg * 16 + (l2 >> 2);
      const int cl = ktl * 16 + half * 8 + (l2 & 3);
      float4 o;
      o.x = tf32_rna(Ss[rl * FS + cl]);
      o.y = tf32_rna(Ss[(rl + 8) * FS + cl]);
      o.z = tf32_rna(Ss[rl * FS + cl + 4]);
      o.w = tf32_rna(Ss[(rl + 8) * FS + cl + 4]);
      const int kt = h * 4 + ktl;
      const size_t off = ((size_t)(rb * 64 + kt)) * 2048 +
                         (((gg << 1) + half) << 7) + (l2 << 2);
      *reinterpret_cast<float4*>(Outp + off) = o;
    }
  }
}

// ---------------------------------------------------------------------------
// build emb (reads padded proj)
// ---------------------------------------------------------------------------
__global__ void build_emb_kernel(const float* __restrict__ proj,
                                 float* __restrict__ emb) {
  const int idx = blockIdx.x * blockDim.x + threadIdx.x;
  if (idx >= SEQ_SSM * 256) return;
  const int i  = idx >> 8;
  const int d4 = (idx & 255) << 2;
  float4 o;
  if (i < SEQ_TXT) {
    const int c = i / TXT_LEN;
    const int t = i - c * TXT_LEN;
    o = *reinterpret_cast<const float4*>(proj + ((size_t)(c * SEG_PAD + t)) * D_MODEL + d4);
  } else {
    const int p = i - SEQ_TXT;
    float4 acc = make_float4(0.f, 0.f, 0.f, 0.f);
    int cnt = 0;
#pragma unroll
    for (int c = 0; c < 4; c++) {
      const int j = p - c * 768;
      if (j >= 0 && j < CHUNK_VID) {
        const float4 v4 = *reinterpret_cast<const float4*>(
            proj + ((size_t)(c * SEG_PAD + TXT_LEN + j)) * D_MODEL + d4);
        acc.x += v4.x; acc.y += v4.y; acc.z += v4.z; acc.w += v4.w;
        cnt++;
      }
    }
    const float inv = 1.f / (float)cnt;
    o.x = acc.x * inv; o.y = acc.y * inv; o.z = acc.z * inv; o.w = acc.w * inv;
  }
  *reinterpret_cast<float4*>(emb + (size_t)i * D_MODEL + d4) = o;
}

// ---------------------------------------------------------------------------
// Parallel SSM scan
// ---------------------------------------------------------------------------
__global__ void scan_pass1_kernel(const float* __restrict__ u,
                                  const float* __restrict__ gate,
                                  float* __restrict__ hloc,
                                  float* __restrict__ carry) {
  const int d = blockIdx.x * 256 + threadIdx.x;
  const int c = blockIdx.y;
  const float a = 1.f / (1.f + expf(-gate[d]));
  const int t0 = c * 128;
  const int t1 = (t0 + 128 < SEQ_SSM) ? (t0 + 128) : SEQ_SSM;
  float hv = 0.f;
  for (int t = t0; t < t1; t++) {
    hv = fmaf(a, hv, u[(size_t)t * D_MODEL + d]);
    hloc[(size_t)t * D_MODEL + d] = hv;
  }
  carry[c * 1024 + d] = hv;
}

__global__ void scan_pass2_kernel(const float* __restrict__ gate,
                                  float* __restrict__ carry) {
  const int d = blockIdx.x * 256 + threadIdx.x;
  const float a = 1.f / (1.f + expf(-gate[d]));
  const float a128 = __powf(a, 128.f);
  float s = 0.f;
  for (int c = 0; c < NCHUNK; c++) {
    const float cv = carry[c * 1024 + d];
    carry[c * 1024 + d] = s;
    s = a128 * s + cv;
  }
}

__global__ void scan_pass3_perm4(const float* __restrict__ hloc,
                                 const float* __restrict__ gate,
                                 const float* __restrict__ carry,
                                 float* __restrict__ hp) {
  const int idx = blockIdx.x * 256 + threadIdx.x;
  const APermIdx ix = aperm_decode(idx);
  const int chunk = ix.r0 >> 7;
  const int t0 = chunk << 7;
  const float a0 = 1.f / (1.f + expf(-gate[ix.c0]));
  const float a1 = 1.f / (1.f + expf(-gate[ix.c0 + 4]));
  const float cin0 = carry[chunk * 1024 + ix.c0];
  const float cin1 = carry[chunk * 1024 + ix.c0 + 4];
  const float e = (float)(ix.r0 - t0 + 1);
  const float p0  = __powf(a0, e);
  const float p1  = __powf(a1, e);
  const float p0b = p0 * __powf(a0, 8.f);
  const float p1b = p1 * __powf(a1, 8.f);
  auto ld = [&](int r, int c) -> float {
    return (r < SEQ_SSM) ? hloc[(size_t)r * D_MODEL + c] : 0.f;
  };
  float4 o;
  o.x = (ix.r0     < SEQ_SSM) ? tf32_rna(ld(ix.r0,     ix.c0)     + p0  * cin0) : 0.f;
  o.y = (ix.r0 + 8 < SEQ_SSM) ? tf32_rna(ld(ix.r0 + 8, ix.c0)     + p0b * cin0) : 0.f;
  o.z = (ix.r0     < SEQ_SSM) ? tf32_rna(ld(ix.r0,     ix.c0 + 4) + p1  * cin1) : 0.f;
  o.w = (ix.r0 + 8 < SEQ_SSM) ? tf32_rna(ld(ix.r0 + 8, ix.c0 + 4) + p1b * cin1) : 0.f;
  *reinterpret_cast<float4*>(hp + ix.off) = o;
}

// ---------------------------------------------------------------------------
// Launch
// ---------------------------------------------------------------------------
static float* sym_addr(const void* symbol) {
  void* p = nullptr;
  cudaGetSymbolAddress(&p, symbol);
  return (float*)p;
}

extern "C" void kernel_launch(void* const* d_in, const int* in_sizes, int n_in,
                              void* d_out, int out_size) {
  (void)in_sizes; (void)n_in; (void)out_size;
  const float* vid   = (const float*)d_in[0];
  const float* txt   = (const float*)d_in[1];
  const float* Wq    = (const float*)d_in[2];
  const float* bq    = (const float*)d_in[3];
  const float* Wk    = (const float*)d_in[4];
  const float* bk    = (const float*)d_in[5];
  const float* Wv    = (const float*)d_in[6];
  const float* bv    = (const float*)d_in[7];
  const float* Wo    = (const float*)d_in[8];
  const float* bo    = (const float*)d_in[9];
  const float* qn_w  = (const float*)d_in[10];
  const float* qn_b  = (const float*)d_in[11];
  const float* kn_w  = (const float*)d_in[12];
  const float* kn_b  = (const float*)d_in[13];
  const float* Win   = (const float*)d_in[14];
  const float* Wout  = (const float*)d_in[15];
  const float* gate  = (const float*)d_in[16];
  const float* fg_t  = (const float*)d_in[17];
  const float* fg_v  = (const float*)d_in[18];
  const float* bg_t  = (const float*)d_in[19];
  const float* bg_v  = (const float*)d_in[20];
  float* out = (float*)d_out;

  float* curp  = sym_addr(g_curp);
  float* qkv   = sym_addr(g_qkv);
  float* qt    = sym_addr(g_qt);
  float* kt    = sym_addr(g_kt);
  float* vt    = sym_addr(g_vt);
  float* attnp = sym_addr(g_attnp);
  float* proj  = sym_addr(g_proj);
  float* emb   = sym_addr(g_emb);
  float* embp  = sym_addr(g_embp);
  float* u     = sym_addr(g_u);
  float* hloc  = sym_addr(g_hloc);
  float* hp    = sym_addr(g_hp);
  float* emb2  = sym_addr(g_emb2);
  float* revp  = sym_addr(g_revp);
  float* carry = sym_addr(g_carry);
  float* wqkv  = sym_addr(g_wqkv);
  float* bqkv  = sym_addr(g_bqkv);
  float* wo_p  = sym_addr(g_wo);
  float* win_p  = sym_addr(g_win);
  float* wout_p = sym_addr(g_wout);
  float* tg     = sym_addr(g_tg);

  cudaFuncSetAttribute(flash_tf32_kernel, cudaFuncAttributeMaxDynamicSharedMemorySize, FA_SMEM);
  cudaFuncSetAttribute(tf32_gemm_perm, cudaFuncAttributeMaxDynamicSharedMemorySize, GEMM_SMEM);

  pack_qkv_perm_kernel<<<dim3(12, 1024), 256>>>(Wq, Wk, Wv, wqkv);
  pack_bias_kernel<<<4, 256>>>(bq, bk, bv, bqkv);
  pack3_b_perm_kernel<<<dim3(12, 1024), 256>>>(Wo, Win, Wout, wo_p, win_p, wout_p);
  tanh_prep_kernel<<<4, 256>>>(fg_t, fg_v, bg_t, bg_v, tg);

  gather_cur_perm4<<<5120, 256>>>(vid, txt, curp);
  tf32_gemm_perm<<<dim3(24, 40), 256, GEMM_SMEM>>>(
      curp, wqkv, bqkv, qkv, M_ATTN, 3072, nullptr, nullptr, nullptr, 0);
  qkv_prep_kernel<<<(M_ATTN * NHEAD) / 128, 128>>>(qkv, qn_w, qn_b, kn_w, kn_b,
                                                   qt, kt, vt);
  flash_tf32_kernel<<<dim3(10, 64), 256, FA_SMEM>>>(qt, kt, vt, attnp);
  tf32_gemm_perm<<<dim3(8, 40), 256, GEMM_SMEM>>>(
      attnp, wo_p, bo, proj, M_PAD, 1024, nullptr, nullptr, nullptr, 0);
  build_emb_kernel<<<SEQ_SSM, 256>>>(proj, emb);
  rowmajor_to_aperm4<<<4352, 256>>>(emb, embp);

  // forward SSM
  tf32_gemm_perm<<<dim3(8, 34), 256, GEMM_SMEM>>>(
      embp, win_p, nullptr, u, SEQ_SSM, 1024, nullptr, nullptr, nullptr, 0);
  scan_pass1_kernel<<<dim3(4, NCHUNK), 256>>>(u, gate, hloc, carry);
  scan_pass2_kernel<<<4, 256>>>(gate, carry);
  scan_pass3_perm4<<<4352, 256>>>(hloc, gate, carry, hp);
  tf32_gemm_perm<<<dim3(8, 34), 256, GEMM_SMEM>>>(
      hp, wout_p, nullptr, emb2, SEQ_SSM, 1024, emb, tg, tg + 1024, 1);

  // backward SSM
  rev_perm4<<<4352, 256>>>(emb2, revp);
  tf32_gemm_perm<<<dim3(8, 34), 256, GEMM_SMEM>>>(
      revp, win_p, nullptr, u, SEQ_SSM, 1024, nullptr, nullptr, nullptr, 0);
  scan_pass1_kernel<<<dim3(4, NCHUNK), 256>>>(u, gate, hloc, carry);
  scan_pass2_kernel<<<4, 256>>>(gate, carry);
  scan_pass3_perm4<<<4352, 256>>>(hloc, gate, carry, hp);
  tf32_gemm_perm<<<dim3(8, 34), 256, GEMM_SMEM>>>(
      hp, wout_p, nullptr, out, SEQ_SSM, 1024, emb2, tg + 2048, tg + 3072, 2);
}

// round 12
// speedup vs baseline: 1.8467x; 1.0301x over previous
#include <cuda_runtime.h>
#include <cuda_bf16.h>
#include <cstdint>

// ---------------------------------------------------------------------------
// Problem constants
// ---------------------------------------------------------------------------
#define D_MODEL 1024
#define NHEAD   16
#define HDIM    64
#define TXT_LEN 226
#define CHUNKS  4
#define SEQ_TXT 904
#define VID_LEN 3328
#define CHUNK_VID 1024
#define T_ATTN  1250
#define SEG_PAD 1280
#define M_ATTN  5000
#define M_PAD   5120
#define SEQ_SSM 4232
#define ATTN_SCALE 0.125f
#define NCHUNK  34

// ---------------------------------------------------------------------------
// Scratch (static __device__)
// ---------------------------------------------------------------------------
__device__ float g_curp [5242880];
__device__ float g_qt   [5120000];
__device__ float g_kt   [5120000];
__device__ float g_vt   [5120000];
__device__ float g_attnp[5242880];
__device__ float g_proj [5242880];
__device__ float g_emb  [4333568];
__device__ float g_embp [4456448];
__device__ float g_u    [4333568];
__device__ float g_hloc [4333568];
__device__ float g_hp   [4456448];
__device__ float g_emb2 [4333568];
__device__ float g_revp [4456448];
__device__ float g_carry[34816];
__device__ float g_wqkv[3145728];
__device__ float g_bqkv[3072];
__device__ float g_wo  [1048576];
__device__ float g_win [1048576];
__device__ float g_wout[1048576];
__device__ float g_tg  [4096];

__device__ __forceinline__ float tf32_rna(float x) {
  float r;
  asm("cvt.rna.tf32.f32 %0, %1;" : "=f"(r) : "f"(x));
  return r;
}

__device__ __forceinline__ size_t bperm_off(int k, int c) {
  const int nb = c >> 7, kt = k >> 4;
  const int n8 = (c >> 3) & 15;
  const int kb = (k >> 3) & 1;
  const int j  = (k >> 2) & 1;
  const int lane = ((c & 7) << 2) | (k & 3);
  return ((size_t)(nb * 64 + kt)) * 2048 + (((n8 << 1) + kb) << 6) +
         (lane << 1) + j;
}

struct APermIdx { int r0, c0; size_t off; };
__device__ __forceinline__ APermIdx aperm_decode(int idx) {
  const int lane = idx & 31;
  const int half = (idx >> 5) & 1;
  const int g    = (idx >> 6) & 7;
  const int kt   = (idx >> 9) & 63;
  const int rb   = idx >> 15;
  APermIdx o;
  o.r0  = rb * 128 + g * 16 + (lane >> 2);
  o.c0  = kt * 16 + half * 8 + (lane & 3);
  o.off = ((size_t)(rb * 64 + kt)) * 2048 + (((g << 1) + half) << 7) + (lane << 2);
  return o;
}

__device__ __forceinline__ void cp16(uint32_t s, const void* g) {
  asm volatile("cp.async.cg.shared.global [%0], [%1], 16;" :: "r"(s), "l"(g));
}

__device__ __forceinline__ int rev_map(int i) {
  if (i < SEQ_TXT) {
    const int c = i / TXT_LEN;
    return (3 - c) * TXT_LEN + (i - c * TXT_LEN);
  }
  return 5135 - i;
}

// shared rope helper (x is 64-float register array)
__device__ __forceinline__ void rope_apply(float* x, int t) {
  const int p = t - TXT_LEN;
  const float fpos = (float)(p >> 8);
  const int rem = p & 255;
  const float hpos = (float)(rem >> 4);
  const float wpos = (float)(rem & 15);
#pragma unroll
  for (int i = 0; i < 8; i++) {
    const float ang = fpos * __powf(10000.f, -(float)i * 0.125f);
    float sn, cs; sincosf(ang, &sn, &cs);
    const float x1 = x[i], x2 = x[8 + i];
    x[i]     = x1 * cs - x2 * sn;
    x[8 + i] = x1 * sn + x2 * cs;
  }
#pragma unroll
  for (int i = 0; i < 12; i++) {
    const float ang = hpos * __powf(10000.f, -(float)i * (1.f / 12.f));
    float sn, cs; sincosf(ang, &sn, &cs);
    const float x1 = x[16 + i], x2 = x[28 + i];
    x[16 + i] = x1 * cs - x2 * sn;
    x[28 + i] = x1 * sn + x2 * cs;
  }
#pragma unroll
  for (int i = 0; i < 12; i++) {
    const float ang = wpos * __powf(10000.f, -(float)i * (1.f / 12.f));
    float sn, cs; sincosf(ang, &sn, &cs);
    const float x1 = x[40 + i], x2 = x[52 + i];
    x[40 + i] = x1 * cs - x2 * sn;
    x[52 + i] = x1 * sn + x2 * cs;
  }
}

// ---------------------------------------------------------------------------
// Weight packing
// ---------------------------------------------------------------------------
__global__ void pack_qkv_perm_kernel(const float* __restrict__ Wq,
                                     const float* __restrict__ Wk,
                                     const float* __restrict__ Wv,
                                     float* __restrict__ dst) {
  const int c = blockIdx.x * 256 + threadIdx.x;
  const int k = blockIdx.y;
  const float* W = (c < 1024) ? Wq : (c < 2048) ? Wk : Wv;
  dst[bperm_off(k, c)] = tf32_rna(W[(size_t)k * 1024 + (c & 1023)]);
}

__global__ void pack_bias_kernel(const float* __restrict__ bq,
                                 const float* __restrict__ bk,
                                 const float* __restrict__ bv,
                                 float* __restrict__ bp) {
  const int i = blockIdx.x * 256 + threadIdx.x;
  if (i < 1024) { bp[i] = bq[i]; bp[1024 + i] = bk[i]; bp[2048 + i] = bv[i]; }
}

__global__ void pack3_b_perm_kernel(const float* __restrict__ W0,
                                    const float* __restrict__ W1,
                                    const float* __restrict__ W2,
                                    float* __restrict__ D0,
                                    float* __restrict__ D1,
                                    float* __restrict__ D2) {
  const int cx = blockIdx.x * 256 + threadIdx.x;
  const int k  = blockIdx.y;
  const int c  = cx & 1023;
  const float* W; float* D;
  if (cx < 1024)      { W = W0; D = D0; }
  else if (cx < 2048) { W = W1; D = D1; }
  else                { W = W2; D = D2; }
  D[bperm_off(k, c)] = tf32_rna(W[(size_t)k * 1024 + c]);
}

__global__ void tanh_prep_kernel(const float* __restrict__ fg_t,
                                 const float* __restrict__ fg_v,
                                 const float* __restrict__ bg_t,
                                 const float* __restrict__ bg_v,
                                 float* __restrict__ tg) {
  const int i = blockIdx.x * 256 + threadIdx.x;
  if (i < 1024) {
    tg[i]        = tanhf(fg_t[i]);
    tg[1024 + i] = tanhf(fg_v[i]);
    tg[2048 + i] = tanhf(bg_t[i]);
    tg[3072 + i] = tanhf(bg_v[i]);
  }
}

// ---------------------------------------------------------------------------
// Common GEMM mainloop macro pieces (GBK=32, 3-stage cp.async, dyn smem)
// ---------------------------------------------------------------------------
#define GEMM_SMEM (6 * 4096 * 4)

#define GEMM_MAINLOOP(Abase, Bbase)                                            \
  float acc[2][8][4];                                                          \
  _Pragma("unroll")                                                            \
  for (int mi = 0; mi < 2; mi++)                                               \
    _Pragma("unroll")                                                          \
    for (int ni = 0; ni < 8; ni++)                                             \
      _Pragma("unroll")                                                        \
      for (int j = 0; j < 4; j++) acc[mi][ni][j] = 0.f;                        \
  auto issue = [&](int kt2, int s) {                                           \
    const float* ga = (Abase) + (size_t)kt2 * 4096;                            \
    const float* gb = (Bbase) + (size_t)kt2 * 4096;                            \
    const uint32_t da = sA + s * 16384 + tid * 16;                             \
    const uint32_t db = sB + s * 16384 + tid * 16;                             \
    cp16(da,         ga + tid * 4);                                            \
    cp16(da + 4096,  ga + 1024 + tid * 4);                                     \
    cp16(da + 8192,  ga + 2048 + tid * 4);                                     \
    cp16(da + 12288, ga + 3072 + tid * 4);                                     \
    cp16(db,         gb + tid * 4);                                            \
    cp16(db + 4096,  gb + 1024 + tid * 4);                                     \
    cp16(db + 8192,  gb + 2048 + tid * 4);                                     \
    cp16(db + 12288, gb + 3072 + tid * 4);                                     \
    asm volatile("cp.async.commit_group;");                                    \
  };                                                                           \
  issue(0, 0);                                                                 \
  issue(1, 1);                                                                 \
  int s = 0;                                                                   \
  for (int t = 0; t < 32; t++) {                                               \
    if (t < 30) { asm volatile("cp.async.wait_group 1;"); }                    \
    else        { asm volatile("cp.async.wait_group 0;"); }                    \
    __syncthreads();                                                           \
    if (t + 2 < 32) issue(t + 2, (t + 2) % 3);                                 \
    const float4* a4 = reinterpret_cast<const float4*>(As + s * 4096);         \
    const float2* b2 = reinterpret_cast<const float2*>(Bs + s * 4096);         \
    _Pragma("unroll")                                                          \
    for (int kb = 0; kb < 4; kb++) {                                           \
      const int half = kb >> 1;                                                \
      const int kbl  = kb & 1;                                                 \
      float4 af[2];                                                            \
      float2 bf[8];                                                            \
      _Pragma("unroll")                                                        \
      for (int mi = 0; mi < 2; mi++)                                           \
        af[mi] = a4[half * 512 + ((((ws << 1) + mi) * 2 + kbl) << 5) + lane];  \
      _Pragma("unroll")                                                        \
      for (int ni = 0; ni < 8; ni++)                                           \
        bf[ni] = b2[half * 1024 + ((((wn >> 3) + ni) * 2 + kbl) << 5) + lane]; \
      _Pragma("unroll")                                                        \
      for (int mi = 0; mi < 2; mi++) {                                         \
        const uint32_t a0 = __float_as_uint(af[mi].x);                         \
        const uint32_t a1 = __float_as_uint(af[mi].y);                         \
        const uint32_t a2 = __float_as_uint(af[mi].z);                         \
        const uint32_t a3 = __float_as_uint(af[mi].w);                         \
        _Pragma("unroll")                                                      \
        for (int ni = 0; ni < 8; ni++) {                                       \
          asm volatile(                                                        \
              "mma.sync.aligned.m16n8k8.row.col.f32.tf32.tf32.f32 "            \
              "{%0,%1,%2,%3}, {%4,%5,%6,%7}, {%8,%9}, {%0,%1,%2,%3};"          \
              : "+f"(acc[mi][ni][0]), "+f"(acc[mi][ni][1]),                    \
                "+f"(acc[mi][ni][2]), "+f"(acc[mi][ni][3])                     \
              : "r"(a0), "r"(a1), "r"(a2), "r"(a3),                            \
                "r"(__float_as_uint(bf[ni].x)),                                \
                "r"(__float_as_uint(bf[ni].y)));                               \
        }                                                                      \
      }                                                                        \
    }                                                                          \
    s = (s + 1) % 3;                                                           \
  }

// ---------------------------------------------------------------------------
// Generic GEMM (modes 0/1/2)
// ---------------------------------------------------------------------------
__global__ void __launch_bounds__(256) tf32_gemm_perm(
    const float* __restrict__ Ap, const float* __restrict__ Bp,
    const float* __restrict__ bias, float* __restrict__ C,
    int M, int N,
    const float* __restrict__ e_base, const float* __restrict__ tga,
    const float* __restrict__ tgb, int mode) {
  extern __shared__ float smg[];
  float* As = smg;
  float* Bs = smg + 12288;
  const int tid = threadIdx.x;
  const int warp = tid >> 5, lane = tid & 31;
  const int ws = warp & 3;
  const int wn = (warp >> 2) << 6;
  const int grp = lane >> 2, gcc = lane & 3;
  const int rb = blockIdx.y, nb = blockIdx.x;
  const uint32_t sA = (uint32_t)__cvta_generic_to_shared(As);
  const uint32_t sB = (uint32_t)__cvta_generic_to_shared(Bs);

  GEMM_MAINLOOP(Ap + (size_t)rb * 64 * 2048, Bp + (size_t)nb * 64 * 2048)

  const int row0 = rb * 128 + ws * 32;
  const int col0 = nb * 128 + wn;

  if (mode == 0) {
#pragma unroll
    for (int mi = 0; mi < 2; mi++) {
      const int row = row0 + mi * 16 + grp;
#pragma unroll
      for (int ni = 0; ni < 8; ni++) {
        const int col = col0 + ni * 8 + (gcc << 1);
        float b0 = 0.f, b1 = 0.f;
        if (bias) { b0 = __ldg(bias + col); b1 = __ldg(bias + col + 1); }
        if (row < M) {
          float2 o; o.x = acc[mi][ni][0] + b0; o.y = acc[mi][ni][1] + b1;
          *reinterpret_cast<float2*>(C + (size_t)row * N + col) = o;
        }
        if (row + 8 < M) {
          float2 o; o.x = acc[mi][ni][2] + b0; o.y = acc[mi][ni][3] + b1;
          *reinterpret_cast<float2*>(C + (size_t)(row + 8) * N + col) = o;
        }
      }
    }
  } else if (mode == 1) {
#pragma unroll
    for (int mi = 0; mi < 2; mi++) {
#pragma unroll
      for (int rr = 0; rr < 2; rr++) {
        const int row = row0 + mi * 16 + grp + rr * 8;
        if (row >= M) continue;
        const float* tg = (row < SEQ_TXT) ? tga : tgb;
#pragma unroll
        for (int ni = 0; ni < 8; ni++) {
          const int col = col0 + ni * 8 + (gcc << 1);
          const float2 e = *reinterpret_cast<const float2*>(e_base + (size_t)row * N + col);
          const float2 t = *reinterpret_cast<const float2*>(tg + col);
          float2 o;
          o.x = e.x + t.x * acc[mi][ni][rr * 2 + 0];
          o.y = e.y + t.y * acc[mi][ni][rr * 2 + 1];
          *reinterpret_cast<float2*>(C + (size_t)row * N + col) = o;
        }
      }
    }
  } else {
#pragma unroll
    for (int mi = 0; mi < 2; mi++) {
#pragma unroll
      for (int rr = 0; rr < 2; rr++) {
        const int row = row0 + mi * 16 + grp + rr * 8;
        if (row >= M) continue;
        const int i = rev_map(row);
        const int dst = (i < SEQ_TXT) ? (VID_LEN + i) : (i - SEQ_TXT);
        const float* tg = (i < SEQ_TXT) ? tga : tgb;
#pragma unroll
        for (int ni = 0; ni < 8; ni++) {
          const int col = col0 + ni * 8 + (gcc << 1);
          const float2 e = *reinterpret_cast<const float2*>(e_base + (size_t)i * N + col);
          const float2 t = *reinterpret_cast<const float2*>(tg + col);
          float2 o;
          o.x = e.x + t.x * acc[mi][ni][rr * 2 + 0];
          o.y = e.y + t.y * acc[mi][ni][rr * 2 + 1];
          *reinterpret_cast<float2*>(C + (size_t)dst * N + col) = o;
        }
      }
    }
  }
}

// ---------------------------------------------------------------------------
// QKV GEMM with fused layernorm+RoPE+transpose epilogue.
// nb<8: Q (qn norm + rope) ; nb<16: K (kn norm + rope) ; else V (round only)
// ---------------------------------------------------------------------------
#define TSTRIDE 132
__global__ void __launch_bounds__(256) tf32_gemm_qkv(
    const float* __restrict__ Ap, const float* __restrict__ Bp,
    const float* __restrict__ bias,
    const float* __restrict__ qn_w, const float* __restrict__ qn_b,
    const float* __restrict__ kn_w, const float* __restrict__ kn_b,
    float* __restrict__ qt, float* __restrict__ kt, float* __restrict__ vt) {
  extern __shared__ float smg[];
  float* As = smg;
  float* Bs = smg + 12288;
  const int tid = threadIdx.x;
  const int warp = tid >> 5, lane = tid & 31;
  const int ws = warp & 3;
  const int wn = (warp >> 2) << 6;
  const int grp = lane >> 2, gcc = lane & 3;
  const int rb = blockIdx.y, nb = blockIdx.x;
  const uint32_t sA = (uint32_t)__cvta_generic_to_shared(As);
  const uint32_t sB = (uint32_t)__cvta_generic_to_shared(Bs);

  GEMM_MAINLOOP(Ap + (size_t)rb * 64 * 2048, Bp + (size_t)nb * 64 * 2048)

  // stage bias-added tile into smem (pipeline stages are drained)
  __syncthreads();
  float* Ts = smg;   // 128 x TSTRIDE = 67.6 KB
#pragma unroll
  for (int mi = 0; mi < 2; mi++) {
#pragma unroll
    for (int rr = 0; rr < 2; rr++) {
      const int trow = ws * 32 + mi * 16 + grp + rr * 8;
#pragma unroll
      for (int ni = 0; ni < 8; ni++) {
        const int tcol = wn + ni * 8 + (gcc << 1);
        const float b0 = __ldg(bias + nb * 128 + tcol);
        const float b1 = __ldg(bias + nb * 128 + tcol + 1);
        Ts[trow * TSTRIDE + tcol]     = acc[mi][ni][rr * 2 + 0] + b0;
        Ts[trow * TSTRIDE + tcol + 1] = acc[mi][ni][rr * 2 + 1] + b1;
      }
    }
  }
  __syncthreads();

  // per-(row, head) norm/rope/write
  const int tr = tid >> 1;
  const int hl = tid & 1;
  const int row = rb * 128 + tr;
  if (row >= M_ATTN) return;
  const int bc = row / T_ATTN;
  const int t  = row - bc * T_ATTN;
  const int h  = ((nb & 7) << 1) + hl;
  float x[64];
#pragma unroll
  for (int d = 0; d < 64; d += 4) {
    const float4 v4 = *reinterpret_cast<const float4*>(&Ts[tr * TSTRIDE + hl * 64 + d]);
    x[d] = v4.x; x[d+1] = v4.y; x[d+2] = v4.z; x[d+3] = v4.w;
  }
  float* outb;
  if (nb < 16) {
    const float* nw = (nb < 8) ? qn_w : kn_w;
    const float* nbi = (nb < 8) ? qn_b : kn_b;
    float sm = 0.f, ss = 0.f;
#pragma unroll
    for (int d = 0; d < 64; d++) { sm += x[d]; ss += x[d] * x[d]; }
    const float mu  = sm * (1.f / 64.f);
    const float var = ss * (1.f / 64.f) - mu * mu;
    const float rr  = rsqrtf(var + 1e-6f);
#pragma unroll
    for (int d = 0; d < 64; d++) x[d] = (x[d] - mu) * rr * nw[d] + nbi[d];
    if (t >= TXT_LEN) rope_apply(x, t);
    outb = (nb < 8) ? qt : kt;
  } else {
    outb = vt;
  }
  const size_t dst = ((size_t)(bc * NHEAD + h) * T_ATTN + t) * HDIM;
#pragma unroll
  for (int d = 0; d < 64; d += 4)
    *reinterpret_cast<float4*>(outb + dst + d) =
        make_float4(tf32_rna(x[d]), tf32_rna(x[d+1]), tf32_rna(x[d+2]), tf32_rna(x[d+3]));
}

// ---------------------------------------------------------------------------
// Coalesced A-perm writers
// ---------------------------------------------------------------------------
__global__ void gather_cur_perm4(const float* __restrict__ vid,
                                 const float* __restrict__ txt,
                                 float* __restrict__ curp) {
  const int idx = blockIdx.x * 256 + threadIdx.x;
  const APermIdx ix = aperm_decode(idx);
  auto ld = [&](int r, int c) -> float {
    if (r >= M_ATTN) return 0.f;
    const int bc = r / T_ATTN;
    const int t  = r - bc * T_ATTN;
    return (t < TXT_LEN)
        ? txt[(size_t)(bc * TXT_LEN + t) * D_MODEL + c]
        : vid[(size_t)(bc * 768 + (t - TXT_LEN)) * D_MODEL + c];
  };
  float4 o;
  o.x = tf32_rna(ld(ix.r0,     ix.c0));
  o.y = tf32_rna(ld(ix.r0 + 8, ix.c0));
  o.z = tf32_rna(ld(ix.r0,     ix.c0 + 4));
  o.w = tf32_rna(ld(ix.r0 + 8, ix.c0 + 4));
  *reinterpret_cast<float4*>(curp + ix.off) = o;
}

__global__ void rowmajor_to_aperm4(const float* __restrict__ src,
                                   float* __restrict__ dst) {
  const int idx = blockIdx.x * 256 + threadIdx.x;
  const APermIdx ix = aperm_decode(idx);
  auto ld = [&](int r, int c) -> float {
    return (r < SEQ_SSM) ? src[(size_t)r * D_MODEL + c] : 0.f;
  };
  float4 o;
  o.x = tf32_rna(ld(ix.r0,     ix.c0));
  o.y = tf32_rna(ld(ix.r0 + 8, ix.c0));
  o.z = tf32_rna(ld(ix.r0,     ix.c0 + 4));
  o.w = tf32_rna(ld(ix.r0 + 8, ix.c0 + 4));
  *reinterpret_cast<float4*>(dst + ix.off) = o;
}

__global__ void rev_perm4(const float* __restrict__ src, float* __restrict__ dst) {
  const int idx = blockIdx.x * 256 + threadIdx.x;
  const APermIdx ix = aperm_decode(idx);
  auto ld = [&](int r, int c) -> float {
    return (r < SEQ_SSM) ? src[(size_t)rev_map(r) * D_MODEL + c] : 0.f;
  };
  float4 o;
  o.x = tf32_rna(ld(ix.r0,     ix.c0));
  o.y = tf32_rna(ld(ix.r0 + 8, ix.c0));
  o.z = tf32_rna(ld(ix.r0,     ix.c0 + 4));
  o.w = tf32_rna(ld(ix.r0 + 8, ix.c0 + 4));
  *reinterpret_cast<float4*>(dst + ix.off) = o;
}

// ---------------------------------------------------------------------------
// Flash attention tf32, 128-row tiles, in-warp softmax (R10 — known good).
// ---------------------------------------------------------------------------
#define FS 68
#define FA_SMEM ((384 * FS) * 4)

__global__ void __launch_bounds__(256) flash_tf32_kernel(
    const float* __restrict__ Qt, const float* __restrict__ Kt,
    const float* __restrict__ Vt, float* __restrict__ Outp) {
  extern __shared__ float sm[];
  float* Qs = sm;
  float* Ks = sm + 128 * FS;
  float* Vs = sm + 192 * FS;
  float* Ss = sm + 256 * FS;

  const int mat = blockIdx.y;
  const int q0  = blockIdx.x * 128;
  const int tid = threadIdx.x;
  const int warp = tid >> 5;
  const int lane = tid & 31;
  const int gr = lane >> 2;
  const int gc = lane & 3;
  const int wm = warp * 16;

  const float* Qb = Qt + (size_t)mat * T_ATTN * HDIM;
  const float* Kb = Kt + (size_t)mat * T_ATTN * HDIM;
  const float* Vb = Vt + (size_t)mat * T_ATTN * HDIM;

  {
    const int r  = tid >> 1;
    const int d0 = (tid & 1) << 5;
    const int gq = q0 + r;
#pragma unroll
    for (int i = 0; i < 32; i += 4) {
      float4 v4 = make_float4(0.f, 0.f, 0.f, 0.f);
      if (gq < T_ATTN)
        v4 = *reinterpret_cast<const float4*>(Qb + (size_t)gq * HDIM + d0 + i);
      *reinterpret_cast<float4*>(&Qs[r * FS + d0 + i]) = v4;
    }
  }
  __syncthreads();

  uint32_t qf[8][4];
#pragma unroll
  for (int kb = 0; kb < 8; kb++) {
    const int base = (wm + gr) * FS + kb * 8 + gc;
    qf[kb][0] = __float_as_uint(Qs[base]);
    qf[kb][1] = __float_as_uint(Qs[base + 8 * FS]);
    qf[kb][2] = __float_as_uint(Qs[base + 4]);
    qf[kb][3] = __float_as_uint(Qs[base + 8 * FS + 4]);
  }
  __syncthreads();

  float acc[8][4];
#pragma unroll
  for (int ni = 0; ni < 8; ni++)
#pragma unroll
    for (int j = 0; j < 4; j++) acc[ni][j] = 0.f;

  float mrun0 = -1e30f, mrun1 = -1e30f;
  float lrun0 = 0.f, lrun1 = 0.f;

  for (int k0 = 0; k0 < T_ATTN; k0 += 64) {
    {
      const int r  = tid >> 2;
      const int d0 = (tid & 3) << 4;
      const int gk = k0 + r;
#pragma unroll
      for (int i = 0; i < 16; i += 4) {
        float4 kv = make_float4(0.f, 0.f, 0.f, 0.f);
        float4 vv = make_float4(0.f, 0.f, 0.f, 0.f);
        if (gk < T_ATTN) {
          kv = *reinterpret_cast<const float4*>(Kb + (size_t)gk * HDIM + d0 + i);
          vv = *reinterpret_cast<const float4*>(Vb + (size_t)gk * HDIM + d0 + i);
        }
        *reinterpret_cast<float4*>(&Ks[r * FS + d0 + i]) = kv;
        *reinterpret_cast<float4*>(&Vs[r * FS + d0 + i]) = vv;
      }
    }
    __syncthreads();

    float sacc[8][4];
#pragma unroll
    for (int ni = 0; ni < 8; ni++)
#pragma unroll
      for (int j = 0; j < 4; j++) sacc[ni][j] = 0.f;
#pragma unroll
    for (int kb = 0; kb < 8; kb++) {
      uint32_t bf[8][2];
#pragma unroll
      for (int ni = 0; ni < 8; ni++) {
        const int kbase = (ni * 8 + gr) * FS + kb * 8 + gc;
        bf[ni][0] = __float_as_uint(Ks[kbase]);
        bf[ni][1] = __float_as_uint(Ks[kbase + 4]);
      }
#pragma unroll
      for (int ni = 0; ni < 8; ni++) {
        asm volatile(
            "mma.sync.aligned.m16n8k8.row.col.f32.tf32.tf32.f32 "
            "{%0,%1,%2,%3}, {%4,%5,%6,%7}, {%8,%9}, {%0,%1,%2,%3};"
            : "+f"(sacc[ni][0]), "+f"(sacc[ni][1]),
              "+f"(sacc[ni][2]), "+f"(sacc[ni][3])
            : "r"(qf[kb][0]), "r"(qf[kb][1]), "r"(qf[kb][2]), "r"(qf[kb][3]),
              "r"(bf[ni][0]), "r"(bf[ni][1]));
      }
    }

    float m0 = -1e30f, m1 = -1e30f;
#pragma unroll
    for (int ni = 0; ni < 8; ni++) {
      const int gk = k0 + ni * 8 + (gc << 1);
      sacc[ni][0] = (gk     < T_ATTN) ? sacc[ni][0] * ATTN_SCALE : -1e30f;
      sacc[ni][1] = (gk + 1 < T_ATTN) ? sacc[ni][1] * ATTN_SCALE : -1e30f;
      sacc[ni][2] = (gk     < T_ATTN) ? sacc[ni][2] * ATTN_SCALE : -1e30f;
      sacc[ni][3] = (gk + 1 < T_ATTN) ? sacc[ni][3] * ATTN_SCALE : -1e30f;
      m0 = fmaxf(m0, fmaxf(sacc[ni][0], sacc[ni][1]));
      m1 = fmaxf(m1, fmaxf(sacc[ni][2], sacc[ni][3]));
    }
    m0 = fmaxf(m0, __shfl_xor_sync(0xffffffffu, m0, 1));
    m0 = fmaxf(m0, __shfl_xor_sync(0xffffffffu, m0, 2));
    m1 = fmaxf(m1, __shfl_xor_sync(0xffffffffu, m1, 1));
    m1 = fmaxf(m1, __shfl_xor_sync(0xffffffffu, m1, 2));
    const float mn0 = fmaxf(mrun0, m0);
    const float mn1 = fmaxf(mrun1, m1);
    const float sc0 = __expf(mrun0 - mn0);
    const float sc1 = __expf(mrun1 - mn1);
    mrun0 = mn0; mrun1 = mn1;

    float s0 = 0.f, s1 = 0.f;
#pragma unroll
    for (int ni = 0; ni < 8; ni++) {
      sacc[ni][0] = tf32_rna(__expf(sacc[ni][0] - mn0));
      sacc[ni][1] = tf32_rna(__expf(sacc[ni][1] - mn0));
      sacc[ni][2] = tf32_rna(__expf(sacc[ni][2] - mn1));
      sacc[ni][3] = tf32_rna(__expf(sacc[ni][3] - mn1));
      s0 += sacc[ni][0] + sacc[ni][1];
      s1 += sacc[ni][2] + sacc[ni][3];
    }
    s0 += __shfl_xor_sync(0xffffffffu, s0, 1);
    s0 += __shfl_xor_sync(0xffffffffu, s0, 2);
    s1 += __shfl_xor_sync(0xffffffffu, s1, 1);
    s1 += __shfl_xor_sync(0xffffffffu, s1, 2);
    lrun0 = lrun0 * sc0 + s0;
    lrun1 = lrun1 * sc1 + s1;

#pragma unroll
    for (int ni = 0; ni < 8; ni++) {
      const int col = ni * 8 + (gc << 1);
      *reinterpret_cast<float2*>(&Ss[(wm + gr) * FS + col]) =
          make_float2(sacc[ni][0], sacc[ni][1]);
      *reinterpret_cast<float2*>(&Ss[(wm + 8 + gr) * FS + col]) =
          make_float2(sacc[ni][2], sacc[ni][3]);
    }
    __syncwarp();

#pragma unroll
    for (int ni = 0; ni < 8; ni++) {
      acc[ni][0] *= sc0; acc[ni][1] *= sc0;
      acc[ni][2] *= sc1; acc[ni][3] *= sc1;
    }
#pragma unroll
    for (int kb = 0; kb < 8; kb++) {
      uint32_t af[4];
      const int abase = (wm + gr) * FS + kb * 8 + gc;
      af[0] = __float_as_uint(Ss[abase]);
      af[1] = __float_as_uint(Ss[abase + 8 * FS]);
      af[2] = __float_as_uint(Ss[abase + 4]);
      af[3] = __float_as_uint(Ss[abase + 8 * FS + 4]);
      uint32_t bf[8][2];
#pragma unroll
      for (int ni = 0; ni < 8; ni++) {
        const int vbase = (kb * 8 + gc) * FS + ni * 8 + gr;
        bf[ni][0] = __float_as_uint(Vs[vbase]);
        bf[ni][1] = __float_as_uint(Vs[vbase + 4 * FS]);
      }
#pragma unroll
      for (int ni = 0; ni < 8; ni++) {
        asm volatile(
            "mma.sync.aligned.m16n8k8.row.col.f32.tf32.tf32.f32 "
            "{%0,%1,%2,%3}, {%4,%5,%6,%7}, {%8,%9}, {%0,%1,%2,%3};"
            : "+f"(acc[ni][0]), "+f"(acc[ni][1]),
              "+f"(acc[ni][2]), "+f"(acc[ni][3])
            : "r"(af[0]), "r"(af[1]), "r"(af[2]), "r"(af[3]),
              "r"(bf[ni][0]), "r"(bf[ni][1]));
      }
    }
    __syncthreads();
  }

  {
    const float inv0 = 1.f / lrun0;
    const float inv1 = 1.f / lrun1;
#pragma unroll
    for (int ni = 0; ni < 8; ni++) {
      const int col = ni * 8 + (gc << 1);
      Ss[(wm + gr) * FS + col]         = acc[ni][0] * inv0;
      Ss[(wm + gr) * FS + col + 1]     = acc[ni][1] * inv0;
      Ss[(wm + 8 + gr) * FS + col]     = acc[ni][2] * inv1;
      Ss[(wm + 8 + gr) * FS + col + 1] = acc[ni][3] * inv1;
    }
  }
  __syncthreads();
  {
    const int bc = mat >> 4;
    const int h  = mat & 15;
    const int rb = (bc * SEG_PAD + q0) >> 7;
    for (int ii = tid; ii < 2048; ii += 256) {
      const int l2   = ii & 31;
      const int half = (ii >> 5) & 1;
      const int ktl  = (ii >> 6) & 3;
      const int gg   = (ii >> 8) & 7;
      const int rl = gg * 16 + (l2 >> 2);
      const int cl = ktl * 16 + half * 8 + (l2 & 3);
      float4 o;
      o.x = tf32_rna(Ss[rl * FS + cl]);
      o.y = tf32_rna(Ss[(rl + 8) * FS + cl]);
      o.z = tf32_rna(Ss[rl * FS + cl + 4]);
      o.w = tf32_rna(Ss[(rl + 8) * FS + cl + 4]);
      const int kt = h * 4 + ktl;
      const size_t off = ((size_t)(rb * 64 + kt)) * 2048 +
                         (((gg << 1) + half) << 7) + (l2 << 2);
      *reinterpret_cast<float4*>(Outp + off) = o;
    }
  }
}

// ---------------------------------------------------------------------------
// build emb (reads padded proj)
// ---------------------------------------------------------------------------
__global__ void build_emb_kernel(const float* __restrict__ proj,
                                 float* __restrict__ emb) {
  const int idx = blockIdx.x * blockDim.x + threadIdx.x;
  if (idx >= SEQ_SSM * 256) return;
  const int i  = idx >> 8;
  const int d4 = (idx & 255) << 2;
  float4 o;
  if (i < SEQ_TXT) {
    const int c = i / TXT_LEN;
    const int t = i - c * TXT_LEN;
    o = *reinterpret_cast<const float4*>(proj + ((size_t)(c * SEG_PAD + t)) * D_MODEL + d4);
  } else {
    const int p = i - SEQ_TXT;
    float4 acc = make_float4(0.f, 0.f, 0.f, 0.f);
    int cnt = 0;
#pragma unroll
    for (int c = 0; c < 4; c++) {
      const int j = p - c * 768;
      if (j >= 0 && j < CHUNK_VID) {
        const float4 v4 = *reinterpret_cast<const float4*>(
            proj + ((size_t)(c * SEG_PAD + TXT_LEN + j)) * D_MODEL + d4);
        acc.x += v4.x; acc.y += v4.y; acc.z += v4.z; acc.w += v4.w;
        cnt++;
      }
    }
    const float inv = 1.f / (float)cnt;
    o.x = acc.x * inv; o.y = acc.y * inv; o.z = acc.z * inv; o.w = acc.w * inv;
  }
  *reinterpret_cast<float4*>(emb + (size_t)i * D_MODEL + d4) = o;
}

// ---------------------------------------------------------------------------
// Parallel SSM scan
// ---------------------------------------------------------------------------
__global__ void scan_pass1_kernel(const float* __restrict__ u,
                                  const float* __restrict__ gate,
                                  float* __restrict__ hloc,
                                  float* __restrict__ carry) {
  const int d = blockIdx.x * 256 + threadIdx.x;
  const int c = blockIdx.y;
  const float a = 1.f / (1.f + expf(-gate[d]));
  const int t0 = c * 128;
  const int t1 = (t0 + 128 < SEQ_SSM) ? (t0 + 128) : SEQ_SSM;
  float hv = 0.f;
  for (int t = t0; t < t1; t++) {
    hv = fmaf(a, hv, u[(size_t)t * D_MODEL + d]);
    hloc[(size_t)t * D_MODEL + d] = hv;
  }
  carry[c * 1024 + d] = hv;
}

__global__ void scan_pass2_kernel(const float* __restrict__ gate,
                                  float* __restrict__ carry) {
  const int d = blockIdx.x * 256 + threadIdx.x;
  const float a = 1.f / (1.f + expf(-gate[d]));
  const float a128 = __powf(a, 128.f);
  float s = 0.f;
  for (int c = 0; c < NCHUNK; c++) {
    const float cv = carry[c * 1024 + d];
    carry[c * 1024 + d] = s;
    s = a128 * s + cv;
  }
}

__global__ void scan_pass3_perm4(const float* __restrict__ hloc,
                                 const float* __restrict__ gate,
                                 const float* __restrict__ carry,
                                 float* __restrict__ hp) {
  const int idx = blockIdx.x * 256 + threadIdx.x;
  const APermIdx ix = aperm_decode(idx);
  const int chunk = ix.r0 >> 7;
  const int t0 = chunk << 7;
  const float a0 = 1.f / (1.f + expf(-gate[ix.c0]));
  const float a1 = 1.f / (1.f + expf(-gate[ix.c0 + 4]));
  const float cin0 = carry[chunk * 1024 + ix.c0];
  const float cin1 = carry[chunk * 1024 + ix.c0 + 4];
  const float e = (float)(ix.r0 - t0 + 1);
  const float p0  = __powf(a0, e);
  const float p1  = __powf(a1, e);
  const float p0b = p0 * __powf(a0, 8.f);
  const float p1b = p1 * __powf(a1, 8.f);
  auto ld = [&](int r, int c) -> float {
    return (r < SEQ_SSM) ? hloc[(size_t)r * D_MODEL + c] : 0.f;
  };
  float4 o;
  o.x = (ix.r0     < SEQ_SSM) ? tf32_rna(ld(ix.r0,     ix.c0)     + p0  * cin0) : 0.f;
  o.y = (ix.r0 + 8 < SEQ_SSM) ? tf32_rna(ld(ix.r0 + 8, ix.c0)     + p0b * cin0) : 0.f;
  o.z = (ix.r0     < SEQ_SSM) ? tf32_rna(ld(ix.r0,     ix.c0 + 4) + p1  * cin1) : 0.f;
  o.w = (ix.r0 + 8 < SEQ_SSM) ? tf32_rna(ld(ix.r0 + 8, ix.c0 + 4) + p1b * cin1) : 0.f;
  *reinterpret_cast<float4*>(hp + ix.off) = o;
}

// ---------------------------------------------------------------------------
// Launch
// ---------------------------------------------------------------------------
static float* sym_addr(const void* symbol) {
  void* p = nullptr;
  cudaGetSymbolAddress(&p, symbol);
  return (float*)p;
}

extern "C" void kernel_launch(void* const* d_in, const int* in_sizes, int n_in,
                              void* d_out, int out_size) {
  (void)in_sizes; (void)n_in; (void)out_size;
  const float* vid   = (const float*)d_in[0];
  const float* txt   = (const float*)d_in[1];
  const float* Wq    = (const float*)d_in[2];
  const float* bq    = (const float*)d_in[3];
  const float* Wk    = (const float*)d_in[4];
  const float* bk    = (const float*)d_in[5];
  const float* Wv    = (const float*)d_in[6];
  const float* bv    = (const float*)d_in[7];
  const float* Wo    = (const float*)d_in[8];
  const float* bo    = (const float*)d_in[9];
  const float* qn_w  = (const float*)d_in[10];
  const float* qn_b  = (const float*)d_in[11];
  const float* kn_w  = (const float*)d_in[12];
  const float* kn_b  = (const float*)d_in[13];
  const float* Win   = (const float*)d_in[14];
  const float* Wout  = (const float*)d_in[15];
  const float* gate  = (const float*)d_in[16];
  const float* fg_t  = (const float*)d_in[17];
  const float* fg_v  = (const float*)d_in[18];
  const float* bg_t  = (const float*)d_in[19];
  const float* bg_v  = (const float*)d_in[20];
  float* out = (float*)d_out;

  float* curp  = sym_addr(g_curp);
  float* qt    = sym_addr(g_qt);
  float* kt    = sym_addr(g_kt);
  float* vt    = sym_addr(g_vt);
  float* attnp = sym_addr(g_attnp);
  float* proj  = sym_addr(g_proj);
  float* emb   = sym_addr(g_emb);
  float* embp  = sym_addr(g_embp);
  float* u     = sym_addr(g_u);
  float* hloc  = sym_addr(g_hloc);
  float* hp    = sym_addr(g_hp);
  float* emb2  = sym_addr(g_emb2);
  float* revp  = sym_addr(g_revp);
  float* carry = sym_addr(g_carry);
  float* wqkv  = sym_addr(g_wqkv);
  float* bqkv  = sym_addr(g_bqkv);
  float* wo_p  = sym_addr(g_wo);
  float* win_p  = sym_addr(g_win);
  float* wout_p = sym_addr(g_wout);
  float* tg     = sym_addr(g_tg);

  cudaFuncSetAttribute(flash_tf32_kernel, cudaFuncAttributeMaxDynamicSharedMemorySize, FA_SMEM);
  cudaFuncSetAttribute(tf32_gemm_perm, cudaFuncAttributeMaxDynamicSharedMemorySize, GEMM_SMEM);
  cudaFuncSetAttribute(tf32_gemm_qkv, cudaFuncAttributeMaxDynamicSharedMemorySize, GEMM_SMEM);

  pack_qkv_perm_kernel<<<dim3(12, 1024), 256>>>(Wq, Wk, Wv, wqkv);
  pack_bias_kernel<<<4, 256>>>(bq, bk, bv, bqkv);
  pack3_b_perm_kernel<<<dim3(12, 1024), 256>>>(Wo, Win, Wout, wo_p, win_p, wout_p);
  tanh_prep_kernel<<<4, 256>>>(fg_t, fg_v, bg_t, bg_v, tg);

  gather_cur_perm4<<<5120, 256>>>(vid, txt, curp);
  tf32_gemm_qkv<<<dim3(24, 40), 256, GEMM_SMEM>>>(
      curp, wqkv, bqkv, qn_w, qn_b, kn_w, kn_b, qt, kt, vt);
  flash_tf32_kernel<<<dim3(10, 64), 256, FA_SMEM>>>(qt, kt, vt, attnp);
  tf32_gemm_perm<<<dim3(8, 40), 256, GEMM_SMEM>>>(
      attnp, wo_p, bo, proj, M_PAD, 1024, nullptr, nullptr, nullptr, 0);
  build_emb_kernel<<<SEQ_SSM, 256>>>(proj, emb);
  rowmajor_to_aperm4<<<4352, 256>>>(emb, embp);

  // forward SSM
  tf32_gemm_perm<<<dim3(8, 34), 256, GEMM_SMEM>>>(
      embp, win_p, nullptr, u, SEQ_SSM, 1024, nullptr, nullptr, nullptr, 0);
  scan_pass1_kernel<<<dim3(4, NCHUNK), 256>>>(u, gate, hloc, carry);
  scan_pass2_kernel<<<4, 256>>>(gate, carry);
  scan_pass3_perm4<<<4352, 256>>>(hloc, gate, carry, hp);
  tf32_gemm_perm<<<dim3(8, 34), 256, GEMM_SMEM>>>(
      hp, wout_p, nullptr, emb2, SEQ_SSM, 1024, emb, tg, tg + 1024, 1);

  // backward SSM
  rev_perm4<<<4352, 256>>>(emb2, revp);
  tf32_gemm_perm<<<dim3(8, 34), 256, GEMM_SMEM>>>(
      revp, win_p, nullptr, u, SEQ_SSM, 1024, nullptr, nullptr, nullptr, 0);
  scan_pass1_kernel<<<dim3(4, NCHUNK), 256>>>(u, gate, hloc, carry);
  scan_pass2_kernel<<<4, 256>>>(gate, carry);
  scan_pass3_perm4<<<4352, 256>>>(hloc, gate, carry, hp);
  tf32_gemm_perm<<<dim3(8, 34), 256, GEMM_SMEM>>>(
      hp, wout_p, nullptr, out, SEQ_SSM, 1024, emb2, tg + 2048, tg + 3072, 2);
}

// round 13
// speedup vs baseline: 1.8828x; 1.0196x over previous
#include <cuda_runtime.h>
#include <cuda_bf16.h>
#include <cstdint>

// ---------------------------------------------------------------------------
// Problem constants
// ---------------------------------------------------------------------------
#define D_MODEL 1024
#define NHEAD   16
#define HDIM    64
#define TXT_LEN 226
#define CHUNKS  4
#define SEQ_TXT 904
#define VID_LEN 3328
#define CHUNK_VID 1024
#define T_ATTN  1250
#define SEG_PAD 1280
#define M_ATTN  5000
#define M_PAD   5120
#define SEQ_SSM 4232
#define ATTN_SCALE 0.125f
#define NCHUNK  34

// ---------------------------------------------------------------------------
// Scratch (static __device__)
// ---------------------------------------------------------------------------
__device__ float g_curp [5242880];
__device__ float g_qt   [5120000];
__device__ float g_kt   [5120000];
__device__ float g_vt   [5120000];
__device__ float g_attnp[5242880];
__device__ float g_proj [5242880];
__device__ float g_emb  [4333568];
__device__ float g_embp [4456448];
__device__ float g_hloc [4333568];
__device__ float g_hp   [4456448];
__device__ float g_emb2 [4333568];
__device__ float g_revp [4456448];
__device__ float g_carry[34816];
__device__ float g_wqkv[3145728];
__device__ float g_bqkv[3072];
__device__ float g_wo  [1048576];
__device__ float g_win [1048576];
__device__ float g_wout[1048576];
__device__ float g_tg  [4096];

__device__ __forceinline__ float tf32_rna(float x) {
  float r;
  asm("cvt.rna.tf32.f32 %0, %1;" : "=f"(r) : "f"(x));
  return r;
}

__device__ __forceinline__ size_t bperm_off(int k, int c) {
  const int nb = c >> 7, kt = k >> 4;
  const int n8 = (c >> 3) & 15;
  const int kb = (k >> 3) & 1;
  const int j  = (k >> 2) & 1;
  const int lane = ((c & 7) << 2) | (k & 3);
  return ((size_t)(nb * 64 + kt)) * 2048 + (((n8 << 1) + kb) << 6) +
         (lane << 1) + j;
}

struct APermIdx { int r0, c0; size_t off; };
__device__ __forceinline__ APermIdx aperm_decode(int idx) {
  const int lane = idx & 31;
  const int half = (idx >> 5) & 1;
  const int g    = (idx >> 6) & 7;
  const int kt   = (idx >> 9) & 63;
  const int rb   = idx >> 15;
  APermIdx o;
  o.r0  = rb * 128 + g * 16 + (lane >> 2);
  o.c0  = kt * 16 + half * 8 + (lane & 3);
  o.off = ((size_t)(rb * 64 + kt)) * 2048 + (((g << 1) + half) << 7) + (lane << 2);
  return o;
}

__device__ __forceinline__ void cp16(uint32_t s, const void* g) {
  asm volatile("cp.async.cg.shared.global [%0], [%1], 16;" :: "r"(s), "l"(g));
}

__device__ __forceinline__ int rev_map(int i) {
  if (i < SEQ_TXT) {
    const int c = i / TXT_LEN;
    return (3 - c) * TXT_LEN + (i - c * TXT_LEN);
  }
  return 5135 - i;
}

__device__ __forceinline__ void rope_apply(float* x, int t) {
  const int p = t - TXT_LEN;
  const float fpos = (float)(p >> 8);
  const int rem = p & 255;
  const float hpos = (float)(rem >> 4);
  const float wpos = (float)(rem & 15);
#pragma unroll
  for (int i = 0; i < 8; i++) {
    const float ang = fpos * __powf(10000.f, -(float)i * 0.125f);
    float sn, cs; sincosf(ang, &sn, &cs);
    const float x1 = x[i], x2 = x[8 + i];
    x[i]     = x1 * cs - x2 * sn;
    x[8 + i] = x1 * sn + x2 * cs;
  }
#pragma unroll
  for (int i = 0; i < 12; i++) {
    const float ang = hpos * __powf(10000.f, -(float)i * (1.f / 12.f));
    float sn, cs; sincosf(ang, &sn, &cs);
    const float x1 = x[16 + i], x2 = x[28 + i];
    x[16 + i] = x1 * cs - x2 * sn;
    x[28 + i] = x1 * sn + x2 * cs;
  }
#pragma unroll
  for (int i = 0; i < 12; i++) {
    const float ang = wpos * __powf(10000.f, -(float)i * (1.f / 12.f));
    float sn, cs; sincosf(ang, &sn, &cs);
    const float x1 = x[40 + i], x2 = x[52 + i];
    x[40 + i] = x1 * cs - x2 * sn;
    x[52 + i] = x1 * sn + x2 * cs;
  }
}

// ---------------------------------------------------------------------------
// Weight packing
// ---------------------------------------------------------------------------
__global__ void pack_qkv_perm_kernel(const float* __restrict__ Wq,
                                     const float* __restrict__ Wk,
                                     const float* __restrict__ Wv,
                                     float* __restrict__ dst) {
  const int c = blockIdx.x * 256 + threadIdx.x;
  const int k = blockIdx.y;
  const float* W = (c < 1024) ? Wq : (c < 2048) ? Wk : Wv;
  dst[bperm_off(k, c)] = tf32_rna(W[(size_t)k * 1024 + (c & 1023)]);
}

// bias pack + tanh gate prep fused
__global__ void pack_small_kernel(const float* __restrict__ bq,
                                  const float* __restrict__ bk,
                                  const float* __restrict__ bv,
                                  const float* __restrict__ fg_t,
                                  const float* __restrict__ fg_v,
                                  const float* __restrict__ bg_t,
                                  const float* __restrict__ bg_v,
                                  float* __restrict__ bp,
                                  float* __restrict__ tg) {
  const int i = blockIdx.x * 256 + threadIdx.x;
  if (i < 1024) {
    bp[i] = bq[i]; bp[1024 + i] = bk[i]; bp[2048 + i] = bv[i];
    tg[i]        = tanhf(fg_t[i]);
    tg[1024 + i] = tanhf(fg_v[i]);
    tg[2048 + i] = tanhf(bg_t[i]);
    tg[3072 + i] = tanhf(bg_v[i]);
  }
}

__global__ void pack3_b_perm_kernel(const float* __restrict__ W0,
                                    const float* __restrict__ W1,
                                    const float* __restrict__ W2,
                                    float* __restrict__ D0,
                                    float* __restrict__ D1,
                                    float* __restrict__ D2) {
  const int cx = blockIdx.x * 256 + threadIdx.x;
  const int k  = blockIdx.y;
  const int c  = cx & 1023;
  const float* W; float* D;
  if (cx < 1024)      { W = W0; D = D0; }
  else if (cx < 2048) { W = W1; D = D1; }
  else                { W = W2; D = D2; }
  D[bperm_off(k, c)] = tf32_rna(W[(size_t)k * 1024 + c]);
}

// ---------------------------------------------------------------------------
// Common GEMM mainloop (GBK=32, 3-stage cp.async, dyn smem)
// ---------------------------------------------------------------------------
#define GEMM_SMEM (6 * 4096 * 4)

#define GEMM_MAINLOOP(Abase, Bbase)                                            \
  float acc[2][8][4];                                                          \
  _Pragma("unroll")                                                            \
  for (int mi = 0; mi < 2; mi++)                                               \
    _Pragma("unroll")                                                          \
    for (int ni = 0; ni < 8; ni++)                                             \
      _Pragma("unroll")                                                        \
      for (int j = 0; j < 4; j++) acc[mi][ni][j] = 0.f;                        \
  auto issue = [&](int kt2, int s) {                                           \
    const float* ga = (Abase) + (size_t)kt2 * 4096;                            \
    const float* gb = (Bbase) + (size_t)kt2 * 4096;                            \
    const uint32_t da = sA + s * 16384 + tid * 16;                             \
    const uint32_t db = sB + s * 16384 + tid * 16;                             \
    cp16(da,         ga + tid * 4);                                            \
    cp16(da + 4096,  ga + 1024 + tid * 4);                                     \
    cp16(da + 8192,  ga + 2048 + tid * 4);                                     \
    cp16(da + 12288, ga + 3072 + tid * 4);                                     \
    cp16(db,         gb + tid * 4);                                            \
    cp16(db + 4096,  gb + 1024 + tid * 4);                                     \
    cp16(db + 8192,  gb + 2048 + tid * 4);                                     \
    cp16(db + 12288, gb + 3072 + tid * 4);                                     \
    asm volatile("cp.async.commit_group;");                                    \
  };                                                                           \
  issue(0, 0);                                                                 \
  issue(1, 1);                                                                 \
  int s = 0;                                                                   \
  for (int t = 0; t < 32; t++) {                                               \
    if (t < 30) { asm volatile("cp.async.wait_group 1;"); }                    \
    else        { asm volatile("cp.async.wait_group 0;"); }                    \
    __syncthreads();                                                           \
    if (t + 2 < 32) issue(t + 2, (t + 2) % 3);                                 \
    const float4* a4 = reinterpret_cast<const float4*>(As + s * 4096);         \
    const float2* b2 = reinterpret_cast<const float2*>(Bs + s * 4096);         \
    _Pragma("unroll")                                                          \
    for (int kb = 0; kb < 4; kb++) {                                           \
      const int half = kb >> 1;                                                \
      const int kbl  = kb & 1;                                                 \
      float4 af[2];                                                            \
      float2 bf[8];                                                            \
      _Pragma("unroll")                                                        \
      for (int mi = 0; mi < 2; mi++)                                           \
        af[mi] = a4[half * 512 + ((((ws << 1) + mi) * 2 + kbl) << 5) + lane];  \
      _Pragma("unroll")                                                        \
      for (int ni = 0; ni < 8; ni++)                                           \
        bf[ni] = b2[half * 1024 + ((((wn >> 3) + ni) * 2 + kbl) << 5) + lane]; \
      _Pragma("unroll")                                                        \
      for (int mi = 0; mi < 2; mi++) {                                         \
        const uint32_t a0 = __float_as_uint(af[mi].x);                         \
        const uint32_t a1 = __float_as_uint(af[mi].y);                         \
        const uint32_t a2 = __float_as_uint(af[mi].z);                         \
        const uint32_t a3 = __float_as_uint(af[mi].w);                         \
        _Pragma("unroll")                                                      \
        for (int ni = 0; ni < 8; ni++) {                                       \
          asm volatile(                                                        \
              "mma.sync.aligned.m16n8k8.row.col.f32.tf32.tf32.f32 "            \
              "{%0,%1,%2,%3}, {%4,%5,%6,%7}, {%8,%9}, {%0,%1,%2,%3};"          \
              : "+f"(acc[mi][ni][0]), "+f"(acc[mi][ni][1]),                    \
                "+f"(acc[mi][ni][2]), "+f"(acc[mi][ni][3])                     \
              : "r"(a0), "r"(a1), "r"(a2), "r"(a3),                            \
                "r"(__float_as_uint(bf[ni].x)),                                \
                "r"(__float_as_uint(bf[ni].y)));                               \
        }                                                                      \
      }                                                                        \
    }                                                                          \
    s = (s + 1) % 3;                                                           \
  }

// ---------------------------------------------------------------------------
// Generic GEMM.
// mode 0: C = A@B (+bias)
// mode 1: C = e_base + tga/tgb * acc (row-gated add)
// mode 2: final output (reversed scatter)
// mode 3: Win+scan pass1 fused: C=hloc, e_base=gate, tga=carry
// ---------------------------------------------------------------------------
#define TSTRIDE 132
__global__ void __launch_bounds__(256) tf32_gemm_perm(
    const float* __restrict__ Ap, const float* __restrict__ Bp,
    const float* __restrict__ bias, float* __restrict__ C,
    int M, int N,
    const float* __restrict__ e_base, const float* __restrict__ tga,
    const float* __restrict__ tgb, int mode) {
  extern __shared__ float smg[];
  float* As = smg;
  float* Bs = smg + 12288;
  const int tid = threadIdx.x;
  const int warp = tid >> 5, lane = tid & 31;
  const int ws = warp & 3;
  const int wn = (warp >> 2) << 6;
  const int grp = lane >> 2, gcc = lane & 3;
  const int rb = blockIdx.y, nb = blockIdx.x;
  const uint32_t sA = (uint32_t)__cvta_generic_to_shared(As);
  const uint32_t sB = (uint32_t)__cvta_generic_to_shared(Bs);

  GEMM_MAINLOOP(Ap + (size_t)rb * 64 * 2048, Bp + (size_t)nb * 64 * 2048)

  const int row0 = rb * 128 + ws * 32;
  const int col0 = nb * 128 + wn;

  if (mode == 0) {
#pragma unroll
    for (int mi = 0; mi < 2; mi++) {
      const int row = row0 + mi * 16 + grp;
#pragma unroll
      for (int ni = 0; ni < 8; ni++) {
        const int col = col0 + ni * 8 + (gcc << 1);
        float b0 = 0.f, b1 = 0.f;
        if (bias) { b0 = __ldg(bias + col); b1 = __ldg(bias + col + 1); }
        if (row < M) {
          float2 o; o.x = acc[mi][ni][0] + b0; o.y = acc[mi][ni][1] + b1;
          *reinterpret_cast<float2*>(C + (size_t)row * N + col) = o;
        }
        if (row + 8 < M) {
          float2 o; o.x = acc[mi][ni][2] + b0; o.y = acc[mi][ni][3] + b1;
          *reinterpret_cast<float2*>(C + (size_t)(row + 8) * N + col) = o;
        }
      }
    }
  } else if (mode == 1) {
#pragma unroll
    for (int mi = 0; mi < 2; mi++) {
#pragma unroll
      for (int rr = 0; rr < 2; rr++) {
        const int row = row0 + mi * 16 + grp + rr * 8;
        if (row >= M) continue;
        const float* tg = (row < SEQ_TXT) ? tga : tgb;
#pragma unroll
        for (int ni = 0; ni < 8; ni++) {
          const int col = col0 + ni * 8 + (gcc << 1);
          const float2 e = *reinterpret_cast<const float2*>(e_base + (size_t)row * N + col);
          const float2 t = *reinterpret_cast<const float2*>(tg + col);
          float2 o;
          o.x = e.x + t.x * acc[mi][ni][rr * 2 + 0];
          o.y = e.y + t.y * acc[mi][ni][rr * 2 + 1];
          *reinterpret_cast<float2*>(C + (size_t)row * N + col) = o;
        }
      }
    }
  } else if (mode == 2) {
#pragma unroll
    for (int mi = 0; mi < 2; mi++) {
#pragma unroll
      for (int rr = 0; rr < 2; rr++) {
        const int row = row0 + mi * 16 + grp + rr * 8;
        if (row >= M) continue;
        const int i = rev_map(row);
        const int dst = (i < SEQ_TXT) ? (VID_LEN + i) : (i - SEQ_TXT);
        const float* tg = (i < SEQ_TXT) ? tga : tgb;
#pragma unroll
        for (int ni = 0; ni < 8; ni++) {
          const int col = col0 + ni * 8 + (gcc << 1);
          const float2 e = *reinterpret_cast<const float2*>(e_base + (size_t)i * N + col);
          const float2 t = *reinterpret_cast<const float2*>(tg + col);
          float2 o;
          o.x = e.x + t.x * acc[mi][ni][rr * 2 + 0];
          o.y = e.y + t.y * acc[mi][ni][rr * 2 + 1];
          *reinterpret_cast<float2*>(C + (size_t)dst * N + col) = o;
        }
      }
    }
  } else {
    // mode 3: stage tile, then per-column local scan (chunk == rb)
    __syncthreads();
    float* Ts = smg;
#pragma unroll
    for (int mi = 0; mi < 2; mi++) {
#pragma unroll
      for (int rr = 0; rr < 2; rr++) {
        const int trow = ws * 32 + mi * 16 + grp + rr * 8;
#pragma unroll
        for (int ni = 0; ni < 8; ni++) {
          const int tcol = wn + ni * 8 + (gcc << 1);
          Ts[trow * TSTRIDE + tcol]     = acc[mi][ni][rr * 2 + 0];
          Ts[trow * TSTRIDE + tcol + 1] = acc[mi][ni][rr * 2 + 1];
        }
      }
    }
    __syncthreads();
    if (tid < 128) {
      const int col = nb * 128 + tid;
      const float a = 1.f / (1.f + expf(-e_base[col]));   // e_base = gate
      const int t0 = rb * 128;
      const int t1 = (t0 + 128 < M) ? (t0 + 128) : M;
      float hv = 0.f;
      for (int t = t0; t < t1; t++) {
        hv = fmaf(a, hv, Ts[(t - t0) * TSTRIDE + tid]);
        C[(size_t)t * N + col] = hv;                      // C = hloc
      }
      ((float*)tga)[rb * 1024 + col] = hv;                // tga = carry
    }
  }
}

// ---------------------------------------------------------------------------
// QKV GEMM with fused layernorm+RoPE+transpose epilogue.
// ---------------------------------------------------------------------------
__global__ void __launch_bounds__(256) tf32_gemm_qkv(
    const float* __restrict__ Ap, const float* __restrict__ Bp,
    const float* __restrict__ bias,
    const float* __restrict__ qn_w, const float* __restrict__ qn_b,
    const float* __restrict__ kn_w, const float* __restrict__ kn_b,
    float* __restrict__ qt, float* __restrict__ kt, float* __restrict__ vt) {
  extern __shared__ float smg[];
  float* As = smg;
  float* Bs = smg + 12288;
  const int tid = threadIdx.x;
  const int warp = tid >> 5, lane = tid & 31;
  const int ws = warp & 3;
  const int wn = (warp >> 2) << 6;
  const int grp = lane >> 2, gcc = lane & 3;
  const int rb = blockIdx.y, nb = blockIdx.x;
  const uint32_t sA = (uint32_t)__cvta_generic_to_shared(As);
  const uint32_t sB = (uint32_t)__cvta_generic_to_shared(Bs);

  GEMM_MAINLOOP(Ap + (size_t)rb * 64 * 2048, Bp + (size_t)nb * 64 * 2048)

  __syncthreads();
  float* Ts = smg;
#pragma unroll
  for (int mi = 0; mi < 2; mi++) {
#pragma unroll
    for (int rr = 0; rr < 2; rr++) {
      const int trow = ws * 32 + mi * 16 + grp + rr * 8;
#pragma unroll
      for (int ni = 0; ni < 8; ni++) {
        const int tcol = wn + ni * 8 + (gcc << 1);
        const float b0 = __ldg(bias + nb * 128 + tcol);
        const float b1 = __ldg(bias + nb * 128 + tcol + 1);
        Ts[trow * TSTRIDE + tcol]     = acc[mi][ni][rr * 2 + 0] + b0;
        Ts[trow * TSTRIDE + tcol + 1] = acc[mi][ni][rr * 2 + 1] + b1;
      }
    }
  }
  __syncthreads();

  const int tr = tid >> 1;
  const int hl = tid & 1;
  const int row = rb * 128 + tr;
  if (row >= M_ATTN) return;
  const int bc = row / T_ATTN;
  const int t  = row - bc * T_ATTN;
  const int h  = ((nb & 7) << 1) + hl;
  float x[64];
#pragma unroll
  for (int d = 0; d < 64; d += 4) {
    const float4 v4 = *reinterpret_cast<const float4*>(&Ts[tr * TSTRIDE + hl * 64 + d]);
    x[d] = v4.x; x[d+1] = v4.y; x[d+2] = v4.z; x[d+3] = v4.w;
  }
  float* outb;
  if (nb < 16) {
    const float* nw = (nb < 8) ? qn_w : kn_w;
    const float* nbi = (nb < 8) ? qn_b : kn_b;
    float sm = 0.f, ss = 0.f;
#pragma unroll
    for (int d = 0; d < 64; d++) { sm += x[d]; ss += x[d] * x[d]; }
    const float mu  = sm * (1.f / 64.f);
    const float var = ss * (1.f / 64.f) - mu * mu;
    const float rr  = rsqrtf(var + 1e-6f);
#pragma unroll
    for (int d = 0; d < 64; d++) x[d] = (x[d] - mu) * rr * nw[d] + nbi[d];
    if (t >= TXT_LEN) rope_apply(x, t);
    outb = (nb < 8) ? qt : kt;
  } else {
    outb = vt;
  }
  const size_t dst = ((size_t)(bc * NHEAD + h) * T_ATTN + t) * HDIM;
#pragma unroll
  for (int d = 0; d < 64; d += 4)
    *reinterpret_cast<float4*>(outb + dst + d) =
        make_float4(tf32_rna(x[d]), tf32_rna(x[d+1]), tf32_rna(x[d+2]), tf32_rna(x[d+3]));
}

// ---------------------------------------------------------------------------
// Coalesced A-perm writers
// ---------------------------------------------------------------------------
__global__ void gather_cur_perm4(const float* __restrict__ vid,
                                 const float* __restrict__ txt,
                                 float* __restrict__ curp) {
  const int idx = blockIdx.x * 256 + threadIdx.x;
  const APermIdx ix = aperm_decode(idx);
  auto ld = [&](int r, int c) -> float {
    if (r >= M_ATTN) return 0.f;
    const int bc = r / T_ATTN;
    const int t  = r - bc * T_ATTN;
    return (t < TXT_LEN)
        ? txt[(size_t)(bc * TXT_LEN + t) * D_MODEL + c]
        : vid[(size_t)(bc * 768 + (t - TXT_LEN)) * D_MODEL + c];
  };
  float4 o;
  o.x = tf32_rna(ld(ix.r0,     ix.c0));
  o.y = tf32_rna(ld(ix.r0 + 8, ix.c0));
  o.z = tf32_rna(ld(ix.r0,     ix.c0 + 4));
  o.w = tf32_rna(ld(ix.r0 + 8, ix.c0 + 4));
  *reinterpret_cast<float4*>(curp + ix.off) = o;
}

__global__ void rowmajor_to_aperm4(const float* __restrict__ src,
                                   float* __restrict__ dst) {
  const int idx = blockIdx.x * 256 + threadIdx.x;
  const APermIdx ix = aperm_decode(idx);
  auto ld = [&](int r, int c) -> float {
    return (r < SEQ_SSM) ? src[(size_t)r * D_MODEL + c] : 0.f;
  };
  float4 o;
  o.x = tf32_rna(ld(ix.r0,     ix.c0));
  o.y = tf32_rna(ld(ix.r0 + 8, ix.c0));
  o.z = tf32_rna(ld(ix.r0,     ix.c0 + 4));
  o.w = tf32_rna(ld(ix.r0 + 8, ix.c0 + 4));
  *reinterpret_cast<float4*>(dst + ix.off) = o;
}

__global__ void rev_perm4(const float* __restrict__ src, float* __restrict__ dst) {
  const int idx = blockIdx.x * 256 + threadIdx.x;
  const APermIdx ix = aperm_decode(idx);
  auto ld = [&](int r, int c) -> float {
    return (r < SEQ_SSM) ? src[(size_t)rev_map(r) * D_MODEL + c] : 0.f;
  };
  float4 o;
  o.x = tf32_rna(ld(ix.r0,     ix.c0));
  o.y = tf32_rna(ld(ix.r0 + 8, ix.c0));
  o.z = tf32_rna(ld(ix.r0,     ix.c0 + 4));
  o.w = tf32_rna(ld(ix.r0 + 8, ix.c0 + 4));
  *reinterpret_cast<float4*>(dst + ix.off) = o;
}

// ---------------------------------------------------------------------------
// Flash attention tf32, 128-row tiles, in-warp softmax (known good).
// ---------------------------------------------------------------------------
#define FS 68
#define FA_SMEM ((384 * FS) * 4)

__global__ void __launch_bounds__(256) flash_tf32_kernel(
    const float* __restrict__ Qt, const float* __restrict__ Kt,
    const float* __restrict__ Vt, float* __restrict__ Outp) {
  extern __shared__ float sm[];
  float* Qs = sm;
  float* Ks = sm + 128 * FS;
  float* Vs = sm + 192 * FS;
  float* Ss = sm + 256 * FS;

  const int mat = blockIdx.y;
  const int q0  = blockIdx.x * 128;
  const int tid = threadIdx.x;
  const int warp = tid >> 5;
  const int lane = tid & 31;
  const int gr = lane >> 2;
  const int gc = lane & 3;
  const int wm = warp * 16;

  const float* Qb = Qt + (size_t)mat * T_ATTN * HDIM;
  const float* Kb = Kt + (size_t)mat * T_ATTN * HDIM;
  const float* Vb = Vt + (size_t)mat * T_ATTN * HDIM;

  {
    const int r  = tid >> 1;
    const int d0 = (tid & 1) << 5;
    const int gq = q0 + r;
#pragma unroll
    for (int i = 0; i < 32; i += 4) {
      float4 v4 = make_float4(0.f, 0.f, 0.f, 0.f);
      if (gq < T_ATTN)
        v4 = *reinterpret_cast<const float4*>(Qb + (size_t)gq * HDIM + d0 + i);
      *reinterpret_cast<float4*>(&Qs[r * FS + d0 + i]) = v4;
    }
  }
  __syncthreads();

  uint32_t qf[8][4];
#pragma unroll
  for (int kb = 0; kb < 8; kb++) {
    const int base = (wm + gr) * FS + kb * 8 + gc;
    qf[kb][0] = __float_as_uint(Qs[base]);
    qf[kb][1] = __float_as_uint(Qs[base + 8 * FS]);
    qf[kb][2] = __float_as_uint(Qs[base + 4]);
    qf[kb][3] = __float_as_uint(Qs[base + 8 * FS + 4]);
  }
  __syncthreads();

  float acc[8][4];
#pragma unroll
  for (int ni = 0; ni < 8; ni++)
#pragma unroll
    for (int j = 0; j < 4; j++) acc[ni][j] = 0.f;

  float mrun0 = -1e30f, mrun1 = -1e30f;
  float lrun0 = 0.f, lrun1 = 0.f;

  for (int k0 = 0; k0 < T_ATTN; k0 += 64) {
    {
      const int r  = tid >> 2;
      const int d0 = (tid & 3) << 4;
      const int gk = k0 + r;
#pragma unroll
      for (int i = 0; i < 16; i += 4) {
        float4 kv = make_float4(0.f, 0.f, 0.f, 0.f);
        float4 vv = make_float4(0.f, 0.f, 0.f, 0.f);
        if (gk < T_ATTN) {
          kv = *reinterpret_cast<const float4*>(Kb + (size_t)gk * HDIM + d0 + i);
          vv = *reinterpret_cast<const float4*>(Vb + (size_t)gk * HDIM + d0 + i);
        }
        *reinterpret_cast<float4*>(&Ks[r * FS + d0 + i]) = kv;
        *reinterpret_cast<float4*>(&Vs[r * FS + d0 + i]) = vv;
      }
    }
    __syncthreads();

    float sacc[8][4];
#pragma unroll
    for (int ni = 0; ni < 8; ni++)
#pragma unroll
      for (int j = 0; j < 4; j++) sacc[ni][j] = 0.f;
#pragma unroll
    for (int kb = 0; kb < 8; kb++) {
      uint32_t bf[8][2];
#pragma unroll
      for (int ni = 0; ni < 8; ni++) {
        const int kbase = (ni * 8 + gr) * FS + kb * 8 + gc;
        bf[ni][0] = __float_as_uint(Ks[kbase]);
        bf[ni][1] = __float_as_uint(Ks[kbase + 4]);
      }
#pragma unroll
      for (int ni = 0; ni < 8; ni++) {
        asm volatile(
            "mma.sync.aligned.m16n8k8.row.col.f32.tf32.tf32.f32 "
            "{%0,%1,%2,%3}, {%4,%5,%6,%7}, {%8,%9}, {%0,%1,%2,%3};"
            : "+f"(sacc[ni][0]), "+f"(sacc[ni][1]),
              "+f"(sacc[ni][2]), "+f"(sacc[ni][3])
            : "r"(qf[kb][0]), "r"(qf[kb][1]), "r"(qf[kb][2]), "r"(qf[kb][3]),
              "r"(bf[ni][0]), "r"(bf[ni][1]));
      }
    }

    float m0 = -1e30f, m1 = -1e30f;
#pragma unroll
    for (int ni = 0; ni < 8; ni++) {
      const int gk = k0 + ni * 8 + (gc << 1);
      sacc[ni][0] = (gk     < T_ATTN) ? sacc[ni][0] * ATTN_SCALE : -1e30f;
      sacc[ni][1] = (gk + 1 < T_ATTN) ? sacc[ni][1] * ATTN_SCALE : -1e30f;
      sacc[ni][2] = (gk     < T_ATTN) ? sacc[ni][2] * ATTN_SCALE : -1e30f;
      sacc[ni][3] = (gk + 1 < T_ATTN) ? sacc[ni][3] * ATTN_SCALE : -1e30f;
      m0 = fmaxf(m0, fmaxf(sacc[ni][0], sacc[ni][1]));
      m1 = fmaxf(m1, fmaxf(sacc[ni][2], sacc[ni][3]));
    }
    m0 = fmaxf(m0, __shfl_xor_sync(0xffffffffu, m0, 1));
    m0 = fmaxf(m0, __shfl_xor_sync(0xffffffffu, m0, 2));
    m1 = fmaxf(m1, __shfl_xor_sync(0xffffffffu, m1, 1));
    m1 = fmaxf(m1, __shfl_xor_sync(0xffffffffu, m1, 2));
    const float mn0 = fmaxf(mrun0, m0);
    const float mn1 = fmaxf(mrun1, m1);
    const float sc0 = __expf(mrun0 - mn0);
    const float sc1 = __expf(mrun1 - mn1);
    mrun0 = mn0; mrun1 = mn1;

    float s0 = 0.f, s1 = 0.f;
#pragma unroll
    for (int ni = 0; ni < 8; ni++) {
      sacc[ni][0] = tf32_rna(__expf(sacc[ni][0] - mn0));
      sacc[ni][1] = tf32_rna(__expf(sacc[ni][1] - mn0));
      sacc[ni][2] = tf32_rna(__expf(sacc[ni][2] - mn1));
      sacc[ni][3] = tf32_rna(__expf(sacc[ni][3] - mn1));
      s0 += sacc[ni][0] + sacc[ni][1];
      s1 += sacc[ni][2] + sacc[ni][3];
    }
    s0 += __shfl_xor_sync(0xffffffffu, s0, 1);
    s0 += __shfl_xor_sync(0xffffffffu, s0, 2);
    s1 += __shfl_xor_sync(0xffffffffu, s1, 1);
    s1 += __shfl_xor_sync(0xffffffffu, s1, 2);
    lrun0 = lrun0 * sc0 + s0;
    lrun1 = lrun1 * sc1 + s1;

#pragma unroll
    for (int ni = 0; ni < 8; ni++) {
      const int col = ni * 8 + (gc << 1);
      *reinterpret_cast<float2*>(&Ss[(wm + gr) * FS + col]) =
          make_float2(sacc[ni][0], sacc[ni][1]);
      *reinterpret_cast<float2*>(&Ss[(wm + 8 + gr) * FS + col]) =
          make_float2(sacc[ni][2], sacc[ni][3]);
    }
    __syncwarp();

#pragma unroll
    for (int ni = 0; ni < 8; ni++) {
      acc[ni][0] *= sc0; acc[ni][1] *= sc0;
      acc[ni][2] *= sc1; acc[ni][3] *= sc1;
    }
#pragma unroll
    for (int kb = 0; kb < 8; kb++) {
      uint32_t af[4];
      const int abase = (wm + gr) * FS + kb * 8 + gc;
      af[0] = __float_as_uint(Ss[abase]);
      af[1] = __float_as_uint(Ss[abase + 8 * FS]);
      af[2] = __float_as_uint(Ss[abase + 4]);
      af[3] = __float_as_uint(Ss[abase + 8 * FS + 4]);
      uint32_t bf[8][2];
#pragma unroll
      for (int ni = 0; ni < 8; ni++) {
        const int vbase = (kb * 8 + gc) * FS + ni * 8 + gr;
        bf[ni][0] = __float_as_uint(Vs[vbase]);
        bf[ni][1] = __float_as_uint(Vs[vbase + 4 * FS]);
      }
#pragma unroll
      for (int ni = 0; ni < 8; ni++) {
        asm volatile(
            "mma.sync.aligned.m16n8k8.row.col.f32.tf32.tf32.f32 "
            "{%0,%1,%2,%3}, {%4,%5,%6,%7}, {%8,%9}, {%0,%1,%2,%3};"
            : "+f"(acc[ni][0]), "+f"(acc[ni][1]),
              "+f"(acc[ni][2]), "+f"(acc[ni][3])
            : "r"(af[0]), "r"(af[1]), "r"(af[2]), "r"(af[3]),
              "r"(bf[ni][0]), "r"(bf[ni][1]));
      }
    }
    __syncthreads();
  }

  {
    const float inv0 = 1.f / lrun0;
    const float inv1 = 1.f / lrun1;
#pragma unroll
    for (int ni = 0; ni < 8; ni++) {
      const int col = ni * 8 + (gc << 1);
      Ss[(wm + gr) * FS + col]         = acc[ni][0] * inv0;
      Ss[(wm + gr) * FS + col + 1]     = acc[ni][1] * inv0;
      Ss[(wm + 8 + gr) * FS + col]     = acc[ni][2] * inv1;
      Ss[(wm + 8 + gr) * FS + col + 1] = acc[ni][3] * inv1;
    }
  }
  __syncthreads();
  {
    const int bc = mat >> 4;
    const int h  = mat & 15;
    const int rb = (bc * SEG_PAD + q0) >> 7;
    for (int ii = tid; ii < 2048; ii += 256) {
      const int l2   = ii & 31;
      const int half = (ii >> 5) & 1;
      const int ktl  = (ii >> 6) & 3;
      const int gg   = (ii >> 8) & 7;
      const int rl = gg * 16 + (l2 >> 2);
      const int cl = ktl * 16 + half * 8 + (l2 & 3);
      float4 o;
      o.x = tf32_rna(Ss[rl * FS + cl]);
      o.y = tf32_rna(Ss[(rl + 8) * FS + cl]);
      o.z = tf32_rna(Ss[rl * FS + cl + 4]);
      o.w = tf32_rna(Ss[(rl + 8) * FS + cl + 4]);
      const int kt = h * 4 + ktl;
      const size_t off = ((size_t)(rb * 64 + kt)) * 2048 +
                         (((gg << 1) + half) << 7) + (l2 << 2);
      *reinterpret_cast<float4*>(Outp + off) = o;
    }
  }
}

// ---------------------------------------------------------------------------
// build emb (reads padded proj)
// ---------------------------------------------------------------------------
__global__ void build_emb_kernel(const float* __restrict__ proj,
                                 float* __restrict__ emb) {
  const int idx = blockIdx.x * blockDim.x + threadIdx.x;
  if (idx >= SEQ_SSM * 256) return;
  const int i  = idx >> 8;
  const int d4 = (idx & 255) << 2;
  float4 o;
  if (i < SEQ_TXT) {
    const int c = i / TXT_LEN;
    const int t = i - c * TXT_LEN;
    o = *reinterpret_cast<const float4*>(proj + ((size_t)(c * SEG_PAD + t)) * D_MODEL + d4);
  } else {
    const int p = i - SEQ_TXT;
    float4 acc = make_float4(0.f, 0.f, 0.f, 0.f);
    int cnt = 0;
#pragma unroll
    for (int c = 0; c < 4; c++) {
      const int j = p - c * 768;
      if (j >= 0 && j < CHUNK_VID) {
        const float4 v4 = *reinterpret_cast<const float4*>(
            proj + ((size_t)(c * SEG_PAD + TXT_LEN + j)) * D_MODEL + d4);
        acc.x += v4.x; acc.y += v4.y; acc.z += v4.z; acc.w += v4.w;
        cnt++;
      }
    }
    const float inv = 1.f / (float)cnt;
    o.x = acc.x * inv; o.y = acc.y * inv; o.z = acc.z * inv; o.w = acc.w * inv;
  }
  *reinterpret_cast<float4*>(emb + (size_t)i * D_MODEL + d4) = o;
}

// ---------------------------------------------------------------------------
// SSM scan passes 2 and 3
// ---------------------------------------------------------------------------
__global__ void scan_pass2_kernel(const float* __restrict__ gate,
                                  float* __restrict__ carry) {
  const int d = blockIdx.x * 256 + threadIdx.x;
  const float a = 1.f / (1.f + expf(-gate[d]));
  const float a128 = __powf(a, 128.f);
  float s = 0.f;
  for (int c = 0; c < NCHUNK; c++) {
    const float cv = carry[c * 1024 + d];
    carry[c * 1024 + d] = s;
    s = a128 * s + cv;
  }
}

__global__ void scan_pass3_perm4(const float* __restrict__ hloc,
                                 const float* __restrict__ gate,
                                 const float* __restrict__ carry,
                                 float* __restrict__ hp) {
  const int idx = blockIdx.x * 256 + threadIdx.x;
  const APermIdx ix = aperm_decode(idx);
  const int chunk = ix.r0 >> 7;
  const int t0 = chunk << 7;
  const float a0 = 1.f / (1.f + expf(-gate[ix.c0]));
  const float a1 = 1.f / (1.f + expf(-gate[ix.c0 + 4]));
  const float cin0 = carry[chunk * 1024 + ix.c0];
  const float cin1 = carry[chunk * 1024 + ix.c0 + 4];
  const float e = (float)(ix.r0 - t0 + 1);
  const float p0  = __powf(a0, e);
  const float p1  = __powf(a1, e);
  const float p0b = p0 * __powf(a0, 8.f);
  const float p1b = p1 * __powf(a1, 8.f);
  auto ld = [&](int r, int c) -> float {
    return (r < SEQ_SSM) ? hloc[(size_t)r * D_MODEL + c] : 0.f;
  };
  float4 o;
  o.x = (ix.r0     < SEQ_SSM) ? tf32_rna(ld(ix.r0,     ix.c0)     + p0  * cin0) : 0.f;
  o.y = (ix.r0 + 8 < SEQ_SSM) ? tf32_rna(ld(ix.r0 + 8, ix.c0)     + p0b * cin0) : 0.f;
  o.z = (ix.r0     < SEQ_SSM) ? tf32_rna(ld(ix.r0,     ix.c0 + 4) + p1  * cin1) : 0.f;
  o.w = (ix.r0 + 8 < SEQ_SSM) ? tf32_rna(ld(ix.r0 + 8, ix.c0 + 4) + p1b * cin1) : 0.f;
  *reinterpret_cast<float4*>(hp + ix.off) = o;
}

// ---------------------------------------------------------------------------
// Launch
// ---------------------------------------------------------------------------
static float* sym_addr(const void* symbol) {
  void* p = nullptr;
  cudaGetSymbolAddress(&p, symbol);
  return (float*)p;
}

extern "C" void kernel_launch(void* const* d_in, const int* in_sizes, int n_in,
                              void* d_out, int out_size) {
  (void)in_sizes; (void)n_in; (void)out_size;
  const float* vid   = (const float*)d_in[0];
  const float* txt   = (const float*)d_in[1];
  const float* Wq    = (const float*)d_in[2];
  const float* bq    = (const float*)d_in[3];
  const float* Wk    = (const float*)d_in[4];
  const float* bk    = (const float*)d_in[5];
  const float* Wv    = (const float*)d_in[6];
  const float* bv    = (const float*)d_in[7];
  const float* Wo    = (const float*)d_in[8];
  const float* bo    = (const float*)d_in[9];
  const float* qn_w  = (const float*)d_in[10];
  const float* qn_b  = (const float*)d_in[11];
  const float* kn_w  = (const float*)d_in[12];
  const float* kn_b  = (const float*)d_in[13];
  const float* Win   = (const float*)d_in[14];
  const float* Wout  = (const float*)d_in[15];
  const float* gate  = (const float*)d_in[16];
  const float* fg_t  = (const float*)d_in[17];
  const float* fg_v  = (const float*)d_in[18];
  const float* bg_t  = (const float*)d_in[19];
  const float* bg_v  = (const float*)d_in[20];
  float* out = (float*)d_out;

  float* curp  = sym_addr(g_curp);
  float* qt    = sym_addr(g_qt);
  float* kt    = sym_addr(g_kt);
  float* vt    = sym_addr(g_vt);
  float* attnp = sym_addr(g_attnp);
  float* proj  = sym_addr(g_proj);
  float* emb   = sym_addr(g_emb);
  float* embp  = sym_addr(g_embp);
  float* hloc  = sym_addr(g_hloc);
  float* hp    = sym_addr(g_hp);
  float* emb2  = sym_addr(g_emb2);
  float* revp  = sym_addr(g_revp);
  float* carry = sym_addr(g_carry);
  float* wqkv  = sym_addr(g_wqkv);
  float* bqkv  = sym_addr(g_bqkv);
  float* wo_p  = sym_addr(g_wo);
  float* win_p  = sym_addr(g_win);
  float* wout_p = sym_addr(g_wout);
  float* tg     = sym_addr(g_tg);

  cudaFuncSetAttribute(flash_tf32_kernel, cudaFuncAttributeMaxDynamicSharedMemorySize, FA_SMEM);
  cudaFuncSetAttribute(tf32_gemm_perm, cudaFuncAttributeMaxDynamicSharedMemorySize, GEMM_SMEM);
  cudaFuncSetAttribute(tf32_gemm_qkv, cudaFuncAttributeMaxDynamicSharedMemorySize, GEMM_SMEM);

  pack_qkv_perm_kernel<<<dim3(12, 1024), 256>>>(Wq, Wk, Wv, wqkv);
  pack_small_kernel<<<4, 256>>>(bq, bk, bv, fg_t, fg_v, bg_t, bg_v, bqkv, tg);
  pack3_b_perm_kernel<<<dim3(12, 1024), 256>>>(Wo, Win, Wout, wo_p, win_p, wout_p);

  gather_cur_perm4<<<5120, 256>>>(vid, txt, curp);
  tf32_gemm_qkv<<<dim3(24, 40), 256, GEMM_SMEM>>>(
      curp, wqkv, bqkv, qn_w, qn_b, kn_w, kn_b, qt, kt, vt);
  flash_tf32_kernel<<<dim3(10, 64), 256, FA_SMEM>>>(qt, kt, vt, attnp);
  tf32_gemm_perm<<<dim3(8, 40), 256, GEMM_SMEM>>>(
      attnp, wo_p, bo, proj, M_PAD, 1024, nullptr, nullptr, nullptr, 0);
  build_emb_kernel<<<SEQ_SSM, 256>>>(proj, emb);
  rowmajor_to_aperm4<<<4352, 256>>>(emb, embp);

  // forward SSM (Win GEMM + local scan fused)
  tf32_gemm_perm<<<dim3(8, 34), 256, GEMM_SMEM>>>(
      embp, win_p, nullptr, hloc, SEQ_SSM, 1024, gate, carry, nullptr, 3);
  scan_pass2_kernel<<<4, 256>>>(gate, carry);
  scan_pass3_perm4<<<4352, 256>>>(hloc, gate, carry, hp);
  tf32_gemm_perm<<<dim3(8, 34), 256, GEMM_SMEM>>>(
      hp, wout_p, nullptr, emb2, SEQ_SSM, 1024, emb, tg, tg + 1024, 1);

  // backward SSM
  rev_perm4<<<4352, 256>>>(emb2, revp);
  tf32_gemm_perm<<<dim3(8, 34), 256, GEMM_SMEM>>>(
      revp, win_p, nullptr, hloc, SEQ_SSM, 1024, gate, carry, nullptr, 3);
  scan_pass2_kernel<<<4, 256>>>(gate, carry);
  scan_pass3_perm4<<<4352, 256>>>(hloc, gate, carry, hp);
  tf32_gemm_perm<<<dim3(8, 34), 256, GEMM_SMEM>>>(
      hp, wout_p, nullptr, out, SEQ_SSM, 1024, emb2, tg + 2048, tg + 3072, 2);
}